// round 1
// baseline (speedup 1.0000x reference)
#include <cuda_runtime.h>
#include <math.h>

#define S_LEN 8192
#define DM    512
#define DK    16
#define DFF   2048

// ---------------- scratch (static device globals; no runtime alloc) --------
__device__ float g_Wqkv[DM * 48];      // packed [512][48] = Wq|Wk|Wv
__device__ float g_Woeff[DK * DM];     // sum of 8 head blocks of W_o: [16][512]
__device__ float g_Q[S_LEN * DK];
__device__ float g_K[S_LEN * DK];
__device__ float g_V[S_LEN * DK];
__device__ float g_head[S_LEN * DK];
__device__ float g_mho[S_LEN * DM];
__device__ float g_h[S_LEN * DFF];

// ---------------- weight packing ------------------------------------------
__global__ void pack_weights(const float* __restrict__ Wq,
                             const float* __restrict__ Wk,
                             const float* __restrict__ Wv,
                             const float* __restrict__ Wo) {
    int idx = blockIdx.x * blockDim.x + threadIdx.x;
    if (idx < DM * 48) {
        int d = idx / 48, c = idx % 48;
        float v;
        if (c < 16)      v = Wq[d * 16 + c];
        else if (c < 32) v = Wk[d * 16 + c - 16];
        else             v = Wv[d * 16 + c - 32];
        g_Wqkv[idx] = v;
    }
    if (idx < DK * DM) {
        int i = idx / DM, c = idx % DM;
        float s = 0.f;
#pragma unroll
        for (int h = 0; h < 8; h++) s += Wo[(h * 16 + i) * DM + c];
        g_Woeff[idx] = s;
    }
}

// ---------------- fused QKV projection: [8192,512] @ [512,48] -------------
__global__ void __launch_bounds__(256) qkv_kernel(const float* __restrict__ frame) {
    __shared__ float Fs[128][33];
    __shared__ float Ws[32][48];
    int t = threadIdx.x;
    int m0 = blockIdx.x * 128;
    int r = t & 127;
    int half = t >> 7;   // 0/1 -> 24 cols each
    float acc[24];
#pragma unroll
    for (int c = 0; c < 24; c++) acc[c] = 0.f;

    int lrow = t >> 3;          // 0..31
    int lds  = (t & 7) * 4;     // 0..28

    for (int d0 = 0; d0 < DM; d0 += 32) {
#pragma unroll
        for (int rr = 0; rr < 128; rr += 32) {
            float4 v = *(const float4*)&frame[(size_t)(m0 + lrow + rr) * DM + d0 + lds];
            Fs[lrow + rr][lds + 0] = v.x;
            Fs[lrow + rr][lds + 1] = v.y;
            Fs[lrow + rr][lds + 2] = v.z;
            Fs[lrow + rr][lds + 3] = v.w;
        }
        for (int q = t; q < 32 * 48; q += 256)
            Ws[q / 48][q % 48] = g_Wqkv[(d0 + q / 48) * 48 + (q % 48)];
        __syncthreads();
#pragma unroll
        for (int d = 0; d < 32; d++) {
            float f = Fs[r][d];
#pragma unroll
            for (int c = 0; c < 24; c++)
                acc[c] = fmaf(f, Ws[d][half * 24 + c], acc[c]);
        }
        __syncthreads();
    }
    int row = m0 + r;
#pragma unroll
    for (int c = 0; c < 24; c++) {
        int cg = half * 24 + c;
        float v = acc[c];
        if (cg < 16)      g_Q[row * 16 + cg]      = v;
        else if (cg < 32) g_K[row * 16 + cg - 16] = v;
        else              g_V[row * 16 + cg - 32] = v;
    }
}

// ---------------- flash attention: warp per query, lanes split keys -------
__global__ void __launch_bounds__(1024, 1) attn_kernel() {
    const int TK = 256;
    __shared__ float Ks[TK][17];
    __shared__ float Vs[TK][17];
    int t = threadIdx.x;
    int warp = t >> 5, lane = t & 31;
    int q = blockIdx.x * 32 + warp;

    float qreg[16];
#pragma unroll
    for (int i = 0; i < 16; i++) qreg[i] = g_Q[q * 16 + i];

    float m = -INFINITY, l = 0.f;
    float acc[16];
#pragma unroll
    for (int i = 0; i < 16; i++) acc[i] = 0.f;

    int jl  = t >> 2;          // 0..255
    int il4 = (t & 3) * 4;

    for (int k0 = 0; k0 < S_LEN; k0 += TK) {
        {
            float4 kv = *(const float4*)&g_K[(size_t)(k0 + jl) * 16 + il4];
            Ks[jl][il4 + 0] = kv.x; Ks[jl][il4 + 1] = kv.y;
            Ks[jl][il4 + 2] = kv.z; Ks[jl][il4 + 3] = kv.w;
            float4 vv = *(const float4*)&g_V[(size_t)(k0 + jl) * 16 + il4];
            Vs[jl][il4 + 0] = vv.x; Vs[jl][il4 + 1] = vv.y;
            Vs[jl][il4 + 2] = vv.z; Vs[jl][il4 + 3] = vv.w;
        }
        __syncthreads();
#pragma unroll 1
        for (int it = 0; it < TK / 32; it++) {
            int j = it * 32 + lane;
            float s = 0.f;
#pragma unroll
            for (int i = 0; i < 16; i++) s = fmaf(qreg[i], Ks[j][i], s);
            s *= 0.25f;   // 1/sqrt(16)
            float p;
            if (s > m) {
                float corr = __expf(m - s);
                l *= corr;
#pragma unroll
                for (int i = 0; i < 16; i++) acc[i] *= corr;
                m = s;
                p = 1.f;
            } else {
                p = __expf(s - m);
            }
            l += p;
#pragma unroll
            for (int i = 0; i < 16; i++) acc[i] = fmaf(p, Vs[j][i], acc[i]);
        }
        __syncthreads();
    }

    // merge lane-partial online-softmax states
    float mmax = m;
#pragma unroll
    for (int off = 16; off; off >>= 1)
        mmax = fmaxf(mmax, __shfl_xor_sync(0xffffffffu, mmax, off));
    float sc = __expf(m - mmax);
    l *= sc;
#pragma unroll
    for (int i = 0; i < 16; i++) acc[i] *= sc;
#pragma unroll
    for (int off = 16; off; off >>= 1)
        l += __shfl_xor_sync(0xffffffffu, l, off);
#pragma unroll
    for (int i = 0; i < 16; i++) {
        float a = acc[i];
#pragma unroll
        for (int off = 16; off; off >>= 1)
            a += __shfl_xor_sync(0xffffffffu, a, off);
        acc[i] = a;
    }
    if (lane == 0) {
        float inv = 1.f / l;
#pragma unroll
        for (int i = 0; i < 16; i++) g_head[q * 16 + i] = acc[i] * inv;
    }
}

// ---------------- mho = head @ Woeff  [8192,16]@[16,512] ------------------
__global__ void __launch_bounds__(256) mho_kernel() {
    __shared__ float hrow[8][16];
    int t = threadIdx.x;
    int r0 = blockIdx.x * 8;
    if (t < 128) hrow[t >> 4][t & 15] = g_head[r0 * 16 + t];
    __syncthreads();

    int cg = (t & 127) * 4;
    int rb = (t >> 7) * 4;
    float4 a0 = make_float4(0.f, 0.f, 0.f, 0.f);
    float4 a1 = a0, a2 = a0, a3 = a0;
#pragma unroll
    for (int i = 0; i < 16; i++) {
        float4 w = *(const float4*)&g_Woeff[i * 512 + cg];
        float h0 = hrow[rb + 0][i], h1 = hrow[rb + 1][i];
        float h2 = hrow[rb + 2][i], h3 = hrow[rb + 3][i];
        a0.x = fmaf(h0, w.x, a0.x); a0.y = fmaf(h0, w.y, a0.y);
        a0.z = fmaf(h0, w.z, a0.z); a0.w = fmaf(h0, w.w, a0.w);
        a1.x = fmaf(h1, w.x, a1.x); a1.y = fmaf(h1, w.y, a1.y);
        a1.z = fmaf(h1, w.z, a1.z); a1.w = fmaf(h1, w.w, a1.w);
        a2.x = fmaf(h2, w.x, a2.x); a2.y = fmaf(h2, w.y, a2.y);
        a2.z = fmaf(h2, w.z, a2.z); a2.w = fmaf(h2, w.w, a2.w);
        a3.x = fmaf(h3, w.x, a3.x); a3.y = fmaf(h3, w.y, a3.y);
        a3.z = fmaf(h3, w.z, a3.z); a3.w = fmaf(h3, w.w, a3.w);
    }
    *(float4*)&g_mho[(size_t)(r0 + rb + 0) * 512 + cg] = a0;
    *(float4*)&g_mho[(size_t)(r0 + rb + 1) * 512 + cg] = a1;
    *(float4*)&g_mho[(size_t)(r0 + rb + 2) * 512 + cg] = a2;
    *(float4*)&g_mho[(size_t)(r0 + rb + 3) * 512 + cg] = a3;
}

// ---------------- tiled NT GEMM: C[M,N] = A[M,K] * B[N,K]^T + epilogue ----
// EPI 0: gelu(x + bias) ; EPI 1: x + bias + res
template <int EPI>
__device__ __forceinline__ void gemm_nt_body(
    const float* __restrict__ A, const float* __restrict__ B,
    const float* __restrict__ bias, const float* __restrict__ res,
    float* __restrict__ C, int N, int K)
{
    __shared__ float As[16][132];
    __shared__ float Bs[16][132];
    int t = threadIdx.x;
    int m0 = blockIdx.y * 128;
    int n0 = blockIdx.x * 128;

    float acc[8][8];
#pragma unroll
    for (int r = 0; r < 8; r++)
#pragma unroll
        for (int c = 0; c < 8; c++) acc[r][c] = 0.f;

    int lr = t >> 2;           // 0..63
    int lk = (t & 3) * 4;      // 0,4,8,12
    int i = t >> 4, j = t & 15;

    for (int k0 = 0; k0 < K; k0 += 16) {
#pragma unroll
        for (int rr = 0; rr < 128; rr += 64) {
            float4 va = *(const float4*)&A[(size_t)(m0 + lr + rr) * K + k0 + lk];
            As[lk + 0][lr + rr] = va.x; As[lk + 1][lr + rr] = va.y;
            As[lk + 2][lr + rr] = va.z; As[lk + 3][lr + rr] = va.w;
            float4 vb = *(const float4*)&B[(size_t)(n0 + lr + rr) * K + k0 + lk];
            Bs[lk + 0][lr + rr] = vb.x; Bs[lk + 1][lr + rr] = vb.y;
            Bs[lk + 2][lr + rr] = vb.z; Bs[lk + 3][lr + rr] = vb.w;
        }
        __syncthreads();
#pragma unroll
        for (int k = 0; k < 16; k++) {
            float a[8], b[8];
            *(float4*)(a + 0) = *(float4*)&As[k][i * 8 + 0];
            *(float4*)(a + 4) = *(float4*)&As[k][i * 8 + 4];
            *(float4*)(b + 0) = *(float4*)&Bs[k][j * 8 + 0];
            *(float4*)(b + 4) = *(float4*)&Bs[k][j * 8 + 4];
#pragma unroll
            for (int r = 0; r < 8; r++)
#pragma unroll
                for (int c = 0; c < 8; c++)
                    acc[r][c] = fmaf(a[r], b[c], acc[r][c]);
        }
        __syncthreads();
    }

    float bvals[8];
    *(float4*)(bvals + 0) = *(const float4*)&bias[n0 + j * 8 + 0];
    *(float4*)(bvals + 4) = *(const float4*)&bias[n0 + j * 8 + 4];

#pragma unroll
    for (int r = 0; r < 8; r++) {
        int row = m0 + i * 8 + r;
        float outv[8];
        if (EPI == 1) {
            *(float4*)(outv + 0) = *(const float4*)&res[(size_t)row * N + n0 + j * 8 + 0];
            *(float4*)(outv + 4) = *(const float4*)&res[(size_t)row * N + n0 + j * 8 + 4];
        }
#pragma unroll
        for (int c = 0; c < 8; c++) {
            float x = acc[r][c] + bvals[c];
            if (EPI == 0) {
                x = 0.5f * x * (1.0f + erff(x * 0.70710678118654752f));
                outv[c] = x;
            } else {
                outv[c] += x;
            }
        }
        *(float4*)&C[(size_t)row * N + n0 + j * 8 + 0] = *(float4*)(outv + 0);
        *(float4*)&C[(size_t)row * N + n0 + j * 8 + 4] = *(float4*)(outv + 4);
    }
}

__global__ void __launch_bounds__(256, 2) gemm1_kernel(const float* __restrict__ fc1_w,
                                                       const float* __restrict__ fc1_b) {
    gemm_nt_body<0>(g_mho, fc1_w, fc1_b, nullptr, g_h, DFF, DM);
}

__global__ void __launch_bounds__(256, 2) gemm2_kernel(const float* __restrict__ fc2_w,
                                                       const float* __restrict__ fc2_b,
                                                       float* __restrict__ out) {
    gemm_nt_body<1>(g_h, fc2_w, fc2_b, g_mho, out, DM, DFF);
}

// ---------------- launch ---------------------------------------------------
extern "C" void kernel_launch(void* const* d_in, const int* in_sizes, int n_in,
                              void* d_out, int out_size) {
    const float* frame = (const float*)d_in[0];
    const float* W_q   = (const float*)d_in[1];
    const float* W_k   = (const float*)d_in[2];
    const float* W_v   = (const float*)d_in[3];
    const float* W_o   = (const float*)d_in[4];
    const float* fc1_w = (const float*)d_in[5];
    const float* fc1_b = (const float*)d_in[6];
    const float* fc2_w = (const float*)d_in[7];
    const float* fc2_b = (const float*)d_in[8];
    float* out = (float*)d_out;

    pack_weights<<<96, 256>>>(W_q, W_k, W_v, W_o);
    qkv_kernel<<<S_LEN / 128, 256>>>(frame);
    attn_kernel<<<S_LEN / 32, 1024>>>();
    mho_kernel<<<S_LEN / 8, 256>>>();
    gemm1_kernel<<<dim3(DFF / 128, S_LEN / 128), 256>>>(fc1_w, fc1_b);
    gemm2_kernel<<<dim3(DM / 128, S_LEN / 128), 256>>>(fc2_w, fc2_b, out);
}

// round 3
// speedup vs baseline: 1.5755x; 1.5755x over previous
#include <cuda_runtime.h>
#include <cuda_fp16.h>
#include <math.h>
#include <stdint.h>

#define S_LEN 8192
#define DM    512
#define DK    16
#define DFF   2048

// ---------------- scratch (static device globals) -------------------------
__device__ __align__(256) float g_Wqkv[DM * 48];
__device__ __align__(256) float g_Woeff[DK * DM];
__device__ __align__(256) float g_Q[S_LEN * DK];
__device__ __align__(256) float g_K[S_LEN * DK];
__device__ __align__(256) float g_V[S_LEN * DK];
__device__ __align__(256) float g_head[S_LEN * DK];
__device__ __align__(256) float g_mho[S_LEN * DM];    // fp32 (residual)
__device__ __align__(256) __half g_mhoh[S_LEN * DM];  // mho hi (fp16)
__device__ __align__(256) __half g_mhol[S_LEN * DM];  // mho lo
__device__ __align__(256) __half g_hh[S_LEN * DFF];   // gelu(h) hi
__device__ __align__(256) __half g_hl[S_LEN * DFF];   // gelu(h) lo
__device__ __align__(256) __half g_w1h[DFF * DM];
__device__ __align__(256) __half g_w1l[DFF * DM];
__device__ __align__(256) __half g_w2h[DM * DFF];
__device__ __align__(256) __half g_w2l[DM * DFF];

// ---------------- helpers ---------------------------------------------------
__device__ __forceinline__ uint32_t smem_u32(const void* p) {
    uint32_t a;
    asm("{ .reg .u64 t; cvta.to.shared.u64 t, %1; cvt.u32.u64 %0, t; }" : "=r"(a) : "l"(p));
    return a;
}
__device__ __forceinline__ void cp16(uint32_t dst, const void* src) {
    asm volatile("cp.async.cg.shared.global [%0], [%1], 16;" :: "r"(dst), "l"(src) : "memory");
}
__device__ __forceinline__ void cp_commit() {
    asm volatile("cp.async.commit_group;" ::: "memory");
}
template <int P>
__device__ __forceinline__ void cp_wait() {
    asm volatile("cp.async.wait_group %0;" :: "n"(P) : "memory");
}
__device__ __forceinline__ void ldsm4(uint32_t addr, uint32_t& r0, uint32_t& r1,
                                      uint32_t& r2, uint32_t& r3) {
    asm volatile("ldmatrix.sync.aligned.m8n8.x4.shared.b16 {%0,%1,%2,%3}, [%4];"
                 : "=r"(r0), "=r"(r1), "=r"(r2), "=r"(r3) : "r"(addr));
}
__device__ __forceinline__ void mma16816(float* c, const uint32_t* a,
                                         uint32_t b0, uint32_t b1) {
    asm volatile(
        "mma.sync.aligned.m16n8k16.row.col.f32.f16.f16.f32 "
        "{%0,%1,%2,%3}, {%4,%5,%6,%7}, {%8,%9}, {%0,%1,%2,%3};"
        : "+f"(c[0]), "+f"(c[1]), "+f"(c[2]), "+f"(c[3])
        : "r"(a[0]), "r"(a[1]), "r"(a[2]), "r"(a[3]), "r"(b0), "r"(b1));
}
__device__ __forceinline__ void h_split(float x, __half& hi, __half& lo) {
    hi = __float2half_rn(x);
    lo = __float2half_rn(x - __half2float(hi));
}

// ---------------- weight packing ------------------------------------------
__global__ void pack_weights(const float* __restrict__ Wq,
                             const float* __restrict__ Wk,
                             const float* __restrict__ Wv,
                             const float* __restrict__ Wo) {
    int idx = blockIdx.x * blockDim.x + threadIdx.x;
    if (idx < DM * 48) {
        int d = idx / 48, c = idx % 48;
        float v;
        if (c < 16)      v = Wq[d * 16 + c];
        else if (c < 32) v = Wk[d * 16 + c - 16];
        else             v = Wv[d * 16 + c - 32];
        g_Wqkv[idx] = v;
    }
    if (idx < DK * DM) {
        int i = idx / DM, c = idx % DM;
        float s = 0.f;
#pragma unroll
        for (int h = 0; h < 8; h++) s += Wo[(h * 16 + i) * DM + c];
        g_Woeff[idx] = s;
    }
}

__global__ void conv_weights(const float* __restrict__ w1, const float* __restrict__ w2) {
    int i = blockIdx.x * blockDim.x + threadIdx.x;
    if (i < DFF * DM) {
        __half h, l;
        h_split(w1[i], h, l);
        g_w1h[i] = h; g_w1l[i] = l;
        h_split(w2[i], h, l);
        g_w2h[i] = h; g_w2l[i] = l;
    }
}

// ---------------- fused QKV projection ------------------------------------
__global__ void __launch_bounds__(256) qkv_kernel(const float* __restrict__ frame) {
    __shared__ float Fs[128][33];
    __shared__ float Ws[32][48];
    int t = threadIdx.x;
    int m0 = blockIdx.x * 128;
    int r = t & 127;
    int hv = t >> 7;
    float acc[24];
#pragma unroll
    for (int c = 0; c < 24; c++) acc[c] = 0.f;

    int lrow = t >> 3;
    int lds  = (t & 7) * 4;

    for (int d0 = 0; d0 < DM; d0 += 32) {
#pragma unroll
        for (int rr = 0; rr < 128; rr += 32) {
            float4 v = *(const float4*)&frame[(size_t)(m0 + lrow + rr) * DM + d0 + lds];
            Fs[lrow + rr][lds + 0] = v.x;
            Fs[lrow + rr][lds + 1] = v.y;
            Fs[lrow + rr][lds + 2] = v.z;
            Fs[lrow + rr][lds + 3] = v.w;
        }
        for (int q = t; q < 32 * 48; q += 256)
            Ws[q / 48][q % 48] = g_Wqkv[(d0 + q / 48) * 48 + (q % 48)];
        __syncthreads();
#pragma unroll
        for (int d = 0; d < 32; d++) {
            float f = Fs[r][d];
#pragma unroll
            for (int c = 0; c < 24; c++)
                acc[c] = fmaf(f, Ws[d][hv * 24 + c], acc[c]);
        }
        __syncthreads();
    }
    int row = m0 + r;
#pragma unroll
    for (int c = 0; c < 24; c++) {
        int cg = hv * 24 + c;
        float v = acc[c];
        if (cg < 16)      g_Q[row * 16 + cg]      = v;
        else if (cg < 32) g_K[row * 16 + cg - 16] = v;
        else              g_V[row * 16 + cg - 32] = v;
    }
}

// ---------------- flash attention ------------------------------------------
__global__ void __launch_bounds__(1024, 1) attn_kernel() {
    const int TK = 256;
    __shared__ float Ks[TK][17];
    __shared__ float Vs[TK][17];
    int t = threadIdx.x;
    int warp = t >> 5, lane = t & 31;
    int q = blockIdx.x * 32 + warp;

    float qreg[16];
#pragma unroll
    for (int i = 0; i < 16; i++) qreg[i] = g_Q[q * 16 + i];

    float m = -INFINITY, l = 0.f;
    float acc[16];
#pragma unroll
    for (int i = 0; i < 16; i++) acc[i] = 0.f;

    int jl  = t >> 2;
    int il4 = (t & 3) * 4;

    for (int k0 = 0; k0 < S_LEN; k0 += TK) {
        {
            float4 kv = *(const float4*)&g_K[(size_t)(k0 + jl) * 16 + il4];
            Ks[jl][il4 + 0] = kv.x; Ks[jl][il4 + 1] = kv.y;
            Ks[jl][il4 + 2] = kv.z; Ks[jl][il4 + 3] = kv.w;
            float4 vv = *(const float4*)&g_V[(size_t)(k0 + jl) * 16 + il4];
            Vs[jl][il4 + 0] = vv.x; Vs[jl][il4 + 1] = vv.y;
            Vs[jl][il4 + 2] = vv.z; Vs[jl][il4 + 3] = vv.w;
        }
        __syncthreads();
#pragma unroll 1
        for (int it = 0; it < TK / 32; it++) {
            int j = it * 32 + lane;
            float s = 0.f;
#pragma unroll
            for (int i = 0; i < 16; i++) s = fmaf(qreg[i], Ks[j][i], s);
            s *= 0.25f;
            float p;
            if (s > m) {
                float corr = __expf(m - s);
                l *= corr;
#pragma unroll
                for (int i = 0; i < 16; i++) acc[i] *= corr;
                m = s;
                p = 1.f;
            } else {
                p = __expf(s - m);
            }
            l += p;
#pragma unroll
            for (int i = 0; i < 16; i++) acc[i] = fmaf(p, Vs[j][i], acc[i]);
        }
        __syncthreads();
    }

    float mmax = m;
#pragma unroll
    for (int off = 16; off; off >>= 1)
        mmax = fmaxf(mmax, __shfl_xor_sync(0xffffffffu, mmax, off));
    float sc = __expf(m - mmax);
    l *= sc;
#pragma unroll
    for (int i = 0; i < 16; i++) acc[i] *= sc;
#pragma unroll
    for (int off = 16; off; off >>= 1)
        l += __shfl_xor_sync(0xffffffffu, l, off);
#pragma unroll
    for (int i = 0; i < 16; i++) {
        float a = acc[i];
#pragma unroll
        for (int off = 16; off; off >>= 1)
            a += __shfl_xor_sync(0xffffffffu, a, off);
        acc[i] = a;
    }
    if (lane == 0) {
        float inv = 1.f / l;
#pragma unroll
        for (int i = 0; i < 16; i++) g_head[q * 16 + i] = acc[i] * inv;
    }
}

// ---------------- mho = head @ Woeff (fp32 + fp16 hi/lo) -------------------
__global__ void __launch_bounds__(256) mho_kernel() {
    __shared__ float hrow[8][16];
    int t = threadIdx.x;
    int r0 = blockIdx.x * 8;
    if (t < 128) hrow[t >> 4][t & 15] = g_head[r0 * 16 + t];
    __syncthreads();

    int cg = (t & 127) * 4;
    int rb = (t >> 7) * 4;
    float4 a[4];
#pragma unroll
    for (int r = 0; r < 4; r++) a[r] = make_float4(0.f, 0.f, 0.f, 0.f);
#pragma unroll
    for (int i = 0; i < 16; i++) {
        float4 w = *(const float4*)&g_Woeff[i * 512 + cg];
#pragma unroll
        for (int r = 0; r < 4; r++) {
            float h = hrow[rb + r][i];
            a[r].x = fmaf(h, w.x, a[r].x); a[r].y = fmaf(h, w.y, a[r].y);
            a[r].z = fmaf(h, w.z, a[r].z); a[r].w = fmaf(h, w.w, a[r].w);
        }
    }
#pragma unroll
    for (int r = 0; r < 4; r++) {
        size_t base = (size_t)(r0 + rb + r) * 512 + cg;
        *(float4*)&g_mho[base] = a[r];
        float v[4] = {a[r].x, a[r].y, a[r].z, a[r].w};
        __half hi[4], lo[4];
#pragma unroll
        for (int k = 0; k < 4; k++) h_split(v[k], hi[k], lo[k]);
        __half2 h01, h23, l01, l23;
        h01.x = hi[0]; h01.y = hi[1]; h23.x = hi[2]; h23.y = hi[3];
        l01.x = lo[0]; l01.y = lo[1]; l23.x = lo[2]; l23.y = lo[3];
        *(__half2*)&g_mhoh[base + 0] = h01;
        *(__half2*)&g_mhoh[base + 2] = h23;
        *(__half2*)&g_mhol[base + 0] = l01;
        *(__half2*)&g_mhol[base + 2] = l23;
    }
}

// ---------------- HMMA split-fp16 GEMM --------------------------------------
// C[M,N] = A[M,K]*B[N,K]^T via Ah*Bh + Ah*Bl + Al*Bh, fp32 accum.
// EPI 0: gelu(x+bias) -> fp16 hi/lo (g_hh/g_hl) ; EPI 1: x+bias+res -> fp32 out
static constexpr int KC      = 64;                 // K per chunk
static constexpr int STR_H   = 72;                 // padded row stride in halves
static constexpr int TILE_B  = 128 * STR_H * 2;    // 18432 B
static constexpr int STAGE_B = 4 * TILE_B;         // Ah|Al|Bh|Bl = 73728 B
static constexpr int SMEM_B  = 2 * STAGE_B;        // 147456 B

__device__ __forceinline__ void load_tile(uint32_t dst, const __half* __restrict__ g,
                                          int row0, int k0, int ldk, int t) {
#pragma unroll
    for (int i = 0; i < 4; i++) {
        int q = t + i * 256;        // 0..1023 : 128 rows x 8 granules(16B)
        int r = q >> 3, gr = q & 7;
        cp16(dst + (uint32_t)r * (STR_H * 2) + (uint32_t)gr * 16,
             g + (size_t)(row0 + r) * ldk + k0 + gr * 8);
    }
}

template <int KTOT, int EPI>
__global__ void __launch_bounds__(256, 1) gemm_hmma(
    const float* __restrict__ bias, float* __restrict__ outf)
{
    extern __shared__ __align__(128) char sm[];
    uint32_t sbase = smem_u32(sm);

    const __half* Ahp = (EPI == 0) ? g_mhoh : g_hh;
    const __half* Alp = (EPI == 0) ? g_mhol : g_hl;
    const __half* Bhp = (EPI == 0) ? g_w1h  : g_w2h;
    const __half* Blp = (EPI == 0) ? g_w1l  : g_w2l;
    const int N = (EPI == 0) ? DFF : DM;

    int t = threadIdx.x;
    int wid = t >> 5, lane = t & 31;
    int wm = wid & 3, wn = wid >> 2;           // 4 m-warps x 2 n-warps
    int m0 = blockIdx.y * 128;
    int n0 = blockIdx.x * 128;
    const int NC = KTOT / KC;

    // lane offsets for ldmatrix addressing
    int a_row = (lane & 15);                   // within 16-row mtile
    int a_kg  = (lane >> 4);                   // 0/1 -> +8 halves
    int b_row = ((lane >> 4) << 3) + (lane & 7);
    int b_kg  = (lane >> 3) & 1;

    float acc[2][8][4];
#pragma unroll
    for (int i = 0; i < 2; i++)
#pragma unroll
        for (int j = 0; j < 8; j++)
#pragma unroll
            for (int k = 0; k < 4; k++) acc[i][j][k] = 0.f;

    // prologue: chunks 0,1
    load_tile(sbase + 0 * TILE_B, Ahp, m0, 0, KTOT, t);
    load_tile(sbase + 1 * TILE_B, Alp, m0, 0, KTOT, t);
    load_tile(sbase + 2 * TILE_B, Bhp, n0, 0, KTOT, t);
    load_tile(sbase + 3 * TILE_B, Blp, n0, 0, KTOT, t);
    cp_commit();
    load_tile(sbase + STAGE_B + 0 * TILE_B, Ahp, m0, KC, KTOT, t);
    load_tile(sbase + STAGE_B + 1 * TILE_B, Alp, m0, KC, KTOT, t);
    load_tile(sbase + STAGE_B + 2 * TILE_B, Bhp, n0, KC, KTOT, t);
    load_tile(sbase + STAGE_B + 3 * TILE_B, Blp, n0, KC, KTOT, t);
    cp_commit();

    for (int c = 0; c < NC; c++) {
        if (c == NC - 1) cp_wait<0>(); else cp_wait<1>();
        __syncthreads();
        uint32_t stg = sbase + (uint32_t)(c & 1) * STAGE_B;
        uint32_t sAh = stg, sAl = stg + TILE_B, sBh = stg + 2 * TILE_B, sBl = stg + 3 * TILE_B;

#pragma unroll
        for (int ks = 0; ks < KC / 16; ks++) {
            uint32_t ah[2][4], al[2][4];
#pragma unroll
            for (int mt = 0; mt < 2; mt++) {
                uint32_t off = (uint32_t)(wm * 32 + mt * 16 + a_row) * (STR_H * 2)
                             + (uint32_t)(ks * 2 + a_kg) * 16;
                ldsm4(sAh + off, ah[mt][0], ah[mt][1], ah[mt][2], ah[mt][3]);
                ldsm4(sAl + off, al[mt][0], al[mt][1], al[mt][2], al[mt][3]);
            }
#pragma unroll
            for (int np = 0; np < 4; np++) {
                uint32_t boff = (uint32_t)(wn * 64 + np * 16 + b_row) * (STR_H * 2)
                              + (uint32_t)(ks * 2 + b_kg) * 16;
                uint32_t bh0, bh1, bh2, bh3, bl0, bl1, bl2, bl3;
                ldsm4(sBh + boff, bh0, bh1, bh2, bh3);
                ldsm4(sBl + boff, bl0, bl1, bl2, bl3);
#pragma unroll
                for (int mt = 0; mt < 2; mt++) {
                    float* c0 = acc[mt][np * 2 + 0];
                    float* c1 = acc[mt][np * 2 + 1];
                    mma16816(c0, ah[mt], bh0, bh1);
                    mma16816(c0, ah[mt], bl0, bl1);
                    mma16816(c0, al[mt], bh0, bh1);
                    mma16816(c1, ah[mt], bh2, bh3);
                    mma16816(c1, ah[mt], bl2, bl3);
                    mma16816(c1, al[mt], bh2, bh3);
                }
            }
        }
        __syncthreads();
        if (c + 2 < NC) {
            int k0 = (c + 2) * KC;
            load_tile(stg + 0 * TILE_B, Ahp, m0, k0, KTOT, t);
            load_tile(stg + 1 * TILE_B, Alp, m0, k0, KTOT, t);
            load_tile(stg + 2 * TILE_B, Bhp, n0, k0, KTOT, t);
            load_tile(stg + 3 * TILE_B, Blp, n0, k0, KTOT, t);
            cp_commit();
        }
    }

    // ---------------- epilogue: stage accums to smem, then coalesced out ---
    float* eb = (float*)sm;                     // 128 x 132 fp32 = 67584 B
#pragma unroll
    for (int mt = 0; mt < 2; mt++) {
#pragma unroll
        for (int nt = 0; nt < 8; nt++) {
            int row = wm * 32 + mt * 16 + (lane >> 2);
            int col = wn * 64 + nt * 8 + (lane & 3) * 2;
            float* p0 = &eb[row * 132 + col];
            p0[0] = acc[mt][nt][0]; p0[1] = acc[mt][nt][1];
            float* p1 = &eb[(row + 8) * 132 + col];
            p1[0] = acc[mt][nt][2]; p1[1] = acc[mt][nt][3];
        }
    }
    __syncthreads();

    int cp2 = (t & 63) * 2;
    float b0 = bias[n0 + cp2], b1 = bias[n0 + cp2 + 1];
#pragma unroll 4
    for (int i = 0; i < 32; i++) {
        int row = (t >> 6) + i * 4;
        float2 v = *(float2*)&eb[row * 132 + cp2];
        float x0 = v.x + b0, x1 = v.y + b1;
        size_t oidx = (size_t)(m0 + row) * N + n0 + cp2;
        if (EPI == 0) {
            x0 = 0.5f * x0 * (1.0f + erff(x0 * 0.70710678118654752f));
            x1 = 0.5f * x1 * (1.0f + erff(x1 * 0.70710678118654752f));
            __half h0, l0, h1, l1;
            h_split(x0, h0, l0);
            h_split(x1, h1, l1);
            __half2 hp, lp;
            hp.x = h0; hp.y = h1; lp.x = l0; lp.y = l1;
            *(__half2*)&g_hh[oidx] = hp;
            *(__half2*)&g_hl[oidx] = lp;
        } else {
            float2 rr = *(const float2*)&g_mho[oidx];
            *(float2*)&outf[oidx] = make_float2(x0 + rr.x, x1 + rr.y);
        }
    }
}

// ---------------- launch ---------------------------------------------------
extern "C" void kernel_launch(void* const* d_in, const int* in_sizes, int n_in,
                              void* d_out, int out_size) {
    const float* frame = (const float*)d_in[0];
    const float* W_q   = (const float*)d_in[1];
    const float* W_k   = (const float*)d_in[2];
    const float* W_v   = (const float*)d_in[3];
    const float* W_o   = (const float*)d_in[4];
    const float* fc1_w = (const float*)d_in[5];
    const float* fc1_b = (const float*)d_in[6];
    const float* fc2_w = (const float*)d_in[7];
    const float* fc2_b = (const float*)d_in[8];
    float* out = (float*)d_out;

    cudaFuncSetAttribute(gemm_hmma<DM, 0>,
                         cudaFuncAttributeMaxDynamicSharedMemorySize, SMEM_B);
    cudaFuncSetAttribute(gemm_hmma<DFF, 1>,
                         cudaFuncAttributeMaxDynamicSharedMemorySize, SMEM_B);

    pack_weights<<<96, 256>>>(W_q, W_k, W_v, W_o);
    conv_weights<<<(DFF * DM + 255) / 256, 256>>>(fc1_w, fc2_w);
    qkv_kernel<<<S_LEN / 128, 256>>>(frame);
    attn_kernel<<<S_LEN / 32, 1024>>>();
    mho_kernel<<<S_LEN / 8, 256>>>();

    gemm_hmma<DM, 0><<<dim3(DFF / 128, S_LEN / 128), 256, SMEM_B>>>(fc1_b, nullptr);
    gemm_hmma<DFF, 1><<<dim3(DM / 128, S_LEN / 128), 256, SMEM_B>>>(fc2_b, out);
}

// round 4
// speedup vs baseline: 2.3507x; 1.4921x over previous
#include <cuda_runtime.h>
#include <cuda_fp16.h>
#include <math.h>
#include <stdint.h>

#define S_LEN 8192
#define DM    512
#define DK    16
#define DFF   2048

// ---------------- scratch (static device globals) -------------------------
__device__ __align__(256) float g_Wqkv[DM * 48];
__device__ __align__(256) float g_Woeff[DK * DM];
__device__ __align__(256) float g_head[S_LEN * DK];
__device__ __align__(256) float g_mho[S_LEN * DM];    // fp32 (residual)
__device__ __align__(256) __half g_mhoh[S_LEN * DM];  // mho hi (fp16)
__device__ __align__(256) __half g_mhol[S_LEN * DM];  // mho lo
__device__ __align__(256) __half g_hh[S_LEN * DFF];   // gelu(h) hi
__device__ __align__(256) __half g_hl[S_LEN * DFF];   // gelu(h) lo
__device__ __align__(256) __half g_w1h[DFF * DM];
__device__ __align__(256) __half g_w1l[DFF * DM];
__device__ __align__(256) __half g_w2h[DM * DFF];
__device__ __align__(256) __half g_w2l[DM * DFF];
// attention fp16 operands
__device__ __align__(256) __half g_Qh[S_LEN * DK];    // scaled by 0.25*log2e
__device__ __align__(256) __half g_Ql[S_LEN * DK];
__device__ __align__(256) __half g_Kh[S_LEN * DK];
__device__ __align__(256) __half g_Kl[S_LEN * DK];
__device__ __align__(256) __half g_Vph[S_LEN * 24];   // V padded: col16=1, 17-23=0
__device__ __align__(256) __half g_Vpl[S_LEN * 24];   // lo part, col16-23=0

#define QSCALE 0.36067376022224085f   // 0.25 * log2(e)

// ---------------- helpers ---------------------------------------------------
__device__ __forceinline__ uint32_t smem_u32(const void* p) {
    uint32_t a;
    asm("{ .reg .u64 t; cvta.to.shared.u64 t, %1; cvt.u32.u64 %0, t; }" : "=r"(a) : "l"(p));
    return a;
}
__device__ __forceinline__ void cp16(uint32_t dst, const void* src) {
    asm volatile("cp.async.cg.shared.global [%0], [%1], 16;" :: "r"(dst), "l"(src) : "memory");
}
__device__ __forceinline__ void cp_commit() {
    asm volatile("cp.async.commit_group;" ::: "memory");
}
template <int P>
__device__ __forceinline__ void cp_wait() {
    asm volatile("cp.async.wait_group %0;" :: "n"(P) : "memory");
}
__device__ __forceinline__ void ldsm4(uint32_t addr, uint32_t& r0, uint32_t& r1,
                                      uint32_t& r2, uint32_t& r3) {
    asm volatile("ldmatrix.sync.aligned.m8n8.x4.shared.b16 {%0,%1,%2,%3}, [%4];"
                 : "=r"(r0), "=r"(r1), "=r"(r2), "=r"(r3) : "r"(addr));
}
__device__ __forceinline__ void ldsm4t(uint32_t addr, uint32_t& r0, uint32_t& r1,
                                       uint32_t& r2, uint32_t& r3) {
    asm volatile("ldmatrix.sync.aligned.m8n8.x4.trans.shared.b16 {%0,%1,%2,%3}, [%4];"
                 : "=r"(r0), "=r"(r1), "=r"(r2), "=r"(r3) : "r"(addr));
}
__device__ __forceinline__ void ldsm2t(uint32_t addr, uint32_t& r0, uint32_t& r1) {
    asm volatile("ldmatrix.sync.aligned.m8n8.x2.trans.shared.b16 {%0,%1}, [%2];"
                 : "=r"(r0), "=r"(r1) : "r"(addr));
}
__device__ __forceinline__ void mma16816(float* c, const uint32_t* a,
                                         uint32_t b0, uint32_t b1) {
    asm volatile(
        "mma.sync.aligned.m16n8k16.row.col.f32.f16.f16.f32 "
        "{%0,%1,%2,%3}, {%4,%5,%6,%7}, {%8,%9}, {%0,%1,%2,%3};"
        : "+f"(c[0]), "+f"(c[1]), "+f"(c[2]), "+f"(c[3])
        : "r"(a[0]), "r"(a[1]), "r"(a[2]), "r"(a[3]), "r"(b0), "r"(b1));
}
__device__ __forceinline__ void mma16816_z(float* c, const uint32_t* a,
                                           uint32_t b0, uint32_t b1) {
    float z = 0.f;
    asm volatile(
        "mma.sync.aligned.m16n8k16.row.col.f32.f16.f16.f32 "
        "{%0,%1,%2,%3}, {%4,%5,%6,%7}, {%8,%9}, {%10,%10,%10,%10};"
        : "=f"(c[0]), "=f"(c[1]), "=f"(c[2]), "=f"(c[3])
        : "r"(a[0]), "r"(a[1]), "r"(a[2]), "r"(a[3]), "r"(b0), "r"(b1), "f"(z));
}
__device__ __forceinline__ float ex2f(float x) {
    float y;
    asm("ex2.approx.ftz.f32 %0, %1;" : "=f"(y) : "f"(x));
    return y;
}
__device__ __forceinline__ uint32_t f16x2_pack(float hi, float lo) {
    uint32_t d;
    asm("cvt.rn.f16x2.f32 %0, %1, %2;" : "=r"(d) : "f"(hi), "f"(lo));
    return d;
}
__device__ __forceinline__ void h_split(float x, __half& hi, __half& lo) {
    hi = __float2half_rn(x);
    lo = __float2half_rn(x - __half2float(hi));
}

// ---------------- weight packing ------------------------------------------
__global__ void pack_weights(const float* __restrict__ Wq,
                             const float* __restrict__ Wk,
                             const float* __restrict__ Wv,
                             const float* __restrict__ Wo) {
    int idx = blockIdx.x * blockDim.x + threadIdx.x;
    if (idx < DM * 48) {
        int d = idx / 48, c = idx % 48;
        float v;
        if (c < 16)      v = Wq[d * 16 + c];
        else if (c < 32) v = Wk[d * 16 + c - 16];
        else             v = Wv[d * 16 + c - 32];
        g_Wqkv[idx] = v;
    }
    if (idx < DK * DM) {
        int i = idx / DM, c = idx % DM;
        float s = 0.f;
#pragma unroll
        for (int h = 0; h < 8; h++) s += Wo[(h * 16 + i) * DM + c];
        g_Woeff[idx] = s;
    }
}

__global__ void conv_weights(const float* __restrict__ w1, const float* __restrict__ w2) {
    int i = blockIdx.x * blockDim.x + threadIdx.x;
    if (i < DFF * DM) {
        __half h, l;
        h_split(w1[i], h, l);
        g_w1h[i] = h; g_w1l[i] = l;
        h_split(w2[i], h, l);
        g_w2h[i] = h; g_w2l[i] = l;
    }
}

// ---------------- fused QKV projection (emits fp16 hi/lo) ------------------
__global__ void __launch_bounds__(256) qkv_kernel(const float* __restrict__ frame) {
    __shared__ float Fs[128][33];
    __shared__ float Ws[32][48];
    int t = threadIdx.x;
    int m0 = blockIdx.x * 128;
    int r = t & 127;
    int hv = t >> 7;
    float acc[24];
#pragma unroll
    for (int c = 0; c < 24; c++) acc[c] = 0.f;

    int lrow = t >> 3;
    int lds  = (t & 7) * 4;

    for (int d0 = 0; d0 < DM; d0 += 32) {
#pragma unroll
        for (int rr = 0; rr < 128; rr += 32) {
            float4 v = *(const float4*)&frame[(size_t)(m0 + lrow + rr) * DM + d0 + lds];
            Fs[lrow + rr][lds + 0] = v.x;
            Fs[lrow + rr][lds + 1] = v.y;
            Fs[lrow + rr][lds + 2] = v.z;
            Fs[lrow + rr][lds + 3] = v.w;
        }
        for (int q = t; q < 32 * 48; q += 256)
            Ws[q / 48][q % 48] = g_Wqkv[(d0 + q / 48) * 48 + (q % 48)];
        __syncthreads();
#pragma unroll
        for (int d = 0; d < 32; d++) {
            float f = Fs[r][d];
#pragma unroll
            for (int c = 0; c < 24; c++)
                acc[c] = fmaf(f, Ws[d][hv * 24 + c], acc[c]);
        }
        __syncthreads();
    }
    int row = m0 + r;
#pragma unroll
    for (int c = 0; c < 24; c++) {
        int cg = hv * 24 + c;
        __half h, l;
        if (cg < 16) {
            h_split(acc[c] * QSCALE, h, l);
            g_Qh[row * 16 + cg] = h;
            g_Ql[row * 16 + cg] = l;
        } else if (cg < 32) {
            h_split(acc[c], h, l);
            g_Kh[row * 16 + cg - 16] = h;
            g_Kl[row * 16 + cg - 16] = l;
        } else {
            h_split(acc[c], h, l);
            g_Vph[row * 24 + cg - 32] = h;
            g_Vpl[row * 24 + cg - 32] = l;
        }
    }
    if (hv == 1) {
#pragma unroll
        for (int c2 = 16; c2 < 24; c2++) {
            g_Vph[row * 24 + c2] = (c2 == 16) ? __float2half_rn(1.0f) : __float2half_rn(0.0f);
            g_Vpl[row * 24 + c2] = __float2half_rn(0.0f);
        }
    }
}

// ---------------- tensor-core flash attention -------------------------------
// CTA: 64 queries, 4 warps (16 q-rows each). K-tiles of 128, cp.async 2-stage.
// S split 3-term fp16; P single fp16 (FA2 reg-layout trick); V hi/lo 2-term;
// row-sum via ones column in padded V (n=24).
static constexpr uint32_t ATT_STG  = 24576;   // Kh(6144)+Kl(6144)+Vh(6144)+Vl(6144)
static constexpr uint32_t ATT_QH   = 49152;
static constexpr uint32_t ATT_QL   = 52224;
static constexpr uint32_t ATT_SMEM = 55296;

__device__ __forceinline__ void attn_load(uint32_t stg, int k0, int t) {
#pragma unroll
    for (int i = 0; i < 2; i++) {
        int q = t + i * 128;
        int row = q >> 1, g = q & 1;
        cp16(stg + (uint32_t)row * 48 + g * 16, g_Kh + (size_t)(k0 + row) * 16 + g * 8);
        cp16(stg + 6144 + (uint32_t)row * 48 + g * 16, g_Kl + (size_t)(k0 + row) * 16 + g * 8);
    }
#pragma unroll
    for (int i = 0; i < 3; i++) {
        int q = t + i * 128;
        int row = q / 3, g = q % 3;
        cp16(stg + 12288 + (uint32_t)row * 48 + g * 16, g_Vph + (size_t)(k0 + row) * 24 + g * 8);
        cp16(stg + 18432 + (uint32_t)row * 48 + g * 16, g_Vpl + (size_t)(k0 + row) * 24 + g * 8);
    }
}

__global__ void __launch_bounds__(128, 2) attn_tc() {
    extern __shared__ __align__(128) char sm[];
    uint32_t sb = smem_u32(sm);
    int t = threadIdx.x, lane = t & 31, w = t >> 5;
    int q0 = blockIdx.x * 64;

    // prologue: Q + tile0 in group0, tile1 in group1
    {
        int row = t >> 1, g = t & 1;
        cp16(sb + ATT_QH + (uint32_t)row * 48 + g * 16, g_Qh + (size_t)(q0 + row) * 16 + g * 8);
        cp16(sb + ATT_QL + (uint32_t)row * 48 + g * 16, g_Ql + (size_t)(q0 + row) * 16 + g * 8);
    }
    attn_load(sb, 0, t);
    cp_commit();
    attn_load(sb + ATT_STG, 128, t);
    cp_commit();

    uint32_t aQ  = sb + ATT_QH + (uint32_t)(w * 16 + (lane & 15)) * 48 + (uint32_t)(lane >> 4) * 16;
    uint32_t aK  = (uint32_t)((lane & 7) + ((lane >> 4) & 1) * 8) * 48 + (uint32_t)((lane >> 3) & 1) * 16;
    uint32_t aV4 = (uint32_t)((lane & 7) + ((lane >> 3) & 1) * 8) * 48 + (uint32_t)(lane >> 4) * 16;
    uint32_t aV2 = (uint32_t)((lane & 7) + ((lane >> 3) & 1) * 8) * 48 + 32;

    uint32_t QH[4], QL[4];
    float o[3][4];
#pragma unroll
    for (int i = 0; i < 3; i++)
#pragma unroll
        for (int j = 0; j < 4; j++) o[i][j] = 0.f;
    float m0 = -INFINITY, m8 = -INFINITY;

    for (int c = 0; c < 64; c++) {
        if (c == 63) cp_wait<0>(); else cp_wait<1>();
        __syncthreads();
        if (c == 0) {
            ldsm4(aQ, QH[0], QH[1], QH[2], QH[3]);
            ldsm4(aQ + (ATT_QL - ATT_QH), QL[0], QL[1], QL[2], QL[3]);
        }
        uint32_t stg = sb + (uint32_t)(c & 1) * ATT_STG;

        // --- S = Qs @ K^T (3-term split), 16 n8-tiles ---
        float s[16][4];
#pragma unroll
        for (int u = 0; u < 8; u++) {
            uint32_t bh0, bh1, bh2, bh3, bl0, bl1, bl2, bl3;
            ldsm4(stg + u * 768 + aK, bh0, bh1, bh2, bh3);
            ldsm4(stg + 6144 + u * 768 + aK, bl0, bl1, bl2, bl3);
            mma16816_z(s[2 * u], QH, bh0, bh1);
            mma16816(s[2 * u], QH, bl0, bl1);
            mma16816(s[2 * u], QL, bh0, bh1);
            mma16816_z(s[2 * u + 1], QH, bh2, bh3);
            mma16816(s[2 * u + 1], QH, bl2, bl3);
            mma16816(s[2 * u + 1], QL, bh2, bh3);
        }

        // --- online softmax (base-2 domain) ---
        float mx0 = s[0][0], mx8 = s[0][2];
#pragma unroll
        for (int nt = 0; nt < 16; nt++) {
            mx0 = fmaxf(mx0, fmaxf(s[nt][0], s[nt][1]));
            mx8 = fmaxf(mx8, fmaxf(s[nt][2], s[nt][3]));
        }
        mx0 = fmaxf(mx0, __shfl_xor_sync(0xffffffffu, mx0, 1));
        mx0 = fmaxf(mx0, __shfl_xor_sync(0xffffffffu, mx0, 2));
        mx8 = fmaxf(mx8, __shfl_xor_sync(0xffffffffu, mx8, 1));
        mx8 = fmaxf(mx8, __shfl_xor_sync(0xffffffffu, mx8, 2));
        float mn0 = fmaxf(m0, mx0), mn8 = fmaxf(m8, mx8);
        float c0 = ex2f(m0 - mn0), c8 = ex2f(m8 - mn8);
        m0 = mn0; m8 = mn8;
#pragma unroll
        for (int i = 0; i < 3; i++) {
            o[i][0] *= c0; o[i][1] *= c0; o[i][2] *= c8; o[i][3] *= c8;
        }
#pragma unroll
        for (int nt = 0; nt < 16; nt++) {
            s[nt][0] = ex2f(s[nt][0] - m0);
            s[nt][1] = ex2f(s[nt][1] - m0);
            s[nt][2] = ex2f(s[nt][2] - m8);
            s[nt][3] = ex2f(s[nt][3] - m8);
        }

        // --- O += P @ Vpad (P fp16 in-register, V 2-term hi/lo) ---
#pragma unroll
        for (int j = 0; j < 8; j++) {
            uint32_t a[4];
            a[0] = f16x2_pack(s[2 * j][1],     s[2 * j][0]);
            a[1] = f16x2_pack(s[2 * j][3],     s[2 * j][2]);
            a[2] = f16x2_pack(s[2 * j + 1][1], s[2 * j + 1][0]);
            a[3] = f16x2_pack(s[2 * j + 1][3], s[2 * j + 1][2]);
            uint32_t v0, v1, v2, v3, v4, v5;
            ldsm4t(stg + 12288 + j * 768 + aV4, v0, v1, v2, v3);
            ldsm2t(stg + 12288 + j * 768 + aV2, v4, v5);
            mma16816(o[0], a, v0, v1);
            mma16816(o[1], a, v2, v3);
            mma16816(o[2], a, v4, v5);
            ldsm4t(stg + 18432 + j * 768 + aV4, v0, v1, v2, v3);
            ldsm2t(stg + 18432 + j * 768 + aV2, v4, v5);
            mma16816(o[0], a, v0, v1);
            mma16816(o[1], a, v2, v3);
            mma16816(o[2], a, v4, v5);
        }
        __syncthreads();
        if (c + 2 < 64) {
            attn_load(stg, (c + 2) * 128, t);
            cp_commit();
        }
    }

    // epilogue: l is column 16 of O (ntile 2, even col of quad-base lane)
    float l0 = __shfl_sync(0xffffffffu, o[2][0], lane & 28);
    float l8 = __shfl_sync(0xffffffffu, o[2][2], lane & 28);
    float i0 = __fdividef(1.f, l0), i8 = __fdividef(1.f, l8);
    int row0 = q0 + w * 16 + (lane >> 2);
    int c4 = (lane & 3) * 2;
    *(float2*)&g_head[(size_t)row0 * 16 + c4]           = make_float2(o[0][0] * i0, o[0][1] * i0);
    *(float2*)&g_head[(size_t)row0 * 16 + 8 + c4]       = make_float2(o[1][0] * i0, o[1][1] * i0);
    *(float2*)&g_head[(size_t)(row0 + 8) * 16 + c4]     = make_float2(o[0][2] * i8, o[0][3] * i8);
    *(float2*)&g_head[(size_t)(row0 + 8) * 16 + 8 + c4] = make_float2(o[1][2] * i8, o[1][3] * i8);
}

// ---------------- mho = head @ Woeff (fp32 + fp16 hi/lo) -------------------
__global__ void __launch_bounds__(256) mho_kernel() {
    __shared__ float hrow[8][16];
    int t = threadIdx.x;
    int r0 = blockIdx.x * 8;
    if (t < 128) hrow[t >> 4][t & 15] = g_head[r0 * 16 + t];
    __syncthreads();

    int cg = (t & 127) * 4;
    int rb = (t >> 7) * 4;
    float4 a[4];
#pragma unroll
    for (int r = 0; r < 4; r++) a[r] = make_float4(0.f, 0.f, 0.f, 0.f);
#pragma unroll
    for (int i = 0; i < 16; i++) {
        float4 w = *(const float4*)&g_Woeff[i * 512 + cg];
#pragma unroll
        for (int r = 0; r < 4; r++) {
            float h = hrow[rb + r][i];
            a[r].x = fmaf(h, w.x, a[r].x); a[r].y = fmaf(h, w.y, a[r].y);
            a[r].z = fmaf(h, w.z, a[r].z); a[r].w = fmaf(h, w.w, a[r].w);
        }
    }
#pragma unroll
    for (int r = 0; r < 4; r++) {
        size_t base = (size_t)(r0 + rb + r) * 512 + cg;
        *(float4*)&g_mho[base] = a[r];
        float v[4] = {a[r].x, a[r].y, a[r].z, a[r].w};
        __half hi[4], lo[4];
#pragma unroll
        for (int k = 0; k < 4; k++) h_split(v[k], hi[k], lo[k]);
        __half2 h01, h23, l01, l23;
        h01.x = hi[0]; h01.y = hi[1]; h23.x = hi[2]; h23.y = hi[3];
        l01.x = lo[0]; l01.y = lo[1]; l23.x = lo[2]; l23.y = lo[3];
        *(__half2*)&g_mhoh[base + 0] = h01;
        *(__half2*)&g_mhoh[base + 2] = h23;
        *(__half2*)&g_mhol[base + 0] = l01;
        *(__half2*)&g_mhol[base + 2] = l23;
    }
}

// ---------------- HMMA split-fp16 GEMM --------------------------------------
static constexpr int KC      = 64;
static constexpr int STR_H   = 72;
static constexpr int TILE_B  = 128 * STR_H * 2;
static constexpr int STAGE_B = 4 * TILE_B;
static constexpr int SMEM_B  = 2 * STAGE_B;

__device__ __forceinline__ void load_tile(uint32_t dst, const __half* __restrict__ g,
                                          int row0, int k0, int ldk, int t) {
#pragma unroll
    for (int i = 0; i < 4; i++) {
        int q = t + i * 256;
        int r = q >> 3, gr = q & 7;
        cp16(dst + (uint32_t)r * (STR_H * 2) + (uint32_t)gr * 16,
             g + (size_t)(row0 + r) * ldk + k0 + gr * 8);
    }
}

template <int KTOT, int EPI>
__global__ void __launch_bounds__(256, 1) gemm_hmma(
    const float* __restrict__ bias, float* __restrict__ outf)
{
    extern __shared__ __align__(128) char sm[];
    uint32_t sbase = smem_u32(sm);

    const __half* Ahp = (EPI == 0) ? g_mhoh : g_hh;
    const __half* Alp = (EPI == 0) ? g_mhol : g_hl;
    const __half* Bhp = (EPI == 0) ? g_w1h  : g_w2h;
    const __half* Blp = (EPI == 0) ? g_w1l  : g_w2l;
    const int N = (EPI == 0) ? DFF : DM;

    int t = threadIdx.x;
    int wid = t >> 5, lane = t & 31;
    int wm = wid & 3, wn = wid >> 2;
    int m0 = blockIdx.y * 128;
    int n0 = blockIdx.x * 128;
    const int NC = KTOT / KC;

    int a_row = (lane & 15);
    int a_kg  = (lane >> 4);
    int b_row = ((lane >> 4) << 3) + (lane & 7);
    int b_kg  = (lane >> 3) & 1;

    float acc[2][8][4];
#pragma unroll
    for (int i = 0; i < 2; i++)
#pragma unroll
        for (int j = 0; j < 8; j++)
#pragma unroll
            for (int k = 0; k < 4; k++) acc[i][j][k] = 0.f;

    load_tile(sbase + 0 * TILE_B, Ahp, m0, 0, KTOT, t);
    load_tile(sbase + 1 * TILE_B, Alp, m0, 0, KTOT, t);
    load_tile(sbase + 2 * TILE_B, Bhp, n0, 0, KTOT, t);
    load_tile(sbase + 3 * TILE_B, Blp, n0, 0, KTOT, t);
    cp_commit();
    load_tile(sbase + STAGE_B + 0 * TILE_B, Ahp, m0, KC, KTOT, t);
    load_tile(sbase + STAGE_B + 1 * TILE_B, Alp, m0, KC, KTOT, t);
    load_tile(sbase + STAGE_B + 2 * TILE_B, Bhp, n0, KC, KTOT, t);
    load_tile(sbase + STAGE_B + 3 * TILE_B, Blp, n0, KC, KTOT, t);
    cp_commit();

    for (int c = 0; c < NC; c++) {
        if (c == NC - 1) cp_wait<0>(); else cp_wait<1>();
        __syncthreads();
        uint32_t stg = sbase + (uint32_t)(c & 1) * STAGE_B;
        uint32_t sAh = stg, sAl = stg + TILE_B, sBh = stg + 2 * TILE_B, sBl = stg + 3 * TILE_B;

#pragma unroll
        for (int ks = 0; ks < KC / 16; ks++) {
            uint32_t ah[2][4], al[2][4];
#pragma unroll
            for (int mt = 0; mt < 2; mt++) {
                uint32_t off = (uint32_t)(wm * 32 + mt * 16 + a_row) * (STR_H * 2)
                             + (uint32_t)(ks * 2 + a_kg) * 16;
                ldsm4(sAh + off, ah[mt][0], ah[mt][1], ah[mt][2], ah[mt][3]);
                ldsm4(sAl + off, al[mt][0], al[mt][1], al[mt][2], al[mt][3]);
            }
#pragma unroll
            for (int np = 0; np < 4; np++) {
                uint32_t boff = (uint32_t)(wn * 64 + np * 16 + b_row) * (STR_H * 2)
                              + (uint32_t)(ks * 2 + b_kg) * 16;
                uint32_t bh0, bh1, bh2, bh3, bl0, bl1, bl2, bl3;
                ldsm4(sBh + boff, bh0, bh1, bh2, bh3);
                ldsm4(sBl + boff, bl0, bl1, bl2, bl3);
#pragma unroll
                for (int mt = 0; mt < 2; mt++) {
                    float* c0 = acc[mt][np * 2 + 0];
                    float* c1 = acc[mt][np * 2 + 1];
                    mma16816(c0, ah[mt], bh0, bh1);
                    mma16816(c0, ah[mt], bl0, bl1);
                    mma16816(c0, al[mt], bh0, bh1);
                    mma16816(c1, ah[mt], bh2, bh3);
                    mma16816(c1, ah[mt], bl2, bl3);
                    mma16816(c1, al[mt], bh2, bh3);
                }
            }
        }
        __syncthreads();
        if (c + 2 < NC) {
            int k0 = (c + 2) * KC;
            load_tile(stg + 0 * TILE_B, Ahp, m0, k0, KTOT, t);
            load_tile(stg + 1 * TILE_B, Alp, m0, k0, KTOT, t);
            load_tile(stg + 2 * TILE_B, Bhp, n0, k0, KTOT, t);
            load_tile(stg + 3 * TILE_B, Blp, n0, k0, KTOT, t);
            cp_commit();
        }
    }

    float* eb = (float*)sm;
#pragma unroll
    for (int mt = 0; mt < 2; mt++) {
#pragma unroll
        for (int nt = 0; nt < 8; nt++) {
            int row = wm * 32 + mt * 16 + (lane >> 2);
            int col = wn * 64 + nt * 8 + (lane & 3) * 2;
            float* p0 = &eb[row * 132 + col];
            p0[0] = acc[mt][nt][0]; p0[1] = acc[mt][nt][1];
            float* p1 = &eb[(row + 8) * 132 + col];
            p1[0] = acc[mt][nt][2]; p1[1] = acc[mt][nt][3];
        }
    }
    __syncthreads();

    int cp2 = (t & 63) * 2;
    float b0 = bias[n0 + cp2], b1 = bias[n0 + cp2 + 1];
#pragma unroll 4
    for (int i = 0; i < 32; i++) {
        int row = (t >> 6) + i * 4;
        float2 v = *(float2*)&eb[row * 132 + cp2];
        float x0 = v.x + b0, x1 = v.y + b1;
        size_t oidx = (size_t)(m0 + row) * N + n0 + cp2;
        if (EPI == 0) {
            x0 = 0.5f * x0 * (1.0f + erff(x0 * 0.70710678118654752f));
            x1 = 0.5f * x1 * (1.0f + erff(x1 * 0.70710678118654752f));
            __half h0, l0, h1, l1;
            h_split(x0, h0, l0);
            h_split(x1, h1, l1);
            __half2 hp, lp;
            hp.x = h0; hp.y = h1; lp.x = l0; lp.y = l1;
            *(__half2*)&g_hh[oidx] = hp;
            *(__half2*)&g_hl[oidx] = lp;
        } else {
            float2 rr = *(const float2*)&g_mho[oidx];
            *(float2*)&outf[oidx] = make_float2(x0 + rr.x, x1 + rr.y);
        }
    }
}

// ---------------- launch ---------------------------------------------------
extern "C" void kernel_launch(void* const* d_in, const int* in_sizes, int n_in,
                              void* d_out, int out_size) {
    const float* frame = (const float*)d_in[0];
    const float* W_q   = (const float*)d_in[1];
    const float* W_k   = (const float*)d_in[2];
    const float* W_v   = (const float*)d_in[3];
    const float* W_o   = (const float*)d_in[4];
    const float* fc1_w = (const float*)d_in[5];
    const float* fc1_b = (const float*)d_in[6];
    const float* fc2_w = (const float*)d_in[7];
    const float* fc2_b = (const float*)d_in[8];
    float* out = (float*)d_out;

    cudaFuncSetAttribute(gemm_hmma<DM, 0>,
                         cudaFuncAttributeMaxDynamicSharedMemorySize, SMEM_B);
    cudaFuncSetAttribute(gemm_hmma<DFF, 1>,
                         cudaFuncAttributeMaxDynamicSharedMemorySize, SMEM_B);
    cudaFuncSetAttribute(attn_tc,
                         cudaFuncAttributeMaxDynamicSharedMemorySize, ATT_SMEM);

    pack_weights<<<96, 256>>>(W_q, W_k, W_v, W_o);
    conv_weights<<<(DFF * DM + 255) / 256, 256>>>(fc1_w, fc2_w);
    qkv_kernel<<<S_LEN / 128, 256>>>(frame);
    attn_tc<<<S_LEN / 64, 128, ATT_SMEM>>>();
    mho_kernel<<<S_LEN / 8, 256>>>();

    gemm_hmma<DM, 0><<<dim3(DFF / 128, S_LEN / 128), 256, SMEM_B>>>(fc1_b, nullptr);
    gemm_hmma<DFF, 1><<<dim3(DM / 128, S_LEN / 128), 256, SMEM_B>>>(fc2_b, out);
}

// round 5
// speedup vs baseline: 2.4339x; 1.0354x over previous
#include <cuda_runtime.h>
#include <cuda_fp16.h>
#include <math.h>
#include <stdint.h>

#define S_LEN 8192
#define DM    512
#define DK    16
#define DFF   2048

// ---------------- scratch (static device globals) -------------------------
__device__ __align__(256) float g_Wqkv[DM * 48];
__device__ __align__(256) float g_Woeff[DK * DM];
__device__ __align__(256) float g_head[S_LEN * DK];
__device__ __align__(256) float g_mho[S_LEN * DM];    // fp32 (residual)
__device__ __align__(256) __half g_mhoh[S_LEN * DM];  // mho hi (fp16)
__device__ __align__(256) __half g_mhol[S_LEN * DM];  // mho lo
__device__ __align__(256) __half g_hh[S_LEN * DFF];   // gelu(h) hi
__device__ __align__(256) __half g_hl[S_LEN * DFF];   // gelu(h) lo
__device__ __align__(256) __half g_w1h[DFF * DM];
__device__ __align__(256) __half g_w1l[DFF * DM];
__device__ __align__(256) __half g_w2h[DM * DFF];
__device__ __align__(256) __half g_w2l[DM * DFF];
// attention fp16 operands
__device__ __align__(256) __half g_Qh[S_LEN * DK];    // scaled by 0.25*log2e
__device__ __align__(256) __half g_Ql[S_LEN * DK];
__device__ __align__(256) __half g_Kh[S_LEN * DK];
__device__ __align__(256) __half g_Kl[S_LEN * DK];
__device__ __align__(256) __half g_Vph[S_LEN * 24];   // V padded: col16=1, 17-23=0
__device__ __align__(256) __half g_Vpl[S_LEN * 24];
// split-KV partials
__device__ __align__(256) float g_po[2][S_LEN][16];   // unnormalized O
__device__ __align__(256) float g_pml[2][S_LEN][2];   // {m (log2), l}

#define QSCALE 0.36067376022224085f   // 0.25 * log2(e)

// ---------------- helpers ---------------------------------------------------
__device__ __forceinline__ uint32_t smem_u32(const void* p) {
    uint32_t a;
    asm("{ .reg .u64 t; cvta.to.shared.u64 t, %1; cvt.u32.u64 %0, t; }" : "=r"(a) : "l"(p));
    return a;
}
__device__ __forceinline__ void cp16(uint32_t dst, const void* src) {
    asm volatile("cp.async.cg.shared.global [%0], [%1], 16;" :: "r"(dst), "l"(src) : "memory");
}
__device__ __forceinline__ void cp_commit() {
    asm volatile("cp.async.commit_group;" ::: "memory");
}
template <int P>
__device__ __forceinline__ void cp_wait() {
    asm volatile("cp.async.wait_group %0;" :: "n"(P) : "memory");
}
__device__ __forceinline__ void ldsm4(uint32_t addr, uint32_t& r0, uint32_t& r1,
                                      uint32_t& r2, uint32_t& r3) {
    asm volatile("ldmatrix.sync.aligned.m8n8.x4.shared.b16 {%0,%1,%2,%3}, [%4];"
                 : "=r"(r0), "=r"(r1), "=r"(r2), "=r"(r3) : "r"(addr));
}
__device__ __forceinline__ void ldsm4t(uint32_t addr, uint32_t& r0, uint32_t& r1,
                                       uint32_t& r2, uint32_t& r3) {
    asm volatile("ldmatrix.sync.aligned.m8n8.x4.trans.shared.b16 {%0,%1,%2,%3}, [%4];"
                 : "=r"(r0), "=r"(r1), "=r"(r2), "=r"(r3) : "r"(addr));
}
__device__ __forceinline__ void ldsm2t(uint32_t addr, uint32_t& r0, uint32_t& r1) {
    asm volatile("ldmatrix.sync.aligned.m8n8.x2.trans.shared.b16 {%0,%1}, [%2];"
                 : "=r"(r0), "=r"(r1) : "r"(addr));
}
__device__ __forceinline__ void mma16816(float* c, const uint32_t* a,
                                         uint32_t b0, uint32_t b1) {
    asm volatile(
        "mma.sync.aligned.m16n8k16.row.col.f32.f16.f16.f32 "
        "{%0,%1,%2,%3}, {%4,%5,%6,%7}, {%8,%9}, {%0,%1,%2,%3};"
        : "+f"(c[0]), "+f"(c[1]), "+f"(c[2]), "+f"(c[3])
        : "r"(a[0]), "r"(a[1]), "r"(a[2]), "r"(a[3]), "r"(b0), "r"(b1));
}
__device__ __forceinline__ void mma16816_z(float* c, const uint32_t* a,
                                           uint32_t b0, uint32_t b1) {
    float z = 0.f;
    asm volatile(
        "mma.sync.aligned.m16n8k16.row.col.f32.f16.f16.f32 "
        "{%0,%1,%2,%3}, {%4,%5,%6,%7}, {%8,%9}, {%10,%10,%10,%10};"
        : "=f"(c[0]), "=f"(c[1]), "=f"(c[2]), "=f"(c[3])
        : "r"(a[0]), "r"(a[1]), "r"(a[2]), "r"(a[3]), "r"(b0), "r"(b1), "f"(z));
}
__device__ __forceinline__ float ex2f(float x) {
    float y;
    asm("ex2.approx.ftz.f32 %0, %1;" : "=f"(y) : "f"(x));
    return y;
}
__device__ __forceinline__ uint32_t f16x2_pack(float hi, float lo) {
    uint32_t d;
    asm("cvt.rn.f16x2.f32 %0, %1, %2;" : "=r"(d) : "f"(hi), "f"(lo));
    return d;
}
__device__ __forceinline__ void h_split(float x, __half& hi, __half& lo) {
    hi = __float2half_rn(x);
    lo = __float2half_rn(x - __half2float(hi));
}

// ---------------- weight packing ------------------------------------------
__global__ void pack_weights(const float* __restrict__ Wq,
                             const float* __restrict__ Wk,
                             const float* __restrict__ Wv,
                             const float* __restrict__ Wo) {
    int idx = blockIdx.x * blockDim.x + threadIdx.x;
    if (idx < DM * 48) {
        int d = idx / 48, c = idx % 48;
        float v;
        if (c < 16)      v = Wq[d * 16 + c];
        else if (c < 32) v = Wk[d * 16 + c - 16];
        else             v = Wv[d * 16 + c - 32];
        g_Wqkv[idx] = v;
    }
    if (idx < DK * DM) {
        int i = idx / DM, c = idx % DM;
        float s = 0.f;
#pragma unroll
        for (int h = 0; h < 8; h++) s += Wo[(h * 16 + i) * DM + c];
        g_Woeff[idx] = s;
    }
}

__global__ void conv_weights(const float* __restrict__ w1, const float* __restrict__ w2) {
    int i = blockIdx.x * blockDim.x + threadIdx.x;
    if (i < DFF * DM) {
        __half h, l;
        h_split(w1[i], h, l);
        g_w1h[i] = h; g_w1l[i] = l;
        h_split(w2[i], h, l);
        g_w2h[i] = h; g_w2l[i] = l;
    }
}

// ---------------- fused QKV projection (emits fp16 hi/lo) ------------------
__global__ void __launch_bounds__(256) qkv_kernel(const float* __restrict__ frame) {
    __shared__ float Fs[128][33];
    __shared__ float Ws[32][48];
    int t = threadIdx.x;
    int m0 = blockIdx.x * 128;
    int r = t & 127;
    int hv = t >> 7;
    float acc[24];
#pragma unroll
    for (int c = 0; c < 24; c++) acc[c] = 0.f;

    int lrow = t >> 3;
    int lds  = (t & 7) * 4;

    for (int d0 = 0; d0 < DM; d0 += 32) {
#pragma unroll
        for (int rr = 0; rr < 128; rr += 32) {
            float4 v = *(const float4*)&frame[(size_t)(m0 + lrow + rr) * DM + d0 + lds];
            Fs[lrow + rr][lds + 0] = v.x;
            Fs[lrow + rr][lds + 1] = v.y;
            Fs[lrow + rr][lds + 2] = v.z;
            Fs[lrow + rr][lds + 3] = v.w;
        }
        for (int q = t; q < 32 * 48; q += 256)
            Ws[q / 48][q % 48] = g_Wqkv[(d0 + q / 48) * 48 + (q % 48)];
        __syncthreads();
#pragma unroll
        for (int d = 0; d < 32; d++) {
            float f = Fs[r][d];
#pragma unroll
            for (int c = 0; c < 24; c++)
                acc[c] = fmaf(f, Ws[d][hv * 24 + c], acc[c]);
        }
        __syncthreads();
    }
    int row = m0 + r;
#pragma unroll
    for (int c = 0; c < 24; c++) {
        int cg = hv * 24 + c;
        __half h, l;
        if (cg < 16) {
            h_split(acc[c] * QSCALE, h, l);
            g_Qh[row * 16 + cg] = h;
            g_Ql[row * 16 + cg] = l;
        } else if (cg < 32) {
            h_split(acc[c], h, l);
            g_Kh[row * 16 + cg - 16] = h;
            g_Kl[row * 16 + cg - 16] = l;
        } else {
            h_split(acc[c], h, l);
            g_Vph[row * 24 + cg - 32] = h;
            g_Vpl[row * 24 + cg - 32] = l;
        }
    }
    if (hv == 1) {
#pragma unroll
        for (int c2 = 16; c2 < 24; c2++) {
            g_Vph[row * 24 + c2] = (c2 == 16) ? __float2half_rn(1.0f) : __float2half_rn(0.0f);
            g_Vpl[row * 24 + c2] = __float2half_rn(0.0f);
        }
    }
}

// ---------------- tensor-core flash attention (split-KV x2) -----------------
static constexpr uint32_t ATT_STG  = 24576;
static constexpr uint32_t ATT_QH   = 49152;
static constexpr uint32_t ATT_QL   = 52224;
static constexpr uint32_t ATT_SMEM = 55296;

__device__ __forceinline__ void attn_load(uint32_t stg, int k0, int t) {
#pragma unroll
    for (int i = 0; i < 2; i++) {
        int q = t + i * 128;
        int row = q >> 1, g = q & 1;
        cp16(stg + (uint32_t)row * 48 + g * 16, g_Kh + (size_t)(k0 + row) * 16 + g * 8);
        cp16(stg + 6144 + (uint32_t)row * 48 + g * 16, g_Kl + (size_t)(k0 + row) * 16 + g * 8);
    }
#pragma unroll
    for (int i = 0; i < 3; i++) {
        int q = t + i * 128;
        int row = q / 3, g = q % 3;
        cp16(stg + 12288 + (uint32_t)row * 48 + g * 16, g_Vph + (size_t)(k0 + row) * 24 + g * 8);
        cp16(stg + 18432 + (uint32_t)row * 48 + g * 16, g_Vpl + (size_t)(k0 + row) * 24 + g * 8);
    }
}

__global__ void __launch_bounds__(128, 2) attn_tc() {
    extern __shared__ __align__(128) char sm[];
    uint32_t sb = smem_u32(sm);
    int t = threadIdx.x, lane = t & 31, w = t >> 5;
    int q0 = (blockIdx.x >> 1) * 64;
    int ks = blockIdx.x & 1;
    int kbase = ks * 4096;

    {
        int row = t >> 1, g = t & 1;
        cp16(sb + ATT_QH + (uint32_t)row * 48 + g * 16, g_Qh + (size_t)(q0 + row) * 16 + g * 8);
        cp16(sb + ATT_QL + (uint32_t)row * 48 + g * 16, g_Ql + (size_t)(q0 + row) * 16 + g * 8);
    }
    attn_load(sb, kbase, t);
    cp_commit();
    attn_load(sb + ATT_STG, kbase + 128, t);
    cp_commit();

    uint32_t aQ  = sb + ATT_QH + (uint32_t)(w * 16 + (lane & 15)) * 48 + (uint32_t)(lane >> 4) * 16;
    uint32_t aK  = (uint32_t)((lane & 7) + ((lane >> 4) & 1) * 8) * 48 + (uint32_t)((lane >> 3) & 1) * 16;
    uint32_t aV4 = (uint32_t)((lane & 7) + ((lane >> 3) & 1) * 8) * 48 + (uint32_t)(lane >> 4) * 16;
    uint32_t aV2 = (uint32_t)((lane & 7) + ((lane >> 3) & 1) * 8) * 48 + 32;

    uint32_t QH[4], QL[4];
    float o[3][4];
#pragma unroll
    for (int i = 0; i < 3; i++)
#pragma unroll
        for (int j = 0; j < 4; j++) o[i][j] = 0.f;
    float m0 = -INFINITY, m8 = -INFINITY;

    for (int c = 0; c < 32; c++) {
        if (c == 31) cp_wait<0>(); else cp_wait<1>();
        __syncthreads();
        if (c == 0) {
            ldsm4(aQ, QH[0], QH[1], QH[2], QH[3]);
            ldsm4(aQ + (ATT_QL - ATT_QH), QL[0], QL[1], QL[2], QL[3]);
        }
        uint32_t stg = sb + (uint32_t)(c & 1) * ATT_STG;

        float s[16][4];
#pragma unroll
        for (int u = 0; u < 8; u++) {
            uint32_t bh0, bh1, bh2, bh3, bl0, bl1, bl2, bl3;
            ldsm4(stg + u * 768 + aK, bh0, bh1, bh2, bh3);
            ldsm4(stg + 6144 + u * 768 + aK, bl0, bl1, bl2, bl3);
            mma16816_z(s[2 * u], QH, bh0, bh1);
            mma16816(s[2 * u], QH, bl0, bl1);
            mma16816(s[2 * u], QL, bh0, bh1);
            mma16816_z(s[2 * u + 1], QH, bh2, bh3);
            mma16816(s[2 * u + 1], QH, bl2, bl3);
            mma16816(s[2 * u + 1], QL, bh2, bh3);
        }

        float mx0 = s[0][0], mx8 = s[0][2];
#pragma unroll
        for (int nt = 0; nt < 16; nt++) {
            mx0 = fmaxf(mx0, fmaxf(s[nt][0], s[nt][1]));
            mx8 = fmaxf(mx8, fmaxf(s[nt][2], s[nt][3]));
        }
        mx0 = fmaxf(mx0, __shfl_xor_sync(0xffffffffu, mx0, 1));
        mx0 = fmaxf(mx0, __shfl_xor_sync(0xffffffffu, mx0, 2));
        mx8 = fmaxf(mx8, __shfl_xor_sync(0xffffffffu, mx8, 1));
        mx8 = fmaxf(mx8, __shfl_xor_sync(0xffffffffu, mx8, 2));
        float mn0 = fmaxf(m0, mx0), mn8 = fmaxf(m8, mx8);
        float c0 = ex2f(m0 - mn0), c8 = ex2f(m8 - mn8);
        m0 = mn0; m8 = mn8;
#pragma unroll
        for (int i = 0; i < 3; i++) {
            o[i][0] *= c0; o[i][1] *= c0; o[i][2] *= c8; o[i][3] *= c8;
        }
#pragma unroll
        for (int nt = 0; nt < 16; nt++) {
            s[nt][0] = ex2f(s[nt][0] - m0);
            s[nt][1] = ex2f(s[nt][1] - m0);
            s[nt][2] = ex2f(s[nt][2] - m8);
            s[nt][3] = ex2f(s[nt][3] - m8);
        }

#pragma unroll
        for (int j = 0; j < 8; j++) {
            uint32_t a[4];
            a[0] = f16x2_pack(s[2 * j][1],     s[2 * j][0]);
            a[1] = f16x2_pack(s[2 * j][3],     s[2 * j][2]);
            a[2] = f16x2_pack(s[2 * j + 1][1], s[2 * j + 1][0]);
            a[3] = f16x2_pack(s[2 * j + 1][3], s[2 * j + 1][2]);
            uint32_t v0, v1, v2, v3, v4, v5;
            ldsm4t(stg + 12288 + j * 768 + aV4, v0, v1, v2, v3);
            ldsm2t(stg + 12288 + j * 768 + aV2, v4, v5);
            mma16816(o[0], a, v0, v1);
            mma16816(o[1], a, v2, v3);
            mma16816(o[2], a, v4, v5);
            ldsm4t(stg + 18432 + j * 768 + aV4, v0, v1, v2, v3);
            ldsm2t(stg + 18432 + j * 768 + aV2, v4, v5);
            mma16816(o[0], a, v0, v1);
            mma16816(o[1], a, v2, v3);
            mma16816(o[2], a, v4, v5);
        }
        __syncthreads();
        if (c + 2 < 32) {
            attn_load(stg, kbase + (c + 2) * 128, t);
            cp_commit();
        }
    }

    // store partial state (unnormalized)
    float l0 = __shfl_sync(0xffffffffu, o[2][0], lane & 28);
    float l8 = __shfl_sync(0xffffffffu, o[2][2], lane & 28);
    int row0 = q0 + w * 16 + (lane >> 2);
    int c4 = (lane & 3) * 2;
    *(float2*)&g_po[ks][row0][c4]         = make_float2(o[0][0], o[0][1]);
    *(float2*)&g_po[ks][row0][8 + c4]     = make_float2(o[1][0], o[1][1]);
    *(float2*)&g_po[ks][row0 + 8][c4]     = make_float2(o[0][2], o[0][3]);
    *(float2*)&g_po[ks][row0 + 8][8 + c4] = make_float2(o[1][2], o[1][3]);
    if ((lane & 3) == 0) {
        *(float2*)&g_pml[ks][row0][0]     = make_float2(m0, l0);
        *(float2*)&g_pml[ks][row0 + 8][0] = make_float2(m8, l8);
    }
}

__global__ void __launch_bounds__(256) attn_merge() {
    int row = blockIdx.x * 256 + threadIdx.x;
    float2 s0 = *(const float2*)&g_pml[0][row][0];
    float2 s1 = *(const float2*)&g_pml[1][row][0];
    float mm = fmaxf(s0.x, s1.x);
    float a0 = ex2f(s0.x - mm), a1 = ex2f(s1.x - mm);
    float inv = __fdividef(1.f, s0.y * a0 + s1.y * a1);
#pragma unroll
    for (int c = 0; c < 16; c += 4) {
        float4 v0 = *(const float4*)&g_po[0][row][c];
        float4 v1 = *(const float4*)&g_po[1][row][c];
        float4 r;
        r.x = (v0.x * a0 + v1.x * a1) * inv;
        r.y = (v0.y * a0 + v1.y * a1) * inv;
        r.z = (v0.z * a0 + v1.z * a1) * inv;
        r.w = (v0.w * a0 + v1.w * a1) * inv;
        *(float4*)&g_head[(size_t)row * 16 + c] = r;
    }
}

// ---------------- mho = head @ Woeff (fp32 + fp16 hi/lo) -------------------
__global__ void __launch_bounds__(256) mho_kernel() {
    __shared__ float hrow[8][16];
    int t = threadIdx.x;
    int r0 = blockIdx.x * 8;
    if (t < 128) hrow[t >> 4][t & 15] = g_head[r0 * 16 + t];
    __syncthreads();

    int cg = (t & 127) * 4;
    int rb = (t >> 7) * 4;
    float4 a[4];
#pragma unroll
    for (int r = 0; r < 4; r++) a[r] = make_float4(0.f, 0.f, 0.f, 0.f);
#pragma unroll
    for (int i = 0; i < 16; i++) {
        float4 w = *(const float4*)&g_Woeff[i * 512 + cg];
#pragma unroll
        for (int r = 0; r < 4; r++) {
            float h = hrow[rb + r][i];
            a[r].x = fmaf(h, w.x, a[r].x); a[r].y = fmaf(h, w.y, a[r].y);
            a[r].z = fmaf(h, w.z, a[r].z); a[r].w = fmaf(h, w.w, a[r].w);
        }
    }
#pragma unroll
    for (int r = 0; r < 4; r++) {
        size_t base = (size_t)(r0 + rb + r) * 512 + cg;
        *(float4*)&g_mho[base] = a[r];
        float v[4] = {a[r].x, a[r].y, a[r].z, a[r].w};
        __half hi[4], lo[4];
#pragma unroll
        for (int k = 0; k < 4; k++) h_split(v[k], hi[k], lo[k]);
        __half2 h01, h23, l01, l23;
        h01.x = hi[0]; h01.y = hi[1]; h23.x = hi[2]; h23.y = hi[3];
        l01.x = lo[0]; l01.y = lo[1]; l23.x = lo[2]; l23.y = lo[3];
        *(__half2*)&g_mhoh[base + 0] = h01;
        *(__half2*)&g_mhoh[base + 2] = h23;
        *(__half2*)&g_mhol[base + 0] = l01;
        *(__half2*)&g_mhol[base + 2] = l23;
    }
}

// ---------------- HMMA split-fp16 GEMM, high-occupancy --------------------
// 128 threads/CTA, tile TM x 64, KC=32, 2-stage cp.async.
// EPI 0: gelu(x+bias) -> fp16 hi/lo ; EPI 1: x+bias+res -> fp32
template <int TM, int KTOT>
__device__ __forceinline__ void g2_load(uint32_t stg, int m0, int n0, int k0, int t,
                                        const __half* __restrict__ Ah,
                                        const __half* __restrict__ Al,
                                        const __half* __restrict__ Bh,
                                        const __half* __restrict__ Bl) {
    const uint32_t AB = TM * 80;
#pragma unroll
    for (int i = 0; i < TM / 32; i++) {
        int q = t + i * 128;
        int r = q >> 2, gr = q & 3;
        cp16(stg + (uint32_t)r * 80 + gr * 16, Ah + (size_t)(m0 + r) * KTOT + k0 + gr * 8);
        cp16(stg + AB + (uint32_t)r * 80 + gr * 16, Al + (size_t)(m0 + r) * KTOT + k0 + gr * 8);
    }
#pragma unroll
    for (int i = 0; i < 2; i++) {
        int q = t + i * 128;
        int r = q >> 2, gr = q & 3;
        cp16(stg + 2 * AB + (uint32_t)r * 80 + gr * 16, Bh + (size_t)(n0 + r) * KTOT + k0 + gr * 8);
        cp16(stg + 2 * AB + 5120 + (uint32_t)r * 80 + gr * 16, Bl + (size_t)(n0 + r) * KTOT + k0 + gr * 8);
    }
}

template <int TM, int KTOT, int EPI, int MAXB>
__global__ void __launch_bounds__(128, MAXB) gemm_hmma2(
    const float* __restrict__ bias, float* __restrict__ outf)
{
    extern __shared__ __align__(128) char sm[];
    uint32_t sbase = smem_u32(sm);
    const uint32_t STAGE = (2 * TM + 128) * 80;
    const uint32_t AB = TM * 80;
    const int MT = TM / 64;             // 16-row mtiles per warp
    const int RW = TM / 4;              // rows per warp

    const __half* Ahp = (EPI == 0) ? g_mhoh : g_hh;
    const __half* Alp = (EPI == 0) ? g_mhol : g_hl;
    const __half* Bhp = (EPI == 0) ? g_w1h  : g_w2h;
    const __half* Blp = (EPI == 0) ? g_w1l  : g_w2l;
    const int N = (EPI == 0) ? DFF : DM;

    int t = threadIdx.x;
    int wm = t >> 5, lane = t & 31;
    int m0 = blockIdx.y * TM;
    int n0 = blockIdx.x * 64;
    const int NC = KTOT / 32;

    int a_row = lane & 15;
    int a_kg  = lane >> 4;
    int b_row = ((lane >> 4) << 3) + (lane & 7);
    int b_kg  = (lane >> 3) & 1;

    float acc[MT][8][4];
#pragma unroll
    for (int i = 0; i < MT; i++)
#pragma unroll
        for (int j = 0; j < 8; j++)
#pragma unroll
            for (int k = 0; k < 4; k++) acc[i][j][k] = 0.f;

    g2_load<TM, KTOT>(sbase, m0, n0, 0, t, Ahp, Alp, Bhp, Blp);
    cp_commit();
    g2_load<TM, KTOT>(sbase + STAGE, m0, n0, 32, t, Ahp, Alp, Bhp, Blp);
    cp_commit();

    for (int c = 0; c < NC; c++) {
        if (c == NC - 1) cp_wait<0>(); else cp_wait<1>();
        __syncthreads();
        uint32_t stg = sbase + (uint32_t)(c & 1) * STAGE;
        uint32_t sAh = stg, sAl = stg + AB, sBh = stg + 2 * AB, sBl = stg + 2 * AB + 5120;

#pragma unroll
        for (int ks = 0; ks < 2; ks++) {
            uint32_t ah[MT][4], al[MT][4];
#pragma unroll
            for (int mt = 0; mt < MT; mt++) {
                uint32_t off = (uint32_t)(wm * RW + mt * 16 + a_row) * 80
                             + (uint32_t)(ks * 32 + a_kg * 16);
                ldsm4(sAh + off, ah[mt][0], ah[mt][1], ah[mt][2], ah[mt][3]);
                ldsm4(sAl + off, al[mt][0], al[mt][1], al[mt][2], al[mt][3]);
            }
#pragma unroll
            for (int np = 0; np < 4; np++) {
                uint32_t boff = (uint32_t)(np * 16 + b_row) * 80
                              + (uint32_t)(ks * 32 + b_kg * 16);
                uint32_t bh0, bh1, bh2, bh3, bl0, bl1, bl2, bl3;
                ldsm4(sBh + boff, bh0, bh1, bh2, bh3);
                ldsm4(sBl + boff, bl0, bl1, bl2, bl3);
#pragma unroll
                for (int mt = 0; mt < MT; mt++) {
                    float* c0 = acc[mt][np * 2 + 0];
                    float* c1 = acc[mt][np * 2 + 1];
                    mma16816(c0, ah[mt], bh0, bh1);
                    mma16816(c0, ah[mt], bl0, bl1);
                    mma16816(c0, al[mt], bh0, bh1);
                    mma16816(c1, ah[mt], bh2, bh3);
                    mma16816(c1, ah[mt], bl2, bl3);
                    mma16816(c1, al[mt], bh2, bh3);
                }
            }
        }
        __syncthreads();
        if (c + 2 < NC) {
            g2_load<TM, KTOT>(stg, m0, n0, (c + 2) * 32, t, Ahp, Alp, Bhp, Blp);
            cp_commit();
        }
    }

    // epilogue: stage to smem, coalesced out
    float* eb = (float*)sm;                 // TM x 68 fp32
#pragma unroll
    for (int mt = 0; mt < MT; mt++) {
#pragma unroll
        for (int nt = 0; nt < 8; nt++) {
            int row = wm * RW + mt * 16 + (lane >> 2);
            int col = nt * 8 + (lane & 3) * 2;
            float* p0 = &eb[row * 68 + col];
            p0[0] = acc[mt][nt][0]; p0[1] = acc[mt][nt][1];
            float* p1 = &eb[(row + 8) * 68 + col];
            p1[0] = acc[mt][nt][2]; p1[1] = acc[mt][nt][3];
        }
    }
    __syncthreads();

    int cp2 = (lane) * 2;                   // 0..62
    float b0 = bias[n0 + cp2], b1 = bias[n0 + cp2 + 1];
#pragma unroll 4
    for (int i = 0; i < TM / 4; i++) {
        int row = (t >> 5) + i * 4;
        float2 v = *(float2*)&eb[row * 68 + cp2];
        float x0 = v.x + b0, x1 = v.y + b1;
        size_t oidx = (size_t)(m0 + row) * N + n0 + cp2;
        if (EPI == 0) {
            x0 = 0.5f * x0 * (1.0f + erff(x0 * 0.70710678118654752f));
            x1 = 0.5f * x1 * (1.0f + erff(x1 * 0.70710678118654752f));
            __half h0, l0, h1, l1;
            h_split(x0, h0, l0);
            h_split(x1, h1, l1);
            __half2 hp, lp;
            hp.x = h0; hp.y = h1; lp.x = l0; lp.y = l1;
            *(__half2*)&g_hh[oidx] = hp;
            *(__half2*)&g_hl[oidx] = lp;
        } else {
            float2 rr = *(const float2*)&g_mho[oidx];
            *(float2*)&outf[oidx] = make_float2(x0 + rr.x, x1 + rr.y);
        }
    }
}

// ---------------- launch ---------------------------------------------------
extern "C" void kernel_launch(void* const* d_in, const int* in_sizes, int n_in,
                              void* d_out, int out_size) {
    const float* frame = (const float*)d_in[0];
    const float* W_q   = (const float*)d_in[1];
    const float* W_k   = (const float*)d_in[2];
    const float* W_v   = (const float*)d_in[3];
    const float* W_o   = (const float*)d_in[4];
    const float* fc1_w = (const float*)d_in[5];
    const float* fc1_b = (const float*)d_in[6];
    const float* fc2_w = (const float*)d_in[7];
    const float* fc2_b = (const float*)d_in[8];
    float* out = (float*)d_out;

    // gemm1: 128x64 tiles; stage=(2*128+128)*80=30720, 2 stages=61440; epi=128*68*4=34816
    const int SM1 = 61440;
    // gemm2: 64x64 tiles; stage=(2*64+128)*80=20480, 2 stages=40960; epi=64*68*4=17408
    const int SM2 = 40960;
    cudaFuncSetAttribute(gemm_hmma2<128, DM, 0, 3>,
                         cudaFuncAttributeMaxDynamicSharedMemorySize, SM1);
    cudaFuncSetAttribute(gemm_hmma2<64, DFF, 1, 4>,
                         cudaFuncAttributeMaxDynamicSharedMemorySize, SM2);
    cudaFuncSetAttribute(attn_tc,
                         cudaFuncAttributeMaxDynamicSharedMemorySize, ATT_SMEM);

    pack_weights<<<96, 256>>>(W_q, W_k, W_v, W_o);
    conv_weights<<<(DFF * DM + 255) / 256, 256>>>(fc1_w, fc2_w);
    qkv_kernel<<<S_LEN / 128, 256>>>(frame);
    attn_tc<<<(S_LEN / 64) * 2, 128, ATT_SMEM>>>();
    attn_merge<<<S_LEN / 256, 256>>>();
    mho_kernel<<<S_LEN / 8, 256>>>();

    gemm_hmma2<128, DM, 0, 3><<<dim3(DFF / 64, S_LEN / 128), 128, SM1>>>(fc1_b, nullptr);
    gemm_hmma2<64, DFF, 1, 4><<<dim3(DM / 64, S_LEN / 64), 128, SM2>>>(fc2_b, out);
}

// round 6
// speedup vs baseline: 3.1963x; 1.3132x over previous
#include <cuda_runtime.h>
#include <cuda_fp16.h>
#include <math.h>
#include <stdint.h>

#define S_LEN 8192
#define DM    512
#define DK    16
#define DFF   2048

// ---------------- scratch (static device globals) -------------------------
__device__ __align__(256) float g_Wqkv[DM * 48];
__device__ __align__(256) float g_Woeff[DK * DM];
__device__ __align__(256) float g_head[S_LEN * DK];
__device__ __align__(256) float g_mho[S_LEN * DM];    // fp32 (residual)
__device__ __align__(256) __half g_mhoh[S_LEN * DM];  // mho hi (fp16)
__device__ __align__(256) __half g_hh[S_LEN * DFF];   // gelu(h) hi
__device__ __align__(256) __half g_w1h[DFF * DM];
__device__ __align__(256) __half g_w1l[DFF * DM];
__device__ __align__(256) __half g_w2h[DM * DFF];
__device__ __align__(256) __half g_w2l[DM * DFF];
// attention fp16 operands
__device__ __align__(256) __half g_Qh[S_LEN * DK];    // scaled by 0.25*log2e
__device__ __align__(256) __half g_Ql[S_LEN * DK];
__device__ __align__(256) __half g_Kh[S_LEN * DK];
__device__ __align__(256) __half g_Vph[S_LEN * 24];   // V padded: col16=1, 17-23=0
__device__ __align__(256) __half g_Vpl[S_LEN * 24];
// split-KV partials
__device__ __align__(256) float g_po[2][S_LEN][16];   // unnormalized O
__device__ __align__(256) float g_pml[2][S_LEN][2];   // {m (log2), l}

#define QSCALE 0.36067376022224085f   // 0.25 * log2(e)

// ---------------- helpers ---------------------------------------------------
__device__ __forceinline__ uint32_t smem_u32(const void* p) {
    uint32_t a;
    asm("{ .reg .u64 t; cvta.to.shared.u64 t, %1; cvt.u32.u64 %0, t; }" : "=r"(a) : "l"(p));
    return a;
}
__device__ __forceinline__ void cp16(uint32_t dst, const void* src) {
    asm volatile("cp.async.cg.shared.global [%0], [%1], 16;" :: "r"(dst), "l"(src) : "memory");
}
__device__ __forceinline__ void cp_commit() {
    asm volatile("cp.async.commit_group;" ::: "memory");
}
template <int P>
__device__ __forceinline__ void cp_wait() {
    asm volatile("cp.async.wait_group %0;" :: "n"(P) : "memory");
}
__device__ __forceinline__ void ldsm4(uint32_t addr, uint32_t& r0, uint32_t& r1,
                                      uint32_t& r2, uint32_t& r3) {
    asm volatile("ldmatrix.sync.aligned.m8n8.x4.shared.b16 {%0,%1,%2,%3}, [%4];"
                 : "=r"(r0), "=r"(r1), "=r"(r2), "=r"(r3) : "r"(addr));
}
__device__ __forceinline__ void ldsm4t(uint32_t addr, uint32_t& r0, uint32_t& r1,
                                       uint32_t& r2, uint32_t& r3) {
    asm volatile("ldmatrix.sync.aligned.m8n8.x4.trans.shared.b16 {%0,%1,%2,%3}, [%4];"
                 : "=r"(r0), "=r"(r1), "=r"(r2), "=r"(r3) : "r"(addr));
}
__device__ __forceinline__ void ldsm2t(uint32_t addr, uint32_t& r0, uint32_t& r1) {
    asm volatile("ldmatrix.sync.aligned.m8n8.x2.trans.shared.b16 {%0,%1}, [%2];"
                 : "=r"(r0), "=r"(r1) : "r"(addr));
}
__device__ __forceinline__ void mma16816(float* c, const uint32_t* a,
                                         uint32_t b0, uint32_t b1) {
    asm volatile(
        "mma.sync.aligned.m16n8k16.row.col.f32.f16.f16.f32 "
        "{%0,%1,%2,%3}, {%4,%5,%6,%7}, {%8,%9}, {%0,%1,%2,%3};"
        : "+f"(c[0]), "+f"(c[1]), "+f"(c[2]), "+f"(c[3])
        : "r"(a[0]), "r"(a[1]), "r"(a[2]), "r"(a[3]), "r"(b0), "r"(b1));
}
__device__ __forceinline__ void mma16816_z(float* c, const uint32_t* a,
                                           uint32_t b0, uint32_t b1) {
    float z = 0.f;
    asm volatile(
        "mma.sync.aligned.m16n8k16.row.col.f32.f16.f16.f32 "
        "{%0,%1,%2,%3}, {%4,%5,%6,%7}, {%8,%9}, {%10,%10,%10,%10};"
        : "=f"(c[0]), "=f"(c[1]), "=f"(c[2]), "=f"(c[3])
        : "r"(a[0]), "r"(a[1]), "r"(a[2]), "r"(a[3]), "r"(b0), "r"(b1), "f"(z));
}
__device__ __forceinline__ float ex2f(float x) {
    float y;
    asm("ex2.approx.ftz.f32 %0, %1;" : "=f"(y) : "f"(x));
    return y;
}
__device__ __forceinline__ uint32_t f16x2_pack(float hi, float lo) {
    uint32_t d;
    asm("cvt.rn.f16x2.f32 %0, %1, %2;" : "=r"(d) : "f"(hi), "f"(lo));
    return d;
}
__device__ __forceinline__ void h_split(float x, __half& hi, __half& lo) {
    hi = __float2half_rn(x);
    lo = __float2half_rn(x - __half2float(hi));
}

// ---------------- weight packing ------------------------------------------
__global__ void pack_weights(const float* __restrict__ Wq,
                             const float* __restrict__ Wk,
                             const float* __restrict__ Wv,
                             const float* __restrict__ Wo) {
    int idx = blockIdx.x * blockDim.x + threadIdx.x;
    if (idx < DM * 48) {
        int d = idx / 48, c = idx % 48;
        float v;
        if (c < 16)      v = Wq[d * 16 + c];
        else if (c < 32) v = Wk[d * 16 + c - 16];
        else             v = Wv[d * 16 + c - 32];
        g_Wqkv[idx] = v;
    }
    if (idx < DK * DM) {
        int i = idx / DM, c = idx % DM;
        float s = 0.f;
#pragma unroll
        for (int h = 0; h < 8; h++) s += Wo[(h * 16 + i) * DM + c];
        g_Woeff[idx] = s;
    }
}

__global__ void conv_weights(const float* __restrict__ w1, const float* __restrict__ w2) {
    int i = blockIdx.x * blockDim.x + threadIdx.x;
    if (i < DFF * DM) {
        __half h, l;
        h_split(w1[i], h, l);
        g_w1h[i] = h; g_w1l[i] = l;
        h_split(w2[i], h, l);
        g_w2h[i] = h; g_w2l[i] = l;
    }
}

// ---------------- fused QKV projection (emits fp16) ------------------------
__global__ void __launch_bounds__(256) qkv_kernel(const float* __restrict__ frame) {
    __shared__ float Fs[128][33];
    __shared__ float Ws[32][48];
    int t = threadIdx.x;
    int m0 = blockIdx.x * 128;
    int r = t & 127;
    int hv = t >> 7;
    float acc[24];
#pragma unroll
    for (int c = 0; c < 24; c++) acc[c] = 0.f;

    int lrow = t >> 3;
    int lds  = (t & 7) * 4;

    for (int d0 = 0; d0 < DM; d0 += 32) {
#pragma unroll
        for (int rr = 0; rr < 128; rr += 32) {
            float4 v = *(const float4*)&frame[(size_t)(m0 + lrow + rr) * DM + d0 + lds];
            Fs[lrow + rr][lds + 0] = v.x;
            Fs[lrow + rr][lds + 1] = v.y;
            Fs[lrow + rr][lds + 2] = v.z;
            Fs[lrow + rr][lds + 3] = v.w;
        }
        for (int q = t; q < 32 * 48; q += 256)
            Ws[q / 48][q % 48] = g_Wqkv[(d0 + q / 48) * 48 + (q % 48)];
        __syncthreads();
#pragma unroll
        for (int d = 0; d < 32; d++) {
            float f = Fs[r][d];
#pragma unroll
            for (int c = 0; c < 24; c++)
                acc[c] = fmaf(f, Ws[d][hv * 24 + c], acc[c]);
        }
        __syncthreads();
    }
    int row = m0 + r;
#pragma unroll
    for (int c = 0; c < 24; c++) {
        int cg = hv * 24 + c;
        __half h, l;
        if (cg < 16) {
            h_split(acc[c] * QSCALE, h, l);
            g_Qh[row * 16 + cg] = h;
            g_Ql[row * 16 + cg] = l;
        } else if (cg < 32) {
            g_Kh[row * 16 + cg - 16] = __float2half_rn(acc[c]);
        } else {
            h_split(acc[c], h, l);
            g_Vph[row * 24 + cg - 32] = h;
            g_Vpl[row * 24 + cg - 32] = l;
        }
    }
    if (hv == 1) {
#pragma unroll
        for (int c2 = 16; c2 < 24; c2++) {
            g_Vph[row * 24 + c2] = (c2 == 16) ? __float2half_rn(1.0f) : __float2half_rn(0.0f);
            g_Vpl[row * 24 + c2] = __float2half_rn(0.0f);
        }
    }
}

// ---------------- tensor-core flash attention (split-KV x2) -----------------
// S = Qh*Kh + Ql*Kh (Q corrected; per-key K rounding averages out)
static constexpr uint32_t ATT_STG  = 18432;   // Kh(6144)+Vh(6144)+Vl(6144)
static constexpr uint32_t ATT_QH   = 36864;
static constexpr uint32_t ATT_QL   = 39936;
static constexpr uint32_t ATT_SMEM = 43008;

__device__ __forceinline__ void attn_load(uint32_t stg, int k0, int t) {
#pragma unroll
    for (int i = 0; i < 2; i++) {
        int q = t + i * 128;
        int row = q >> 1, g = q & 1;
        cp16(stg + (uint32_t)row * 48 + g * 16, g_Kh + (size_t)(k0 + row) * 16 + g * 8);
    }
#pragma unroll
    for (int i = 0; i < 3; i++) {
        int q = t + i * 128;
        int row = q / 3, g = q % 3;
        cp16(stg + 6144 + (uint32_t)row * 48 + g * 16, g_Vph + (size_t)(k0 + row) * 24 + g * 8);
        cp16(stg + 12288 + (uint32_t)row * 48 + g * 16, g_Vpl + (size_t)(k0 + row) * 24 + g * 8);
    }
}

__global__ void __launch_bounds__(128, 2) attn_tc() {
    extern __shared__ __align__(128) char sm[];
    uint32_t sb = smem_u32(sm);
    int t = threadIdx.x, lane = t & 31, w = t >> 5;
    int q0 = (blockIdx.x >> 1) * 64;
    int ks = blockIdx.x & 1;
    int kbase = ks * 4096;

    {
        int row = t >> 1, g = t & 1;
        cp16(sb + ATT_QH + (uint32_t)row * 48 + g * 16, g_Qh + (size_t)(q0 + row) * 16 + g * 8);
        cp16(sb + ATT_QL + (uint32_t)row * 48 + g * 16, g_Ql + (size_t)(q0 + row) * 16 + g * 8);
    }
    attn_load(sb, kbase, t);
    cp_commit();
    attn_load(sb + ATT_STG, kbase + 128, t);
    cp_commit();

    uint32_t aQ  = sb + ATT_QH + (uint32_t)(w * 16 + (lane & 15)) * 48 + (uint32_t)(lane >> 4) * 16;
    uint32_t aK  = (uint32_t)((lane & 7) + ((lane >> 4) & 1) * 8) * 48 + (uint32_t)((lane >> 3) & 1) * 16;
    uint32_t aV4 = (uint32_t)((lane & 7) + ((lane >> 3) & 1) * 8) * 48 + (uint32_t)(lane >> 4) * 16;
    uint32_t aV2 = (uint32_t)((lane & 7) + ((lane >> 3) & 1) * 8) * 48 + 32;

    uint32_t QH[4], QL[4];
    float o[3][4];
#pragma unroll
    for (int i = 0; i < 3; i++)
#pragma unroll
        for (int j = 0; j < 4; j++) o[i][j] = 0.f;
    float m0 = -INFINITY, m8 = -INFINITY;

    for (int c = 0; c < 32; c++) {
        if (c == 31) cp_wait<0>(); else cp_wait<1>();
        __syncthreads();
        if (c == 0) {
            ldsm4(aQ, QH[0], QH[1], QH[2], QH[3]);
            ldsm4(aQ + (ATT_QL - ATT_QH), QL[0], QL[1], QL[2], QL[3]);
        }
        uint32_t stg = sb + (uint32_t)(c & 1) * ATT_STG;

        float s[16][4];
#pragma unroll
        for (int u = 0; u < 8; u++) {
            uint32_t bh0, bh1, bh2, bh3;
            ldsm4(stg + u * 768 + aK, bh0, bh1, bh2, bh3);
            mma16816_z(s[2 * u], QH, bh0, bh1);
            mma16816(s[2 * u], QL, bh0, bh1);
            mma16816_z(s[2 * u + 1], QH, bh2, bh3);
            mma16816(s[2 * u + 1], QL, bh2, bh3);
        }

        float mx0 = s[0][0], mx8 = s[0][2];
#pragma unroll
        for (int nt = 0; nt < 16; nt++) {
            mx0 = fmaxf(mx0, fmaxf(s[nt][0], s[nt][1]));
            mx8 = fmaxf(mx8, fmaxf(s[nt][2], s[nt][3]));
        }
        mx0 = fmaxf(mx0, __shfl_xor_sync(0xffffffffu, mx0, 1));
        mx0 = fmaxf(mx0, __shfl_xor_sync(0xffffffffu, mx0, 2));
        mx8 = fmaxf(mx8, __shfl_xor_sync(0xffffffffu, mx8, 1));
        mx8 = fmaxf(mx8, __shfl_xor_sync(0xffffffffu, mx8, 2));
        float mn0 = fmaxf(m0, mx0), mn8 = fmaxf(m8, mx8);
        float c0 = ex2f(m0 - mn0), c8 = ex2f(m8 - mn8);
        m0 = mn0; m8 = mn8;
#pragma unroll
        for (int i = 0; i < 3; i++) {
            o[i][0] *= c0; o[i][1] *= c0; o[i][2] *= c8; o[i][3] *= c8;
        }
#pragma unroll
        for (int nt = 0; nt < 16; nt++) {
            s[nt][0] = ex2f(s[nt][0] - m0);
            s[nt][1] = ex2f(s[nt][1] - m0);
            s[nt][2] = ex2f(s[nt][2] - m8);
            s[nt][3] = ex2f(s[nt][3] - m8);
        }

#pragma unroll
        for (int j = 0; j < 8; j++) {
            uint32_t a[4];
            a[0] = f16x2_pack(s[2 * j][1],     s[2 * j][0]);
            a[1] = f16x2_pack(s[2 * j][3],     s[2 * j][2]);
            a[2] = f16x2_pack(s[2 * j + 1][1], s[2 * j + 1][0]);
            a[3] = f16x2_pack(s[2 * j + 1][3], s[2 * j + 1][2]);
            uint32_t v0, v1, v2, v3, v4, v5;
            ldsm4t(stg + 6144 + j * 768 + aV4, v0, v1, v2, v3);
            ldsm2t(stg + 6144 + j * 768 + aV2, v4, v5);
            mma16816(o[0], a, v0, v1);
            mma16816(o[1], a, v2, v3);
            mma16816(o[2], a, v4, v5);
            ldsm4t(stg + 12288 + j * 768 + aV4, v0, v1, v2, v3);
            ldsm2t(stg + 12288 + j * 768 + aV2, v4, v5);
            mma16816(o[0], a, v0, v1);
            mma16816(o[1], a, v2, v3);
            mma16816(o[2], a, v4, v5);
        }
        __syncthreads();
        if (c + 2 < 32) {
            attn_load(stg, kbase + (c + 2) * 128, t);
            cp_commit();
        }
    }

    float l0 = __shfl_sync(0xffffffffu, o[2][0], lane & 28);
    float l8 = __shfl_sync(0xffffffffu, o[2][2], lane & 28);
    int row0 = q0 + w * 16 + (lane >> 2);
    int c4 = (lane & 3) * 2;
    *(float2*)&g_po[ks][row0][c4]         = make_float2(o[0][0], o[0][1]);
    *(float2*)&g_po[ks][row0][8 + c4]     = make_float2(o[1][0], o[1][1]);
    *(float2*)&g_po[ks][row0 + 8][c4]     = make_float2(o[0][2], o[0][3]);
    *(float2*)&g_po[ks][row0 + 8][8 + c4] = make_float2(o[1][2], o[1][3]);
    if ((lane & 3) == 0) {
        *(float2*)&g_pml[ks][row0][0]     = make_float2(m0, l0);
        *(float2*)&g_pml[ks][row0 + 8][0] = make_float2(m8, l8);
    }
}

__global__ void __launch_bounds__(256) attn_merge() {
    int row = blockIdx.x * 256 + threadIdx.x;
    float2 s0 = *(const float2*)&g_pml[0][row][0];
    float2 s1 = *(const float2*)&g_pml[1][row][0];
    float mm = fmaxf(s0.x, s1.x);
    float a0 = ex2f(s0.x - mm), a1 = ex2f(s1.x - mm);
    float inv = __fdividef(1.f, s0.y * a0 + s1.y * a1);
#pragma unroll
    for (int c = 0; c < 16; c += 4) {
        float4 v0 = *(const float4*)&g_po[0][row][c];
        float4 v1 = *(const float4*)&g_po[1][row][c];
        float4 r;
        r.x = (v0.x * a0 + v1.x * a1) * inv;
        r.y = (v0.y * a0 + v1.y * a1) * inv;
        r.z = (v0.z * a0 + v1.z * a1) * inv;
        r.w = (v0.w * a0 + v1.w * a1) * inv;
        *(float4*)&g_head[(size_t)row * 16 + c] = r;
    }
}

// ---------------- mho = head @ Woeff (fp32 + fp16 hi) ----------------------
__global__ void __launch_bounds__(256) mho_kernel() {
    __shared__ float hrow[8][16];
    int t = threadIdx.x;
    int r0 = blockIdx.x * 8;
    if (t < 128) hrow[t >> 4][t & 15] = g_head[r0 * 16 + t];
    __syncthreads();

    int cg = (t & 127) * 4;
    int rb = (t >> 7) * 4;
    float4 a[4];
#pragma unroll
    for (int r = 0; r < 4; r++) a[r] = make_float4(0.f, 0.f, 0.f, 0.f);
#pragma unroll
    for (int i = 0; i < 16; i++) {
        float4 w = *(const float4*)&g_Woeff[i * 512 + cg];
#pragma unroll
        for (int r = 0; r < 4; r++) {
            float h = hrow[rb + r][i];
            a[r].x = fmaf(h, w.x, a[r].x); a[r].y = fmaf(h, w.y, a[r].y);
            a[r].z = fmaf(h, w.z, a[r].z); a[r].w = fmaf(h, w.w, a[r].w);
        }
    }
#pragma unroll
    for (int r = 0; r < 4; r++) {
        size_t base = (size_t)(r0 + rb + r) * 512 + cg;
        *(float4*)&g_mho[base] = a[r];
        __half2 h01, h23;
        h01.x = __float2half_rn(a[r].x); h01.y = __float2half_rn(a[r].y);
        h23.x = __float2half_rn(a[r].z); h23.y = __float2half_rn(a[r].w);
        *(__half2*)&g_mhoh[base + 0] = h01;
        *(__half2*)&g_mhoh[base + 2] = h23;
    }
}

// ---------------- HMMA 2-term GEMM: C = Ah*(Bh+Bl)^T + epilogue ------------
// 128x128 tile, 256 threads, KC=32, double-buffered cp.async.
// EPI 0: gelu(x+bias) -> fp16 hi ; EPI 1: x+bias+res -> fp32
static constexpr int G_STAGE = 30720;   // Ah(10240)+Bh(10240)+Bl(10240)
static constexpr int G_SMEM  = 67584;   // max(2 stages, 128x132 fp32 epilogue)

__device__ __forceinline__ void g3_load(uint32_t stg, int m0, int n0, int k0, int t,
                                        int ldk,
                                        const __half* __restrict__ Ah,
                                        const __half* __restrict__ Bh,
                                        const __half* __restrict__ Bl) {
#pragma unroll
    for (int i = 0; i < 2; i++) {
        int q = t + i * 256;
        int r = q >> 2, gr = q & 3;
        uint32_t off = (uint32_t)r * 80 + gr * 16;
        size_t gidx = (size_t)r * ldk + k0 + gr * 8;
        cp16(stg + off,         Ah + (size_t)m0 * ldk + gidx);
        cp16(stg + 10240 + off, Bh + (size_t)n0 * ldk + gidx);
        cp16(stg + 20480 + off, Bl + (size_t)n0 * ldk + gidx);
    }
}

template <int KTOT, int EPI>
__global__ void __launch_bounds__(256, 2) gemm3(
    const float* __restrict__ bias, float* __restrict__ outf)
{
    extern __shared__ __align__(128) char sm[];
    uint32_t sbase = smem_u32(sm);

    const __half* Ahp = (EPI == 0) ? g_mhoh : g_hh;
    const __half* Bhp = (EPI == 0) ? g_w1h  : g_w2h;
    const __half* Blp = (EPI == 0) ? g_w1l  : g_w2l;
    const int N = (EPI == 0) ? DFF : DM;

    int t = threadIdx.x;
    int wid = t >> 5, lane = t & 31;
    int wm = wid & 3, wn = wid >> 2;       // 4 m-warps x 2 n-warps
    int m0 = blockIdx.y * 128;
    int n0 = blockIdx.x * 128;
    const int NC = KTOT / 32;

    int a_row = lane & 15;
    int a_kg  = lane >> 4;
    int b_row = ((lane >> 4) << 3) + (lane & 7);
    int b_kg  = (lane >> 3) & 1;

    float acc[2][8][4];
#pragma unroll
    for (int i = 0; i < 2; i++)
#pragma unroll
        for (int j = 0; j < 8; j++)
#pragma unroll
            for (int k = 0; k < 4; k++) acc[i][j][k] = 0.f;

    g3_load(sbase, m0, n0, 0, t, KTOT, Ahp, Bhp, Blp);
    cp_commit();
    g3_load(sbase + G_STAGE, m0, n0, 32, t, KTOT, Ahp, Bhp, Blp);
    cp_commit();

    for (int c = 0; c < NC; c++) {
        if (c == NC - 1) cp_wait<0>(); else cp_wait<1>();
        __syncthreads();
        uint32_t stg = sbase + (uint32_t)(c & 1) * G_STAGE;
        uint32_t sAh = stg, sBh = stg + 10240, sBl = stg + 20480;

#pragma unroll
        for (int ks = 0; ks < 2; ks++) {
            uint32_t ah[2][4];
#pragma unroll
            for (int mt = 0; mt < 2; mt++) {
                uint32_t off = (uint32_t)(wm * 32 + mt * 16 + a_row) * 80
                             + (uint32_t)(ks * 32 + a_kg * 16);
                ldsm4(sAh + off, ah[mt][0], ah[mt][1], ah[mt][2], ah[mt][3]);
            }
#pragma unroll
            for (int np = 0; np < 4; np++) {
                uint32_t boff = (uint32_t)(wn * 64 + np * 16 + b_row) * 80
                              + (uint32_t)(ks * 32 + b_kg * 16);
                uint32_t bh0, bh1, bh2, bh3, bl0, bl1, bl2, bl3;
                ldsm4(sBh + boff, bh0, bh1, bh2, bh3);
                ldsm4(sBl + boff, bl0, bl1, bl2, bl3);
#pragma unroll
                for (int mt = 0; mt < 2; mt++) {
                    float* c0 = acc[mt][np * 2 + 0];
                    float* c1 = acc[mt][np * 2 + 1];
                    mma16816(c0, ah[mt], bh0, bh1);
                    mma16816(c0, ah[mt], bl0, bl1);
                    mma16816(c1, ah[mt], bh2, bh3);
                    mma16816(c1, ah[mt], bl2, bl3);
                }
            }
        }
        __syncthreads();
        if (c + 2 < NC) {
            g3_load(stg, m0, n0, (c + 2) * 32, t, KTOT, Ahp, Bhp, Blp);
            cp_commit();
        }
    }

    // epilogue: stage accums to smem, coalesced out
    float* eb = (float*)sm;                 // 128 x 132 fp32
#pragma unroll
    for (int mt = 0; mt < 2; mt++) {
#pragma unroll
        for (int nt = 0; nt < 8; nt++) {
            int row = wm * 32 + mt * 16 + (lane >> 2);
            int col = wn * 64 + nt * 8 + (lane & 3) * 2;
            float* p0 = &eb[row * 132 + col];
            p0[0] = acc[mt][nt][0]; p0[1] = acc[mt][nt][1];
            float* p1 = &eb[(row + 8) * 132 + col];
            p1[0] = acc[mt][nt][2]; p1[1] = acc[mt][nt][3];
        }
    }
    __syncthreads();

    int cp2 = (t & 63) * 2;
    float b0 = bias[n0 + cp2], b1 = bias[n0 + cp2 + 1];
#pragma unroll 4
    for (int i = 0; i < 32; i++) {
        int row = (t >> 6) + i * 4;
        float2 v = *(float2*)&eb[row * 132 + cp2];
        float x0 = v.x + b0, x1 = v.y + b1;
        size_t oidx = (size_t)(m0 + row) * N + n0 + cp2;
        if (EPI == 0) {
            x0 = 0.5f * x0 * (1.0f + erff(x0 * 0.70710678118654752f));
            x1 = 0.5f * x1 * (1.0f + erff(x1 * 0.70710678118654752f));
            __half2 hp;
            hp.x = __float2half_rn(x0); hp.y = __float2half_rn(x1);
            *(__half2*)&g_hh[oidx] = hp;
        } else {
            float2 rr = *(const float2*)&g_mho[oidx];
            *(float2*)&outf[oidx] = make_float2(x0 + rr.x, x1 + rr.y);
        }
    }
}

// ---------------- launch ---------------------------------------------------
extern "C" void kernel_launch(void* const* d_in, const int* in_sizes, int n_in,
                              void* d_out, int out_size) {
    const float* frame = (const float*)d_in[0];
    const float* W_q   = (const float*)d_in[1];
    const float* W_k   = (const float*)d_in[2];
    const float* W_v   = (const float*)d_in[3];
    const float* W_o   = (const float*)d_in[4];
    const float* fc1_w = (const float*)d_in[5];
    const float* fc1_b = (const float*)d_in[6];
    const float* fc2_w = (const float*)d_in[7];
    const float* fc2_b = (const float*)d_in[8];
    float* out = (float*)d_out;

    cudaFuncSetAttribute(gemm3<DM, 0>,
                         cudaFuncAttributeMaxDynamicSharedMemorySize, G_SMEM);
    cudaFuncSetAttribute(gemm3<DFF, 1>,
                         cudaFuncAttributeMaxDynamicSharedMemorySize, G_SMEM);
    cudaFuncSetAttribute(attn_tc,
                         cudaFuncAttributeMaxDynamicSharedMemorySize, ATT_SMEM);

    pack_weights<<<96, 256>>>(W_q, W_k, W_v, W_o);
    conv_weights<<<(DFF * DM + 255) / 256, 256>>>(fc1_w, fc2_w);
    qkv_kernel<<<S_LEN / 128, 256>>>(frame);
    attn_tc<<<(S_LEN / 64) * 2, 128, ATT_SMEM>>>();
    attn_merge<<<S_LEN / 256, 256>>>();
    mho_kernel<<<S_LEN / 8, 256>>>();

    gemm3<DM, 0><<<dim3(DFF / 128, S_LEN / 128), 256, G_SMEM>>>(fc1_b, nullptr);
    gemm3<DFF, 1><<<dim3(DM / 128, S_LEN / 128), 256, G_SMEM>>>(fc2_b, out);
}

// round 7
// speedup vs baseline: 4.1630x; 1.3024x over previous
#include <cuda_runtime.h>
#include <cuda_fp16.h>
#include <math.h>
#include <stdint.h>

#define S_LEN 8192
#define DM    512
#define DK    16
#define DFF   2048

// ---------------- scratch (static device globals) -------------------------
__device__ __align__(256) float g_Wqkv[DM * 48];
__device__ __align__(256) float g_Woeff[DK * DM];
__device__ __align__(256) float g_mho[S_LEN * DM];    // fp32 (residual)
__device__ __align__(256) __half g_mhoh[S_LEN * DM];  // mho hi (fp16)
__device__ __align__(256) __half g_hh[S_LEN * DFF];   // gelu(h) fp16
__device__ __align__(256) __half g_w1h[DFF * DM];
__device__ __align__(256) __half g_w2h[DM * DFF];
// attention fp16 operands
__device__ __align__(256) __half g_Qh[S_LEN * DK];    // scaled by 0.25*log2e
__device__ __align__(256) __half g_Ql[S_LEN * DK];
__device__ __align__(256) __half g_Kh[S_LEN * DK];
__device__ __align__(256) __half g_Kl[S_LEN * DK];
__device__ __align__(256) __half g_Vph[S_LEN * 24];   // V padded: col16=1, 17-23=0
// split-KV partials (x4)
__device__ __align__(256) float g_po[4][S_LEN][16];   // unnormalized O
__device__ __align__(256) float g_pml[4][S_LEN][2];   // {m (log2), l}

#define QSCALE 0.36067376022224085f   // 0.25 * log2(e)

// ---------------- helpers ---------------------------------------------------
__device__ __forceinline__ uint32_t smem_u32(const void* p) {
    uint32_t a;
    asm("{ .reg .u64 t; cvta.to.shared.u64 t, %1; cvt.u32.u64 %0, t; }" : "=r"(a) : "l"(p));
    return a;
}
__device__ __forceinline__ void cp16(uint32_t dst, const void* src) {
    asm volatile("cp.async.cg.shared.global [%0], [%1], 16;" :: "r"(dst), "l"(src) : "memory");
}
__device__ __forceinline__ void cp_commit() {
    asm volatile("cp.async.commit_group;" ::: "memory");
}
template <int P>
__device__ __forceinline__ void cp_wait() {
    asm volatile("cp.async.wait_group %0;" :: "n"(P) : "memory");
}
__device__ __forceinline__ void ldsm4(uint32_t addr, uint32_t& r0, uint32_t& r1,
                                      uint32_t& r2, uint32_t& r3) {
    asm volatile("ldmatrix.sync.aligned.m8n8.x4.shared.b16 {%0,%1,%2,%3}, [%4];"
                 : "=r"(r0), "=r"(r1), "=r"(r2), "=r"(r3) : "r"(addr));
}
__device__ __forceinline__ void ldsm4t(uint32_t addr, uint32_t& r0, uint32_t& r1,
                                       uint32_t& r2, uint32_t& r3) {
    asm volatile("ldmatrix.sync.aligned.m8n8.x4.trans.shared.b16 {%0,%1,%2,%3}, [%4];"
                 : "=r"(r0), "=r"(r1), "=r"(r2), "=r"(r3) : "r"(addr));
}
__device__ __forceinline__ void ldsm2t(uint32_t addr, uint32_t& r0, uint32_t& r1) {
    asm volatile("ldmatrix.sync.aligned.m8n8.x2.trans.shared.b16 {%0,%1}, [%2];"
                 : "=r"(r0), "=r"(r1) : "r"(addr));
}
__device__ __forceinline__ void mma16816(float* c, const uint32_t* a,
                                         uint32_t b0, uint32_t b1) {
    asm volatile(
        "mma.sync.aligned.m16n8k16.row.col.f32.f16.f16.f32 "
        "{%0,%1,%2,%3}, {%4,%5,%6,%7}, {%8,%9}, {%0,%1,%2,%3};"
        : "+f"(c[0]), "+f"(c[1]), "+f"(c[2]), "+f"(c[3])
        : "r"(a[0]), "r"(a[1]), "r"(a[2]), "r"(a[3]), "r"(b0), "r"(b1));
}
__device__ __forceinline__ void mma16816_z(float* c, const uint32_t* a,
                                           uint32_t b0, uint32_t b1) {
    float z = 0.f;
    asm volatile(
        "mma.sync.aligned.m16n8k16.row.col.f32.f16.f16.f32 "
        "{%0,%1,%2,%3}, {%4,%5,%6,%7}, {%8,%9}, {%10,%10,%10,%10};"
        : "=f"(c[0]), "=f"(c[1]), "=f"(c[2]), "=f"(c[3])
        : "r"(a[0]), "r"(a[1]), "r"(a[2]), "r"(a[3]), "r"(b0), "r"(b1), "f"(z));
}
__device__ __forceinline__ float ex2f(float x) {
    float y;
    asm("ex2.approx.ftz.f32 %0, %1;" : "=f"(y) : "f"(x));
    return y;
}
__device__ __forceinline__ uint32_t f16x2_pack(float hi, float lo) {
    uint32_t d;
    asm("cvt.rn.f16x2.f32 %0, %1, %2;" : "=r"(d) : "f"(hi), "f"(lo));
    return d;
}
__device__ __forceinline__ void h_split(float x, __half& hi, __half& lo) {
    hi = __float2half_rn(x);
    lo = __float2half_rn(x - __half2float(hi));
}

// ---------------- weight packing ------------------------------------------
__global__ void pack_weights(const float* __restrict__ Wq,
                             const float* __restrict__ Wk,
                             const float* __restrict__ Wv,
                             const float* __restrict__ Wo) {
    int idx = blockIdx.x * blockDim.x + threadIdx.x;
    if (idx < DM * 48) {
        int d = idx / 48, c = idx % 48;
        float v;
        if (c < 16)      v = Wq[d * 16 + c];
        else if (c < 32) v = Wk[d * 16 + c - 16];
        else             v = Wv[d * 16 + c - 32];
        g_Wqkv[idx] = v;
    }
    if (idx < DK * DM) {
        int i = idx / DM, c = idx % DM;
        float s = 0.f;
#pragma unroll
        for (int h = 0; h < 8; h++) s += Wo[(h * 16 + i) * DM + c];
        g_Woeff[idx] = s;
    }
}

__global__ void conv_weights(const float* __restrict__ w1, const float* __restrict__ w2) {
    int i = blockIdx.x * blockDim.x + threadIdx.x;
    if (i < DFF * DM) {
        g_w1h[i] = __float2half_rn(w1[i]);
        g_w2h[i] = __float2half_rn(w2[i]);
    }
}

// ---------------- fused QKV projection (emits fp16) ------------------------
__global__ void __launch_bounds__(256) qkv_kernel(const float* __restrict__ frame) {
    __shared__ float Fs[128][33];
    __shared__ float Ws[32][48];
    int t = threadIdx.x;
    int m0 = blockIdx.x * 128;
    int r = t & 127;
    int hv = t >> 7;
    float acc[24];
#pragma unroll
    for (int c = 0; c < 24; c++) acc[c] = 0.f;

    int lrow = t >> 3;
    int lds  = (t & 7) * 4;

    for (int d0 = 0; d0 < DM; d0 += 32) {
#pragma unroll
        for (int rr = 0; rr < 128; rr += 32) {
            float4 v = *(const float4*)&frame[(size_t)(m0 + lrow + rr) * DM + d0 + lds];
            Fs[lrow + rr][lds + 0] = v.x;
            Fs[lrow + rr][lds + 1] = v.y;
            Fs[lrow + rr][lds + 2] = v.z;
            Fs[lrow + rr][lds + 3] = v.w;
        }
        for (int q = t; q < 32 * 48; q += 256)
            Ws[q / 48][q % 48] = g_Wqkv[(d0 + q / 48) * 48 + (q % 48)];
        __syncthreads();
#pragma unroll
        for (int d = 0; d < 32; d++) {
            float f = Fs[r][d];
#pragma unroll
            for (int c = 0; c < 24; c++)
                acc[c] = fmaf(f, Ws[d][hv * 24 + c], acc[c]);
        }
        __syncthreads();
    }
    int row = m0 + r;
#pragma unroll
    for (int c = 0; c < 24; c++) {
        int cg = hv * 24 + c;
        __half h, l;
        if (cg < 16) {
            h_split(acc[c] * QSCALE, h, l);
            g_Qh[row * 16 + cg] = h;
            g_Ql[row * 16 + cg] = l;
        } else if (cg < 32) {
            h_split(acc[c], h, l);
            g_Kh[row * 16 + cg - 16] = h;
            g_Kl[row * 16 + cg - 16] = l;
        } else {
            g_Vph[row * 24 + cg - 32] = __float2half_rn(acc[c]);
        }
    }
    if (hv == 1) {
#pragma unroll
        for (int c2 = 16; c2 < 24; c2++)
            g_Vph[row * 24 + c2] = (c2 == 16) ? __float2half_rn(1.0f) : __float2half_rn(0.0f);
    }
}

// ---------------- tensor-core flash attention (split-KV x4) -----------------
// S = QH*KH + QH*KL + QL*KH (full 3-term); PV: single V (linear averaging).
static constexpr uint32_t ATT_STG  = 18432;   // Kh(6144)+Kl(6144)+Vh(6144)
static constexpr uint32_t ATT_QH   = 36864;
static constexpr uint32_t ATT_QL   = 39936;
static constexpr uint32_t ATT_SMEM = 43008;

__device__ __forceinline__ void attn_load(uint32_t stg, int k0, int t) {
#pragma unroll
    for (int i = 0; i < 2; i++) {
        int q = t + i * 128;
        int row = q >> 1, g = q & 1;
        cp16(stg + (uint32_t)row * 48 + g * 16, g_Kh + (size_t)(k0 + row) * 16 + g * 8);
        cp16(stg + 6144 + (uint32_t)row * 48 + g * 16, g_Kl + (size_t)(k0 + row) * 16 + g * 8);
    }
#pragma unroll
    for (int i = 0; i < 3; i++) {
        int q = t + i * 128;
        int row = q / 3, g = q % 3;
        cp16(stg + 12288 + (uint32_t)row * 48 + g * 16, g_Vph + (size_t)(k0 + row) * 24 + g * 8);
    }
}

__global__ void __launch_bounds__(128, 3) attn_tc() {
    extern __shared__ __align__(128) char sm[];
    uint32_t sb = smem_u32(sm);
    int t = threadIdx.x, lane = t & 31, w = t >> 5;
    int q0 = (blockIdx.x >> 2) * 64;
    int ks = blockIdx.x & 3;
    int kbase = ks * 2048;

    {
        int row = t >> 1, g = t & 1;
        cp16(sb + ATT_QH + (uint32_t)row * 48 + g * 16, g_Qh + (size_t)(q0 + row) * 16 + g * 8);
        cp16(sb + ATT_QL + (uint32_t)row * 48 + g * 16, g_Ql + (size_t)(q0 + row) * 16 + g * 8);
    }
    attn_load(sb, kbase, t);
    cp_commit();
    attn_load(sb + ATT_STG, kbase + 128, t);
    cp_commit();

    uint32_t aQ  = sb + ATT_QH + (uint32_t)(w * 16 + (lane & 15)) * 48 + (uint32_t)(lane >> 4) * 16;
    uint32_t aK  = (uint32_t)((lane & 7) + ((lane >> 4) & 1) * 8) * 48 + (uint32_t)((lane >> 3) & 1) * 16;
    uint32_t aV4 = (uint32_t)((lane & 7) + ((lane >> 3) & 1) * 8) * 48 + (uint32_t)(lane >> 4) * 16;
    uint32_t aV2 = (uint32_t)((lane & 7) + ((lane >> 3) & 1) * 8) * 48 + 32;

    uint32_t QH[4], QL[4];
    float o[3][4];
#pragma unroll
    for (int i = 0; i < 3; i++)
#pragma unroll
        for (int j = 0; j < 4; j++) o[i][j] = 0.f;
    float m0 = -INFINITY, m8 = -INFINITY;

    for (int c = 0; c < 16; c++) {
        if (c == 15) cp_wait<0>(); else cp_wait<1>();
        __syncthreads();
        if (c == 0) {
            ldsm4(aQ, QH[0], QH[1], QH[2], QH[3]);
            ldsm4(aQ + (ATT_QL - ATT_QH), QL[0], QL[1], QL[2], QL[3]);
        }
        uint32_t stg = sb + (uint32_t)(c & 1) * ATT_STG;

        float s[16][4];
#pragma unroll
        for (int u = 0; u < 8; u++) {
            uint32_t bh0, bh1, bh2, bh3, bl0, bl1, bl2, bl3;
            ldsm4(stg + u * 768 + aK, bh0, bh1, bh2, bh3);
            ldsm4(stg + 6144 + u * 768 + aK, bl0, bl1, bl2, bl3);
            mma16816_z(s[2 * u], QH, bh0, bh1);
            mma16816(s[2 * u], QH, bl0, bl1);
            mma16816(s[2 * u], QL, bh0, bh1);
            mma16816_z(s[2 * u + 1], QH, bh2, bh3);
            mma16816(s[2 * u + 1], QH, bl2, bl3);
            mma16816(s[2 * u + 1], QL, bh2, bh3);
        }

        float mx0 = s[0][0], mx8 = s[0][2];
#pragma unroll
        for (int nt = 0; nt < 16; nt++) {
            mx0 = fmaxf(mx0, fmaxf(s[nt][0], s[nt][1]));
            mx8 = fmaxf(mx8, fmaxf(s[nt][2], s[nt][3]));
        }
        mx0 = fmaxf(mx0, __shfl_xor_sync(0xffffffffu, mx0, 1));
        mx0 = fmaxf(mx0, __shfl_xor_sync(0xffffffffu, mx0, 2));
        mx8 = fmaxf(mx8, __shfl_xor_sync(0xffffffffu, mx8, 1));
        mx8 = fmaxf(mx8, __shfl_xor_sync(0xffffffffu, mx8, 2));
        float mn0 = fmaxf(m0, mx0), mn8 = fmaxf(m8, mx8);
        float c0 = ex2f(m0 - mn0), c8 = ex2f(m8 - mn8);
        m0 = mn0; m8 = mn8;
#pragma unroll
        for (int i = 0; i < 3; i++) {
            o[i][0] *= c0; o[i][1] *= c0; o[i][2] *= c8; o[i][3] *= c8;
        }
#pragma unroll
        for (int nt = 0; nt < 16; nt++) {
            s[nt][0] = ex2f(s[nt][0] - m0);
            s[nt][1] = ex2f(s[nt][1] - m0);
            s[nt][2] = ex2f(s[nt][2] - m8);
            s[nt][3] = ex2f(s[nt][3] - m8);
        }

#pragma unroll
        for (int j = 0; j < 8; j++) {
            uint32_t a[4];
            a[0] = f16x2_pack(s[2 * j][1],     s[2 * j][0]);
            a[1] = f16x2_pack(s[2 * j][3],     s[2 * j][2]);
            a[2] = f16x2_pack(s[2 * j + 1][1], s[2 * j + 1][0]);
            a[3] = f16x2_pack(s[2 * j + 1][3], s[2 * j + 1][2]);
            uint32_t v0, v1, v2, v3, v4, v5;
            ldsm4t(stg + 12288 + j * 768 + aV4, v0, v1, v2, v3);
            ldsm2t(stg + 12288 + j * 768 + aV2, v4, v5);
            mma16816(o[0], a, v0, v1);
            mma16816(o[1], a, v2, v3);
            mma16816(o[2], a, v4, v5);
        }
        __syncthreads();
        if (c + 2 < 16) {
            attn_load(stg, kbase + (c + 2) * 128, t);
            cp_commit();
        }
    }

    float l0 = __shfl_sync(0xffffffffu, o[2][0], lane & 28);
    float l8 = __shfl_sync(0xffffffffu, o[2][2], lane & 28);
    int row0 = q0 + w * 16 + (lane >> 2);
    int c4 = (lane & 3) * 2;
    *(float2*)&g_po[ks][row0][c4]         = make_float2(o[0][0], o[0][1]);
    *(float2*)&g_po[ks][row0][8 + c4]     = make_float2(o[1][0], o[1][1]);
    *(float2*)&g_po[ks][row0 + 8][c4]     = make_float2(o[0][2], o[0][3]);
    *(float2*)&g_po[ks][row0 + 8][8 + c4] = make_float2(o[1][2], o[1][3]);
    if ((lane & 3) == 0) {
        *(float2*)&g_pml[ks][row0][0]     = make_float2(m0, l0);
        *(float2*)&g_pml[ks][row0 + 8][0] = make_float2(m8, l8);
    }
}

// ---------------- mho = merge(partials) @ Woeff (fp32 + fp16 hi) -----------
__global__ void __launch_bounds__(256) mho_kernel() {
    __shared__ float hrow[8][16];
    int t = threadIdx.x;
    int r0 = blockIdx.x * 8;
    if (t < 128) {
        int row = r0 + (t >> 4), col = t & 15;
        float mm = -INFINITY;
#pragma unroll
        for (int k = 0; k < 4; k++) mm = fmaxf(mm, g_pml[k][row][0]);
        float l = 0.f, acc = 0.f;
#pragma unroll
        for (int k = 0; k < 4; k++) {
            float2 s = *(const float2*)&g_pml[k][row][0];
            float a = ex2f(s.x - mm);
            l = fmaf(s.y, a, l);
            acc = fmaf(g_po[k][row][col], a, acc);
        }
        hrow[t >> 4][col] = acc * __fdividef(1.f, l);
    }
    __syncthreads();

    int cg = (t & 127) * 4;
    int rb = (t >> 7) * 4;
    float4 a[4];
#pragma unroll
    for (int r = 0; r < 4; r++) a[r] = make_float4(0.f, 0.f, 0.f, 0.f);
#pragma unroll
    for (int i = 0; i < 16; i++) {
        float4 w = *(const float4*)&g_Woeff[i * 512 + cg];
#pragma unroll
        for (int r = 0; r < 4; r++) {
            float h = hrow[rb + r][i];
            a[r].x = fmaf(h, w.x, a[r].x); a[r].y = fmaf(h, w.y, a[r].y);
            a[r].z = fmaf(h, w.z, a[r].z); a[r].w = fmaf(h, w.w, a[r].w);
        }
    }
#pragma unroll
    for (int r = 0; r < 4; r++) {
        size_t base = (size_t)(r0 + rb + r) * 512 + cg;
        *(float4*)&g_mho[base] = a[r];
        __half2 h01, h23;
        h01.x = __float2half_rn(a[r].x); h01.y = __float2half_rn(a[r].y);
        h23.x = __float2half_rn(a[r].z); h23.y = __float2half_rn(a[r].w);
        *(__half2*)&g_mhoh[base + 0] = h01;
        *(__half2*)&g_mhoh[base + 2] = h23;
    }
}

// ---------------- HMMA single-term GEMM: C = Ah*Bh^T + epilogue ------------
// 128x128 tile, 256 threads, KC=32, double-buffered cp.async.
static constexpr int G_STAGE = 20480;   // Ah(10240)+Bh(10240)
static constexpr int G_SMEM  = 67584;   // epilogue buffer dominates

__device__ __forceinline__ void g3_load(uint32_t stg, int m0, int n0, int k0, int t,
                                        int ldk,
                                        const __half* __restrict__ Ah,
                                        const __half* __restrict__ Bh) {
#pragma unroll
    for (int i = 0; i < 2; i++) {
        int q = t + i * 256;
        int r = q >> 2, gr = q & 3;
        uint32_t off = (uint32_t)r * 80 + gr * 16;
        size_t gidx = (size_t)r * ldk + k0 + gr * 8;
        cp16(stg + off,         Ah + (size_t)m0 * ldk + gidx);
        cp16(stg + 10240 + off, Bh + (size_t)n0 * ldk + gidx);
    }
}

template <int KTOT, int EPI>
__global__ void __launch_bounds__(256, 2) gemm3(
    const float* __restrict__ bias, float* __restrict__ outf)
{
    extern __shared__ __align__(128) char sm[];
    uint32_t sbase = smem_u32(sm);

    const __half* Ahp = (EPI == 0) ? g_mhoh : g_hh;
    const __half* Bhp = (EPI == 0) ? g_w1h  : g_w2h;
    const int N = (EPI == 0) ? DFF : DM;

    int t = threadIdx.x;
    int wid = t >> 5, lane = t & 31;
    int wm = wid & 3, wn = wid >> 2;       // 4 m-warps x 2 n-warps
    int m0 = blockIdx.y * 128;
    int n0 = blockIdx.x * 128;
    const int NC = KTOT / 32;

    int a_row = lane & 15;
    int a_kg  = lane >> 4;
    int b_row = ((lane >> 4) << 3) + (lane & 7);
    int b_kg  = (lane >> 3) & 1;

    float acc[2][8][4];
#pragma unroll
    for (int i = 0; i < 2; i++)
#pragma unroll
        for (int j = 0; j < 8; j++)
#pragma unroll
            for (int k = 0; k < 4; k++) acc[i][j][k] = 0.f;

    g3_load(sbase, m0, n0, 0, t, KTOT, Ahp, Bhp);
    cp_commit();
    g3_load(sbase + G_STAGE, m0, n0, 32, t, KTOT, Ahp, Bhp);
    cp_commit();

    for (int c = 0; c < NC; c++) {
        if (c == NC - 1) cp_wait<0>(); else cp_wait<1>();
        __syncthreads();
        uint32_t stg = sbase + (uint32_t)(c & 1) * G_STAGE;
        uint32_t sAh = stg, sBh = stg + 10240;

#pragma unroll
        for (int ks = 0; ks < 2; ks++) {
            uint32_t ah[2][4];
#pragma unroll
            for (int mt = 0; mt < 2; mt++) {
                uint32_t off = (uint32_t)(wm * 32 + mt * 16 + a_row) * 80
                             + (uint32_t)(ks * 32 + a_kg * 16);
                ldsm4(sAh + off, ah[mt][0], ah[mt][1], ah[mt][2], ah[mt][3]);
            }
#pragma unroll
            for (int np = 0; np < 4; np++) {
                uint32_t boff = (uint32_t)(wn * 64 + np * 16 + b_row) * 80
                              + (uint32_t)(ks * 32 + b_kg * 16);
                uint32_t bh0, bh1, bh2, bh3;
                ldsm4(sBh + boff, bh0, bh1, bh2, bh3);
#pragma unroll
                for (int mt = 0; mt < 2; mt++) {
                    mma16816(acc[mt][np * 2 + 0], ah[mt], bh0, bh1);
                    mma16816(acc[mt][np * 2 + 1], ah[mt], bh2, bh3);
                }
            }
        }
        __syncthreads();
        if (c + 2 < NC) {
            g3_load(stg, m0, n0, (c + 2) * 32, t, KTOT, Ahp, Bhp);
            cp_commit();
        }
    }

    // epilogue: stage accums to smem, coalesced out
    float* eb = (float*)sm;                 // 128 x 132 fp32
#pragma unroll
    for (int mt = 0; mt < 2; mt++) {
#pragma unroll
        for (int nt = 0; nt < 8; nt++) {
            int row = wm * 32 + mt * 16 + (lane >> 2);
            int col = wn * 64 + nt * 8 + (lane & 3) * 2;
            float* p0 = &eb[row * 132 + col];
            p0[0] = acc[mt][nt][0]; p0[1] = acc[mt][nt][1];
            float* p1 = &eb[(row + 8) * 132 + col];
            p1[0] = acc[mt][nt][2]; p1[1] = acc[mt][nt][3];
        }
    }
    __syncthreads();

    int cp2 = (t & 63) * 2;
    float b0 = bias[n0 + cp2], b1 = bias[n0 + cp2 + 1];
#pragma unroll 4
    for (int i = 0; i < 32; i++) {
        int row = (t >> 6) + i * 4;
        float2 v = *(float2*)&eb[row * 132 + cp2];
        float x0 = v.x + b0, x1 = v.y + b1;
        size_t oidx = (size_t)(m0 + row) * N + n0 + cp2;
        if (EPI == 0) {
            x0 = 0.5f * x0 * (1.0f + erff(x0 * 0.70710678118654752f));
            x1 = 0.5f * x1 * (1.0f + erff(x1 * 0.70710678118654752f));
            __half2 hp;
            hp.x = __float2half_rn(x0); hp.y = __float2half_rn(x1);
            *(__half2*)&g_hh[oidx] = hp;
        } else {
            float2 rr = *(const float2*)&g_mho[oidx];
            *(float2*)&outf[oidx] = make_float2(x0 + rr.x, x1 + rr.y);
        }
    }
}

// ---------------- launch ---------------------------------------------------
extern "C" void kernel_launch(void* const* d_in, const int* in_sizes, int n_in,
                              void* d_out, int out_size) {
    const float* frame = (const float*)d_in[0];
    const float* W_q   = (const float*)d_in[1];
    const float* W_k   = (const float*)d_in[2];
    const float* W_v   = (const float*)d_in[3];
    const float* W_o   = (const float*)d_in[4];
    const float* fc1_w = (const float*)d_in[5];
    const float* fc1_b = (const float*)d_in[6];
    const float* fc2_w = (const float*)d_in[7];
    const float* fc2_b = (const float*)d_in[8];
    float* out = (float*)d_out;

    cudaFuncSetAttribute(gemm3<DM, 0>,
                         cudaFuncAttributeMaxDynamicSharedMemorySize, G_SMEM);
    cudaFuncSetAttribute(gemm3<DFF, 1>,
                         cudaFuncAttributeMaxDynamicSharedMemorySize, G_SMEM);
    cudaFuncSetAttribute(attn_tc,
                         cudaFuncAttributeMaxDynamicSharedMemorySize, ATT_SMEM);

    pack_weights<<<96, 256>>>(W_q, W_k, W_v, W_o);
    conv_weights<<<(DFF * DM + 255) / 256, 256>>>(fc1_w, fc2_w);
    qkv_kernel<<<S_LEN / 128, 256>>>(frame);
    attn_tc<<<(S_LEN / 64) * 4, 128, ATT_SMEM>>>();
    mho_kernel<<<S_LEN / 8, 256>>>();

    gemm3<DM, 0><<<dim3(DFF / 128, S_LEN / 128), 256, G_SMEM>>>(fc1_b, nullptr);
    gemm3<DFF, 1><<<dim3(DM / 128, S_LEN / 128), 256, G_SMEM>>>(fc2_b, out);
}

// round 8
// speedup vs baseline: 4.3132x; 1.0361x over previous
#include <cuda_runtime.h>
#include <cuda_fp16.h>
#include <math.h>
#include <stdint.h>

#define S_LEN 8192
#define DM    512
#define DK    16
#define DFF   2048

// ---------------- scratch (static device globals) -------------------------
__device__ __align__(256) float g_Wqkv[DM * 48];
__device__ __align__(256) float g_Woeff[DK * DM];
__device__ __align__(256) float g_mho[S_LEN * DM];    // fp32 (residual)
__device__ __align__(256) __half g_mhoh[S_LEN * DM];  // mho hi (fp16)
__device__ __align__(256) __half g_hh[S_LEN * DFF];   // gelu(h) fp16
__device__ __align__(256) __half g_w1h[DFF * DM];
__device__ __align__(256) __half g_w2h[DM * DFF];
// attention fp16 operands
__device__ __align__(256) __half g_Qh[S_LEN * DK];    // scaled by 0.25*log2e
__device__ __align__(256) __half g_Ql[S_LEN * DK];
__device__ __align__(256) __half g_Kh[S_LEN * DK];
__device__ __align__(256) __half g_Kl[S_LEN * DK];
__device__ __align__(256) __half g_Vph[S_LEN * 24];   // V padded: col16=1, 17-23=0
// split-KV partials (x4)
__device__ __align__(256) float g_po[4][S_LEN][16];   // unnormalized O
__device__ __align__(256) float g_pml[4][S_LEN][2];   // {m (log2), l}

#define QSCALE 0.36067376022224085f   // 0.25 * log2(e)

// ---------------- helpers ---------------------------------------------------
__device__ __forceinline__ uint32_t smem_u32(const void* p) {
    uint32_t a;
    asm("{ .reg .u64 t; cvta.to.shared.u64 t, %1; cvt.u32.u64 %0, t; }" : "=r"(a) : "l"(p));
    return a;
}
__device__ __forceinline__ void cp16(uint32_t dst, const void* src) {
    asm volatile("cp.async.cg.shared.global [%0], [%1], 16;" :: "r"(dst), "l"(src) : "memory");
}
__device__ __forceinline__ void cp_commit() {
    asm volatile("cp.async.commit_group;" ::: "memory");
}
template <int P>
__device__ __forceinline__ void cp_wait() {
    asm volatile("cp.async.wait_group %0;" :: "n"(P) : "memory");
}
__device__ __forceinline__ void ldsm4(uint32_t addr, uint32_t& r0, uint32_t& r1,
                                      uint32_t& r2, uint32_t& r3) {
    asm volatile("ldmatrix.sync.aligned.m8n8.x4.shared.b16 {%0,%1,%2,%3}, [%4];"
                 : "=r"(r0), "=r"(r1), "=r"(r2), "=r"(r3) : "r"(addr));
}
__device__ __forceinline__ void ldsm4t(uint32_t addr, uint32_t& r0, uint32_t& r1,
                                       uint32_t& r2, uint32_t& r3) {
    asm volatile("ldmatrix.sync.aligned.m8n8.x4.trans.shared.b16 {%0,%1,%2,%3}, [%4];"
                 : "=r"(r0), "=r"(r1), "=r"(r2), "=r"(r3) : "r"(addr));
}
__device__ __forceinline__ void ldsm2t(uint32_t addr, uint32_t& r0, uint32_t& r1) {
    asm volatile("ldmatrix.sync.aligned.m8n8.x2.trans.shared.b16 {%0,%1}, [%2];"
                 : "=r"(r0), "=r"(r1) : "r"(addr));
}
__device__ __forceinline__ void mma16816(float* c, const uint32_t* a,
                                         uint32_t b0, uint32_t b1) {
    asm volatile(
        "mma.sync.aligned.m16n8k16.row.col.f32.f16.f16.f32 "
        "{%0,%1,%2,%3}, {%4,%5,%6,%7}, {%8,%9}, {%0,%1,%2,%3};"
        : "+f"(c[0]), "+f"(c[1]), "+f"(c[2]), "+f"(c[3])
        : "r"(a[0]), "r"(a[1]), "r"(a[2]), "r"(a[3]), "r"(b0), "r"(b1));
}
__device__ __forceinline__ void mma16816_z(float* c, const uint32_t* a,
                                           uint32_t b0, uint32_t b1) {
    float z = 0.f;
    asm volatile(
        "mma.sync.aligned.m16n8k16.row.col.f32.f16.f16.f32 "
        "{%0,%1,%2,%3}, {%4,%5,%6,%7}, {%8,%9}, {%10,%10,%10,%10};"
        : "=f"(c[0]), "=f"(c[1]), "=f"(c[2]), "=f"(c[3])
        : "r"(a[0]), "r"(a[1]), "r"(a[2]), "r"(a[3]), "r"(b0), "r"(b1), "f"(z));
}
__device__ __forceinline__ float ex2f(float x) {
    float y;
    asm("ex2.approx.ftz.f32 %0, %1;" : "=f"(y) : "f"(x));
    return y;
}
__device__ __forceinline__ uint32_t f16x2_pack(float hi, float lo) {
    uint32_t d;
    asm("cvt.rn.f16x2.f32 %0, %1, %2;" : "=r"(d) : "f"(hi), "f"(lo));
    return d;
}
__device__ __forceinline__ void h_split(float x, __half& hi, __half& lo) {
    hi = __float2half_rn(x);
    lo = __float2half_rn(x - __half2float(hi));
}

// ---------------- weight packing ------------------------------------------
__global__ void pack_weights(const float* __restrict__ Wq,
                             const float* __restrict__ Wk,
                             const float* __restrict__ Wv,
                             const float* __restrict__ Wo) {
    int idx = blockIdx.x * blockDim.x + threadIdx.x;
    if (idx < DM * 48) {
        int d = idx / 48, c = idx % 48;
        float v;
        if (c < 16)      v = Wq[d * 16 + c];
        else if (c < 32) v = Wk[d * 16 + c - 16];
        else             v = Wv[d * 16 + c - 32];
        g_Wqkv[idx] = v;
    }
    if (idx < DK * DM) {
        int i = idx / DM, c = idx % DM;
        float s = 0.f;
#pragma unroll
        for (int h = 0; h < 8; h++) s += Wo[(h * 16 + i) * DM + c];
        g_Woeff[idx] = s;
    }
}

__global__ void conv_weights(const float* __restrict__ w1, const float* __restrict__ w2) {
    int i = blockIdx.x * blockDim.x + threadIdx.x;
    if (i < DFF * DM) {
        g_w1h[i] = __float2half_rn(w1[i]);
        g_w2h[i] = __float2half_rn(w2[i]);
    }
}

// ---------------- fused QKV projection (emits fp16) ------------------------
__global__ void __launch_bounds__(256) qkv_kernel(const float* __restrict__ frame) {
    __shared__ float Fs[128][33];
    __shared__ float Ws[32][48];
    int t = threadIdx.x;
    int m0 = blockIdx.x * 128;
    int r = t & 127;
    int hv = t >> 7;
    float acc[24];
#pragma unroll
    for (int c = 0; c < 24; c++) acc[c] = 0.f;

    int lrow = t >> 3;
    int lds  = (t & 7) * 4;

    for (int d0 = 0; d0 < DM; d0 += 32) {
#pragma unroll
        for (int rr = 0; rr < 128; rr += 32) {
            float4 v = *(const float4*)&frame[(size_t)(m0 + lrow + rr) * DM + d0 + lds];
            Fs[lrow + rr][lds + 0] = v.x;
            Fs[lrow + rr][lds + 1] = v.y;
            Fs[lrow + rr][lds + 2] = v.z;
            Fs[lrow + rr][lds + 3] = v.w;
        }
        for (int q = t; q < 32 * 48; q += 256)
            Ws[q / 48][q % 48] = g_Wqkv[(d0 + q / 48) * 48 + (q % 48)];
        __syncthreads();
#pragma unroll
        for (int d = 0; d < 32; d++) {
            float f = Fs[r][d];
#pragma unroll
            for (int c = 0; c < 24; c++)
                acc[c] = fmaf(f, Ws[d][hv * 24 + c], acc[c]);
        }
        __syncthreads();
    }
    int row = m0 + r;
#pragma unroll
    for (int c = 0; c < 24; c++) {
        int cg = hv * 24 + c;
        __half h, l;
        if (cg < 16) {
            h_split(acc[c] * QSCALE, h, l);
            g_Qh[row * 16 + cg] = h;
            g_Ql[row * 16 + cg] = l;
        } else if (cg < 32) {
            h_split(acc[c], h, l);
            g_Kh[row * 16 + cg - 16] = h;
            g_Kl[row * 16 + cg - 16] = l;
        } else {
            g_Vph[row * 24 + cg - 32] = __float2half_rn(acc[c]);
        }
    }
    if (hv == 1) {
#pragma unroll
        for (int c2 = 16; c2 < 24; c2++)
            g_Vph[row * 24 + c2] = (c2 == 16) ? __float2half_rn(1.0f) : __float2half_rn(0.0f);
    }
}

// ---------------- tensor-core flash attention (split-KV x4, 3-buf) ---------
// S = QH*KH + QH*KL + QL*KH; PV: single V (linear averaging).
static constexpr uint32_t ATT_STG  = 18432;   // Kh(6144)+Kl(6144)+Vh(6144)
static constexpr uint32_t ATT_QH   = 55296;   // after 3 stages
static constexpr uint32_t ATT_QL   = 58368;
static constexpr uint32_t ATT_SMEM = 61440;

__device__ __forceinline__ void attn_load(uint32_t stg, int k0, int t) {
#pragma unroll
    for (int i = 0; i < 2; i++) {
        int q = t + i * 128;
        int row = q >> 1, g = q & 1;
        cp16(stg + (uint32_t)row * 48 + g * 16, g_Kh + (size_t)(k0 + row) * 16 + g * 8);
        cp16(stg + 6144 + (uint32_t)row * 48 + g * 16, g_Kl + (size_t)(k0 + row) * 16 + g * 8);
    }
#pragma unroll
    for (int i = 0; i < 3; i++) {
        int q = t + i * 128;
        int row = q / 3, g = q % 3;
        cp16(stg + 12288 + (uint32_t)row * 48 + g * 16, g_Vph + (size_t)(k0 + row) * 24 + g * 8);
    }
}

__global__ void __launch_bounds__(128, 3) attn_tc() {
    extern __shared__ __align__(128) char sm[];
    uint32_t sb = smem_u32(sm);
    int t = threadIdx.x, lane = t & 31, w = t >> 5;
    int q0 = (blockIdx.x >> 2) * 64;
    int ks = blockIdx.x & 3;
    int kbase = ks * 2048;

    {
        int row = t >> 1, g = t & 1;
        cp16(sb + ATT_QH + (uint32_t)row * 48 + g * 16, g_Qh + (size_t)(q0 + row) * 16 + g * 8);
        cp16(sb + ATT_QL + (uint32_t)row * 48 + g * 16, g_Ql + (size_t)(q0 + row) * 16 + g * 8);
    }
    attn_load(sb, kbase, t);
    cp_commit();
    attn_load(sb + ATT_STG, kbase + 128, t);
    cp_commit();

    uint32_t aQ  = sb + ATT_QH + (uint32_t)(w * 16 + (lane & 15)) * 48 + (uint32_t)(lane >> 4) * 16;
    uint32_t aK  = (uint32_t)((lane & 7) + ((lane >> 4) & 1) * 8) * 48 + (uint32_t)((lane >> 3) & 1) * 16;
    uint32_t aV4 = (uint32_t)((lane & 7) + ((lane >> 3) & 1) * 8) * 48 + (uint32_t)(lane >> 4) * 16;
    uint32_t aV2 = (uint32_t)((lane & 7) + ((lane >> 3) & 1) * 8) * 48 + 32;

    uint32_t QH[4], QL[4];
    float o[3][4];
#pragma unroll
    for (int i = 0; i < 3; i++)
#pragma unroll
        for (int j = 0; j < 4; j++) o[i][j] = 0.f;
    float m0 = -INFINITY, m8 = -INFINITY;

    int sidx = 0;   // (c % 3)
    for (int c = 0; c < 16; c++) {
        if (c == 15) cp_wait<0>(); else cp_wait<1>();
        __syncthreads();
        if (c == 0) {
            ldsm4(aQ, QH[0], QH[1], QH[2], QH[3]);
            ldsm4(aQ + (ATT_QL - ATT_QH), QL[0], QL[1], QL[2], QL[3]);
        }
        // prefetch c+2 into the buffer freed at iter c-1 ((c+2)%3)
        if (c + 2 < 16) {
            int pidx = sidx + 2; if (pidx >= 3) pidx -= 3;
            attn_load(sb + (uint32_t)pidx * ATT_STG, kbase + (c + 2) * 128, t);
            cp_commit();
        }
        uint32_t stg = sb + (uint32_t)sidx * ATT_STG;

        float s[16][4];
#pragma unroll
        for (int u = 0; u < 8; u++) {
            uint32_t bh0, bh1, bh2, bh3, bl0, bl1, bl2, bl3;
            ldsm4(stg + u * 768 + aK, bh0, bh1, bh2, bh3);
            ldsm4(stg + 6144 + u * 768 + aK, bl0, bl1, bl2, bl3);
            mma16816_z(s[2 * u], QH, bh0, bh1);
            mma16816(s[2 * u], QH, bl0, bl1);
            mma16816(s[2 * u], QL, bh0, bh1);
            mma16816_z(s[2 * u + 1], QH, bh2, bh3);
            mma16816(s[2 * u + 1], QH, bl2, bl3);
            mma16816(s[2 * u + 1], QL, bh2, bh3);
        }

        float mx0 = s[0][0], mx8 = s[0][2];
#pragma unroll
        for (int nt = 0; nt < 16; nt++) {
            mx0 = fmaxf(mx0, fmaxf(s[nt][0], s[nt][1]));
            mx8 = fmaxf(mx8, fmaxf(s[nt][2], s[nt][3]));
        }
        mx0 = fmaxf(mx0, __shfl_xor_sync(0xffffffffu, mx0, 1));
        mx0 = fmaxf(mx0, __shfl_xor_sync(0xffffffffu, mx0, 2));
        mx8 = fmaxf(mx8, __shfl_xor_sync(0xffffffffu, mx8, 1));
        mx8 = fmaxf(mx8, __shfl_xor_sync(0xffffffffu, mx8, 2));
        float mn0 = fmaxf(m0, mx0), mn8 = fmaxf(m8, mx8);
        float c0 = ex2f(m0 - mn0), c8 = ex2f(m8 - mn8);
        m0 = mn0; m8 = mn8;
#pragma unroll
        for (int i = 0; i < 3; i++) {
            o[i][0] *= c0; o[i][1] *= c0; o[i][2] *= c8; o[i][3] *= c8;
        }
#pragma unroll
        for (int nt = 0; nt < 16; nt++) {
            s[nt][0] = ex2f(s[nt][0] - m0);
            s[nt][1] = ex2f(s[nt][1] - m0);
            s[nt][2] = ex2f(s[nt][2] - m8);
            s[nt][3] = ex2f(s[nt][3] - m8);
        }

#pragma unroll
        for (int j = 0; j < 8; j++) {
            uint32_t a[4];
            a[0] = f16x2_pack(s[2 * j][1],     s[2 * j][0]);
            a[1] = f16x2_pack(s[2 * j][3],     s[2 * j][2]);
            a[2] = f16x2_pack(s[2 * j + 1][1], s[2 * j + 1][0]);
            a[3] = f16x2_pack(s[2 * j + 1][3], s[2 * j + 1][2]);
            uint32_t v0, v1, v2, v3, v4, v5;
            ldsm4t(stg + 12288 + j * 768 + aV4, v0, v1, v2, v3);
            ldsm2t(stg + 12288 + j * 768 + aV2, v4, v5);
            mma16816(o[0], a, v0, v1);
            mma16816(o[1], a, v2, v3);
            mma16816(o[2], a, v4, v5);
        }
        if (++sidx == 3) sidx = 0;
    }

    float l0 = __shfl_sync(0xffffffffu, o[2][0], lane & 28);
    float l8 = __shfl_sync(0xffffffffu, o[2][2], lane & 28);
    int row0 = q0 + w * 16 + (lane >> 2);
    int c4 = (lane & 3) * 2;
    *(float2*)&g_po[ks][row0][c4]         = make_float2(o[0][0], o[0][1]);
    *(float2*)&g_po[ks][row0][8 + c4]     = make_float2(o[1][0], o[1][1]);
    *(float2*)&g_po[ks][row0 + 8][c4]     = make_float2(o[0][2], o[0][3]);
    *(float2*)&g_po[ks][row0 + 8][8 + c4] = make_float2(o[1][2], o[1][3]);
    if ((lane & 3) == 0) {
        *(float2*)&g_pml[ks][row0][0]     = make_float2(m0, l0);
        *(float2*)&g_pml[ks][row0 + 8][0] = make_float2(m8, l8);
    }
}

// ---------------- mho = merge(partials) @ Woeff (fp32 + fp16 hi) -----------
__global__ void __launch_bounds__(256) mho_kernel() {
    __shared__ float hrow[8][16];
    int t = threadIdx.x;
    int r0 = blockIdx.x * 8;
    if (t < 128) {
        int row = r0 + (t >> 4), col = t & 15;
        float mm = -INFINITY;
#pragma unroll
        for (int k = 0; k < 4; k++) mm = fmaxf(mm, g_pml[k][row][0]);
        float l = 0.f, acc = 0.f;
#pragma unroll
        for (int k = 0; k < 4; k++) {
            float2 s = *(const float2*)&g_pml[k][row][0];
            float a = ex2f(s.x - mm);
            l = fmaf(s.y, a, l);
            acc = fmaf(g_po[k][row][col], a, acc);
        }
        hrow[t >> 4][col] = acc * __fdividef(1.f, l);
    }
    __syncthreads();

    int cg = (t & 127) * 4;
    int rb = (t >> 7) * 4;
    float4 a[4];
#pragma unroll
    for (int r = 0; r < 4; r++) a[r] = make_float4(0.f, 0.f, 0.f, 0.f);
#pragma unroll
    for (int i = 0; i < 16; i++) {
        float4 w = *(const float4*)&g_Woeff[i * 512 + cg];
#pragma unroll
        for (int r = 0; r < 4; r++) {
            float h = hrow[rb + r][i];
            a[r].x = fmaf(h, w.x, a[r].x); a[r].y = fmaf(h, w.y, a[r].y);
            a[r].z = fmaf(h, w.z, a[r].z); a[r].w = fmaf(h, w.w, a[r].w);
        }
    }
#pragma unroll
    for (int r = 0; r < 4; r++) {
        size_t base = (size_t)(r0 + rb + r) * 512 + cg;
        *(float4*)&g_mho[base] = a[r];
        __half2 h01, h23;
        h01.x = __float2half_rn(a[r].x); h01.y = __float2half_rn(a[r].y);
        h23.x = __float2half_rn(a[r].z); h23.y = __float2half_rn(a[r].w);
        *(__half2*)&g_mhoh[base + 0] = h01;
        *(__half2*)&g_mhoh[base + 2] = h23;
    }
}

// ---------------- HMMA single-term GEMM (3-buf pipeline) -------------------
// 128x128 tile, 256 threads, KC=32.
static constexpr int G_STAGE = 20480;   // Ah(10240)+Bh(10240)
static constexpr int G_SMEM  = 67584;   // max(3 stages=61440, epilogue 128x132 fp32)

__device__ __forceinline__ void g3_load(uint32_t stg, int m0, int n0, int k0, int t,
                                        int ldk,
                                        const __half* __restrict__ Ah,
                                        const __half* __restrict__ Bh) {
#pragma unroll
    for (int i = 0; i < 2; i++) {
        int q = t + i * 256;
        int r = q >> 2, gr = q & 3;
        uint32_t off = (uint32_t)r * 80 + gr * 16;
        size_t gidx = (size_t)r * ldk + k0 + gr * 8;
        cp16(stg + off,         Ah + (size_t)m0 * ldk + gidx);
        cp16(stg + 10240 + off, Bh + (size_t)n0 * ldk + gidx);
    }
}

template <int KTOT, int EPI>
__global__ void __launch_bounds__(256, 2) gemm3(
    const float* __restrict__ bias, float* __restrict__ outf)
{
    extern __shared__ __align__(128) char sm[];
    uint32_t sbase = smem_u32(sm);

    const __half* Ahp = (EPI == 0) ? g_mhoh : g_hh;
    const __half* Bhp = (EPI == 0) ? g_w1h  : g_w2h;
    const int N = (EPI == 0) ? DFF : DM;

    int t = threadIdx.x;
    int wid = t >> 5, lane = t & 31;
    int wm = wid & 3, wn = wid >> 2;       // 4 m-warps x 2 n-warps
    int m0 = blockIdx.y * 128;
    int n0 = blockIdx.x * 128;
    const int NC = KTOT / 32;

    int a_row = lane & 15;
    int a_kg  = lane >> 4;
    int b_row = ((lane >> 4) << 3) + (lane & 7);
    int b_kg  = (lane >> 3) & 1;

    float acc[2][8][4];
#pragma unroll
    for (int i = 0; i < 2; i++)
#pragma unroll
        for (int j = 0; j < 8; j++)
#pragma unroll
            for (int k = 0; k < 4; k++) acc[i][j][k] = 0.f;

    g3_load(sbase, m0, n0, 0, t, KTOT, Ahp, Bhp);
    cp_commit();
    g3_load(sbase + G_STAGE, m0, n0, 32, t, KTOT, Ahp, Bhp);
    cp_commit();

    int sidx = 0;
    for (int c = 0; c < NC; c++) {
        if (c == NC - 1) cp_wait<0>(); else cp_wait<1>();
        __syncthreads();
        // prefetch chunk c+2 into buffer (c+2)%3 (freed at iter c-1)
        if (c + 2 < NC) {
            int pidx = sidx + 2; if (pidx >= 3) pidx -= 3;
            g3_load(sbase + (uint32_t)pidx * G_STAGE, m0, n0, (c + 2) * 32, t, KTOT, Ahp, Bhp);
            cp_commit();
        }
        uint32_t stg = sbase + (uint32_t)sidx * G_STAGE;
        uint32_t sAh = stg, sBh = stg + 10240;

#pragma unroll
        for (int ks = 0; ks < 2; ks++) {
            uint32_t ah[2][4];
#pragma unroll
            for (int mt = 0; mt < 2; mt++) {
                uint32_t off = (uint32_t)(wm * 32 + mt * 16 + a_row) * 80
                             + (uint32_t)(ks * 32 + a_kg * 16);
                ldsm4(sAh + off, ah[mt][0], ah[mt][1], ah[mt][2], ah[mt][3]);
            }
#pragma unroll
            for (int np = 0; np < 4; np++) {
                uint32_t boff = (uint32_t)(wn * 64 + np * 16 + b_row) * 80
                              + (uint32_t)(ks * 32 + b_kg * 16);
                uint32_t bh0, bh1, bh2, bh3;
                ldsm4(sBh + boff, bh0, bh1, bh2, bh3);
#pragma unroll
                for (int mt = 0; mt < 2; mt++) {
                    mma16816(acc[mt][np * 2 + 0], ah[mt], bh0, bh1);
                    mma16816(acc[mt][np * 2 + 1], ah[mt], bh2, bh3);
                }
            }
        }
        if (++sidx == 3) sidx = 0;
    }

    // epilogue: stage accums to smem, coalesced out
    __syncthreads();
    float* eb = (float*)sm;                 // 128 x 132 fp32
#pragma unroll
    for (int mt = 0; mt < 2; mt++) {
#pragma unroll
        for (int nt = 0; nt < 8; nt++) {
            int row = wm * 32 + mt * 16 + (lane >> 2);
            int col = wn * 64 + nt * 8 + (lane & 3) * 2;
            float* p0 = &eb[row * 132 + col];
            p0[0] = acc[mt][nt][0]; p0[1] = acc[mt][nt][1];
            float* p1 = &eb[(row + 8) * 132 + col];
            p1[0] = acc[mt][nt][2]; p1[1] = acc[mt][nt][3];
        }
    }
    __syncthreads();

    int cp2 = (t & 63) * 2;
    float b0 = bias[n0 + cp2], b1 = bias[n0 + cp2 + 1];
#pragma unroll 4
    for (int i = 0; i < 32; i++) {
        int row = (t >> 6) + i * 4;
        float2 v = *(float2*)&eb[row * 132 + cp2];
        float x0 = v.x + b0, x1 = v.y + b1;
        size_t oidx = (size_t)(m0 + row) * N + n0 + cp2;
        if (EPI == 0) {
            x0 = 0.5f * x0 * (1.0f + erff(x0 * 0.70710678118654752f));
            x1 = 0.5f * x1 * (1.0f + erff(x1 * 0.70710678118654752f));
            __half2 hp;
            hp.x = __float2half_rn(x0); hp.y = __float2half_rn(x1);
            *(__half2*)&g_hh[oidx] = hp;
        } else {
            float2 rr = *(const float2*)&g_mho[oidx];
            *(float2*)&outf[oidx] = make_float2(x0 + rr.x, x1 + rr.y);
        }
    }
}

// ---------------- launch ---------------------------------------------------
extern "C" void kernel_launch(void* const* d_in, const int* in_sizes, int n_in,
                              void* d_out, int out_size) {
    const float* frame = (const float*)d_in[0];
    const float* W_q   = (const float*)d_in[1];
    const float* W_k   = (const float*)d_in[2];
    const float* W_v   = (const float*)d_in[3];
    const float* W_o   = (const float*)d_in[4];
    const float* fc1_w = (const float*)d_in[5];
    const float* fc1_b = (const float*)d_in[6];
    const float* fc2_w = (const float*)d_in[7];
    const float* fc2_b = (const float*)d_in[8];
    float* out = (float*)d_out;

    cudaFuncSetAttribute(gemm3<DM, 0>,
                         cudaFuncAttributeMaxDynamicSharedMemorySize, G_SMEM);
    cudaFuncSetAttribute(gemm3<DFF, 1>,
                         cudaFuncAttributeMaxDynamicSharedMemorySize, G_SMEM);
    cudaFuncSetAttribute(attn_tc,
                         cudaFuncAttributeMaxDynamicSharedMemorySize, ATT_SMEM);

    pack_weights<<<96, 256>>>(W_q, W_k, W_v, W_o);
    conv_weights<<<(DFF * DM + 255) / 256, 256>>>(fc1_w, fc2_w);
    qkv_kernel<<<S_LEN / 128, 256>>>(frame);
    attn_tc<<<(S_LEN / 64) * 4, 128, ATT_SMEM>>>();
    mho_kernel<<<S_LEN / 8, 256>>>();

    gemm3<DM, 0><<<dim3(DFF / 128, S_LEN / 128), 256, G_SMEM>>>(fc1_b, nullptr);
    gemm3<DFF, 1><<<dim3(DM / 128, S_LEN / 128), 256, G_SMEM>>>(fc2_b, out);
}

// round 9
// speedup vs baseline: 4.5439x; 1.0535x over previous
#include <cuda_runtime.h>
#include <cuda_fp16.h>
#include <math.h>
#include <stdint.h>

#define S_LEN 8192
#define DM    512
#define DK    16
#define DFF   2048

// ---------------- scratch (static device globals) -------------------------
__device__ __align__(256) float g_Wqkv[DM * 48];
__device__ __align__(256) float g_Woeff[DK * DM];
__device__ __align__(256) float g_mho[S_LEN * DM];    // fp32 (residual)
__device__ __align__(256) __half g_mhoh[S_LEN * DM];  // mho hi (fp16)
__device__ __align__(256) __half g_hh[S_LEN * DFF];   // gelu(h) fp16
__device__ __align__(256) __half g_w1h[DFF * DM];
__device__ __align__(256) __half g_w2h[DM * DFF];
// attention fp16 operands
__device__ __align__(256) __half g_Qh[S_LEN * DK];    // scaled by 0.25*log2e
__device__ __align__(256) __half g_Ql[S_LEN * DK];
__device__ __align__(256) __half g_Kh[S_LEN * DK];
__device__ __align__(256) __half g_Kl[S_LEN * DK];
__device__ __align__(256) __half g_Vph[S_LEN * 24];   // V padded: col16=1, 17-23=0
// split-KV partials (x4)
__device__ __align__(256) float g_po[4][S_LEN][16];   // unnormalized O
__device__ __align__(256) float g_pml[4][S_LEN][2];   // {m (log2), l}
// work queues + completion counters (reset by qkv_kernel each call)
__device__ int g_gq;
__device__ int g_aq;
__device__ int g_cnt[64];

#define QSCALE 0.36067376022224085f   // 0.25 * log2(e)

// ---------------- helpers ---------------------------------------------------
__device__ __forceinline__ uint32_t smem_u32(const void* p) {
    uint32_t a;
    asm("{ .reg .u64 t; cvta.to.shared.u64 t, %1; cvt.u32.u64 %0, t; }" : "=r"(a) : "l"(p));
    return a;
}
__device__ __forceinline__ void cp16(uint32_t dst, const void* src) {
    asm volatile("cp.async.cg.shared.global [%0], [%1], 16;" :: "r"(dst), "l"(src) : "memory");
}
__device__ __forceinline__ void cp_commit() {
    asm volatile("cp.async.commit_group;" ::: "memory");
}
template <int P>
__device__ __forceinline__ void cp_wait() {
    asm volatile("cp.async.wait_group %0;" :: "n"(P) : "memory");
}
__device__ __forceinline__ void ldsm4(uint32_t addr, uint32_t& r0, uint32_t& r1,
                                      uint32_t& r2, uint32_t& r3) {
    asm volatile("ldmatrix.sync.aligned.m8n8.x4.shared.b16 {%0,%1,%2,%3}, [%4];"
                 : "=r"(r0), "=r"(r1), "=r"(r2), "=r"(r3) : "r"(addr));
}
__device__ __forceinline__ void ldsm4t(uint32_t addr, uint32_t& r0, uint32_t& r1,
                                       uint32_t& r2, uint32_t& r3) {
    asm volatile("ldmatrix.sync.aligned.m8n8.x4.trans.shared.b16 {%0,%1,%2,%3}, [%4];"
                 : "=r"(r0), "=r"(r1), "=r"(r2), "=r"(r3) : "r"(addr));
}
__device__ __forceinline__ void ldsm2t(uint32_t addr, uint32_t& r0, uint32_t& r1) {
    asm volatile("ldmatrix.sync.aligned.m8n8.x2.trans.shared.b16 {%0,%1}, [%2];"
                 : "=r"(r0), "=r"(r1) : "r"(addr));
}
__device__ __forceinline__ void mma16816(float* c, const uint32_t* a,
                                         uint32_t b0, uint32_t b1) {
    asm volatile(
        "mma.sync.aligned.m16n8k16.row.col.f32.f16.f16.f32 "
        "{%0,%1,%2,%3}, {%4,%5,%6,%7}, {%8,%9}, {%0,%1,%2,%3};"
        : "+f"(c[0]), "+f"(c[1]), "+f"(c[2]), "+f"(c[3])
        : "r"(a[0]), "r"(a[1]), "r"(a[2]), "r"(a[3]), "r"(b0), "r"(b1));
}
__device__ __forceinline__ void mma16816_z(float* c, const uint32_t* a,
                                           uint32_t b0, uint32_t b1) {
    float z = 0.f;
    asm volatile(
        "mma.sync.aligned.m16n8k16.row.col.f32.f16.f16.f32 "
        "{%0,%1,%2,%3}, {%4,%5,%6,%7}, {%8,%9}, {%10,%10,%10,%10};"
        : "=f"(c[0]), "=f"(c[1]), "=f"(c[2]), "=f"(c[3])
        : "r"(a[0]), "r"(a[1]), "r"(a[2]), "r"(a[3]), "r"(b0), "r"(b1), "f"(z));
}
__device__ __forceinline__ float ex2f(float x) {
    float y;
    asm("ex2.approx.ftz.f32 %0, %1;" : "=f"(y) : "f"(x));
    return y;
}
__device__ __forceinline__ uint32_t f16x2_pack(float hi, float lo) {
    uint32_t d;
    asm("cvt.rn.f16x2.f32 %0, %1, %2;" : "=r"(d) : "f"(hi), "f"(lo));
    return d;
}
__device__ __forceinline__ void h_split(float x, __half& hi, __half& lo) {
    hi = __float2half_rn(x);
    lo = __float2half_rn(x - __half2float(hi));
}

// ---------------- weight packing ------------------------------------------
__global__ void pack_weights(const float* __restrict__ Wq,
                             const float* __restrict__ Wk,
                             const float* __restrict__ Wv,
                             const float* __restrict__ Wo) {
    int idx = blockIdx.x * blockDim.x + threadIdx.x;
    if (idx < DM * 48) {
        int d = idx / 48, c = idx % 48;
        float v;
        if (c < 16)      v = Wq[d * 16 + c];
        else if (c < 32) v = Wk[d * 16 + c - 16];
        else             v = Wv[d * 16 + c - 32];
        g_Wqkv[idx] = v;
    }
    if (idx < DK * DM) {
        int i = idx / DM, c = idx % DM;
        float s = 0.f;
#pragma unroll
        for (int h = 0; h < 8; h++) s += Wo[(h * 16 + i) * DM + c];
        g_Woeff[idx] = s;
    }
}

__global__ void conv_weights(const float* __restrict__ w1, const float* __restrict__ w2) {
    int i = blockIdx.x * blockDim.x + threadIdx.x;
    if (i < DFF * DM) {
        g_w1h[i] = __float2half_rn(w1[i]);
        g_w2h[i] = __float2half_rn(w2[i]);
    }
}

// ---------------- fused QKV projection: 64 rows/CTA, 128 CTAs --------------
__global__ void __launch_bounds__(256) qkv_kernel(const float* __restrict__ frame) {
    __shared__ float Fs[64][33];
    __shared__ float Ws[32][48];
    int t = threadIdx.x;
    int m0 = blockIdx.x * 64;
    int r = t & 63;
    int seg = t >> 6;        // 0..3 -> 12 cols each

    if (blockIdx.x == 0) {   // reset work queues + counters for this call
        if (t == 0) { g_gq = 0; g_aq = 0; }
        if (t < 64) g_cnt[t] = 0;
    }

    float acc[12];
#pragma unroll
    for (int c = 0; c < 12; c++) acc[c] = 0.f;

    int lrow = t >> 2;          // 0..63
    int lds  = (t & 3) * 8;     // 0,8,16,24

    for (int d0 = 0; d0 < DM; d0 += 32) {
        {
            float4 v0 = *(const float4*)&frame[(size_t)(m0 + lrow) * DM + d0 + lds];
            float4 v1 = *(const float4*)&frame[(size_t)(m0 + lrow) * DM + d0 + lds + 4];
            Fs[lrow][lds + 0] = v0.x; Fs[lrow][lds + 1] = v0.y;
            Fs[lrow][lds + 2] = v0.z; Fs[lrow][lds + 3] = v0.w;
            Fs[lrow][lds + 4] = v1.x; Fs[lrow][lds + 5] = v1.y;
            Fs[lrow][lds + 6] = v1.z; Fs[lrow][lds + 7] = v1.w;
        }
        for (int q = t; q < 32 * 48; q += 256)
            Ws[q / 48][q % 48] = g_Wqkv[(d0 + q / 48) * 48 + (q % 48)];
        __syncthreads();
#pragma unroll
        for (int d = 0; d < 32; d++) {
            float f = Fs[r][d];
#pragma unroll
            for (int c = 0; c < 12; c++)
                acc[c] = fmaf(f, Ws[d][seg * 12 + c], acc[c]);
        }
        __syncthreads();
    }
    int row = m0 + r;
#pragma unroll
    for (int c = 0; c < 12; c++) {
        int cg = seg * 12 + c;
        __half h, l;
        if (cg < 16) {
            h_split(acc[c] * QSCALE, h, l);
            g_Qh[row * 16 + cg] = h;
            g_Ql[row * 16 + cg] = l;
        } else if (cg < 32) {
            h_split(acc[c], h, l);
            g_Kh[row * 16 + cg - 16] = h;
            g_Kl[row * 16 + cg - 16] = l;
        } else {
            g_Vph[row * 24 + cg - 32] = __float2half_rn(acc[c]);
        }
    }
    if (seg == 0) {
#pragma unroll
        for (int c2 = 16; c2 < 24; c2++)
            g_Vph[row * 24 + c2] = (c2 == 16) ? __float2half_rn(1.0f) : __float2half_rn(0.0f);
    }
}

// ---------------- persistent tensor-core flash attention --------------------
// 512 items = 128 q-tiles x 4 KV splits, dynamic queue over 444 CTAs.
static constexpr uint32_t ATT_STG  = 18432;   // Kh(6144)+Kl(6144)+Vh(6144)
static constexpr uint32_t ATT_QH   = 55296;   // after 3 stages
static constexpr uint32_t ATT_QL   = 58368;
static constexpr uint32_t ATT_SMEM = 61440;

__device__ __forceinline__ void attn_load(uint32_t stg, int k0, int t) {
#pragma unroll
    for (int i = 0; i < 2; i++) {
        int q = t + i * 128;
        int row = q >> 1, g = q & 1;
        cp16(stg + (uint32_t)row * 48 + g * 16, g_Kh + (size_t)(k0 + row) * 16 + g * 8);
        cp16(stg + 6144 + (uint32_t)row * 48 + g * 16, g_Kl + (size_t)(k0 + row) * 16 + g * 8);
    }
#pragma unroll
    for (int i = 0; i < 3; i++) {
        int q = t + i * 128;
        int row = q / 3, g = q % 3;
        cp16(stg + 12288 + (uint32_t)row * 48 + g * 16, g_Vph + (size_t)(k0 + row) * 24 + g * 8);
    }
}

__global__ void __launch_bounds__(128, 3) attn_tc() {
    extern __shared__ __align__(128) char sm[];
    __shared__ int sm_it;
    uint32_t sb = smem_u32(sm);
    int t = threadIdx.x, lane = t & 31, w = t >> 5;

    uint32_t aQ  = sb + ATT_QH + (uint32_t)(w * 16 + (lane & 15)) * 48 + (uint32_t)(lane >> 4) * 16;
    uint32_t aK  = (uint32_t)((lane & 7) + ((lane >> 4) & 1) * 8) * 48 + (uint32_t)((lane >> 3) & 1) * 16;
    uint32_t aV4 = (uint32_t)((lane & 7) + ((lane >> 3) & 1) * 8) * 48 + (uint32_t)(lane >> 4) * 16;
    uint32_t aV2 = (uint32_t)((lane & 7) + ((lane >> 3) & 1) * 8) * 48 + 32;

    for (;;) {
        __syncthreads();
        if (t == 0) sm_it = atomicAdd(&g_aq, 1);
        __syncthreads();
        int it = sm_it;
        if (it >= 512) return;
        int q0 = (it >> 2) * 64;
        int ks = it & 3;
        int kbase = ks * 2048;

        {
            int row = t >> 1, g = t & 1;
            cp16(sb + ATT_QH + (uint32_t)row * 48 + g * 16, g_Qh + (size_t)(q0 + row) * 16 + g * 8);
            cp16(sb + ATT_QL + (uint32_t)row * 48 + g * 16, g_Ql + (size_t)(q0 + row) * 16 + g * 8);
        }
        attn_load(sb, kbase, t);
        cp_commit();
        attn_load(sb + ATT_STG, kbase + 128, t);
        cp_commit();

        uint32_t QH[4], QL[4];
        float o[3][4];
#pragma unroll
        for (int i = 0; i < 3; i++)
#pragma unroll
            for (int j = 0; j < 4; j++) o[i][j] = 0.f;
        float m0 = -INFINITY, m8 = -INFINITY;

        int sidx = 0;
        for (int c = 0; c < 16; c++) {
            if (c == 15) cp_wait<0>(); else cp_wait<1>();
            __syncthreads();
            if (c == 0) {
                ldsm4(aQ, QH[0], QH[1], QH[2], QH[3]);
                ldsm4(aQ + (ATT_QL - ATT_QH), QL[0], QL[1], QL[2], QL[3]);
            }
            if (c + 2 < 16) {
                int pidx = sidx + 2; if (pidx >= 3) pidx -= 3;
                attn_load(sb + (uint32_t)pidx * ATT_STG, kbase + (c + 2) * 128, t);
                cp_commit();
            }
            uint32_t stg = sb + (uint32_t)sidx * ATT_STG;

            float s[16][4];
#pragma unroll
            for (int u = 0; u < 8; u++) {
                uint32_t bh0, bh1, bh2, bh3, bl0, bl1, bl2, bl3;
                ldsm4(stg + u * 768 + aK, bh0, bh1, bh2, bh3);
                ldsm4(stg + 6144 + u * 768 + aK, bl0, bl1, bl2, bl3);
                mma16816_z(s[2 * u], QH, bh0, bh1);
                mma16816(s[2 * u], QH, bl0, bl1);
                mma16816(s[2 * u], QL, bh0, bh1);
                mma16816_z(s[2 * u + 1], QH, bh2, bh3);
                mma16816(s[2 * u + 1], QH, bl2, bl3);
                mma16816(s[2 * u + 1], QL, bh2, bh3);
            }

            float mx0 = s[0][0], mx8 = s[0][2];
#pragma unroll
            for (int nt = 0; nt < 16; nt++) {
                mx0 = fmaxf(mx0, fmaxf(s[nt][0], s[nt][1]));
                mx8 = fmaxf(mx8, fmaxf(s[nt][2], s[nt][3]));
            }
            mx0 = fmaxf(mx0, __shfl_xor_sync(0xffffffffu, mx0, 1));
            mx0 = fmaxf(mx0, __shfl_xor_sync(0xffffffffu, mx0, 2));
            mx8 = fmaxf(mx8, __shfl_xor_sync(0xffffffffu, mx8, 1));
            mx8 = fmaxf(mx8, __shfl_xor_sync(0xffffffffu, mx8, 2));
            float mn0 = fmaxf(m0, mx0), mn8 = fmaxf(m8, mx8);
            float c0 = ex2f(m0 - mn0), c8 = ex2f(m8 - mn8);
            m0 = mn0; m8 = mn8;
#pragma unroll
            for (int i = 0; i < 3; i++) {
                o[i][0] *= c0; o[i][1] *= c0; o[i][2] *= c8; o[i][3] *= c8;
            }
#pragma unroll
            for (int nt = 0; nt < 16; nt++) {
                s[nt][0] = ex2f(s[nt][0] - m0);
                s[nt][1] = ex2f(s[nt][1] - m0);
                s[nt][2] = ex2f(s[nt][2] - m8);
                s[nt][3] = ex2f(s[nt][3] - m8);
            }

#pragma unroll
            for (int j = 0; j < 8; j++) {
                uint32_t a[4];
                a[0] = f16x2_pack(s[2 * j][1],     s[2 * j][0]);
                a[1] = f16x2_pack(s[2 * j][3],     s[2 * j][2]);
                a[2] = f16x2_pack(s[2 * j + 1][1], s[2 * j + 1][0]);
                a[3] = f16x2_pack(s[2 * j + 1][3], s[2 * j + 1][2]);
                uint32_t v0, v1, v2, v3, v4, v5;
                ldsm4t(stg + 12288 + j * 768 + aV4, v0, v1, v2, v3);
                ldsm2t(stg + 12288 + j * 768 + aV2, v4, v5);
                mma16816(o[0], a, v0, v1);
                mma16816(o[1], a, v2, v3);
                mma16816(o[2], a, v4, v5);
            }
            if (++sidx == 3) sidx = 0;
        }

        float l0 = __shfl_sync(0xffffffffu, o[2][0], lane & 28);
        float l8 = __shfl_sync(0xffffffffu, o[2][2], lane & 28);
        int row0 = q0 + w * 16 + (lane >> 2);
        int c4 = (lane & 3) * 2;
        *(float2*)&g_po[ks][row0][c4]         = make_float2(o[0][0], o[0][1]);
        *(float2*)&g_po[ks][row0][8 + c4]     = make_float2(o[1][0], o[1][1]);
        *(float2*)&g_po[ks][row0 + 8][c4]     = make_float2(o[0][2], o[0][3]);
        *(float2*)&g_po[ks][row0 + 8][8 + c4] = make_float2(o[1][2], o[1][3]);
        if ((lane & 3) == 0) {
            *(float2*)&g_pml[ks][row0][0]     = make_float2(m0, l0);
            *(float2*)&g_pml[ks][row0 + 8][0] = make_float2(m8, l8);
        }
    }
}

// ---------------- mho = merge(partials) @ Woeff (fp32 + fp16 hi) -----------
__global__ void __launch_bounds__(256) mho_kernel() {
    __shared__ float hrow[8][16];
    int t = threadIdx.x;
    int r0 = blockIdx.x * 8;
    if (t < 128) {
        int row = r0 + (t >> 4), col = t & 15;
        float mm = -INFINITY;
#pragma unroll
        for (int k = 0; k < 4; k++) mm = fmaxf(mm, g_pml[k][row][0]);
        float l = 0.f, acc = 0.f;
#pragma unroll
        for (int k = 0; k < 4; k++) {
            float2 s = *(const float2*)&g_pml[k][row][0];
            float a = ex2f(s.x - mm);
            l = fmaf(s.y, a, l);
            acc = fmaf(g_po[k][row][col], a, acc);
        }
        hrow[t >> 4][col] = acc * __fdividef(1.f, l);
    }
    __syncthreads();

    int cg = (t & 127) * 4;
    int rb = (t >> 7) * 4;
    float4 a[4];
#pragma unroll
    for (int r = 0; r < 4; r++) a[r] = make_float4(0.f, 0.f, 0.f, 0.f);
#pragma unroll
    for (int i = 0; i < 16; i++) {
        float4 w = *(const float4*)&g_Woeff[i * 512 + cg];
#pragma unroll
        for (int r = 0; r < 4; r++) {
            float h = hrow[rb + r][i];
            a[r].x = fmaf(h, w.x, a[r].x); a[r].y = fmaf(h, w.y, a[r].y);
            a[r].z = fmaf(h, w.z, a[r].z); a[r].w = fmaf(h, w.w, a[r].w);
        }
    }
#pragma unroll
    for (int r = 0; r < 4; r++) {
        size_t base = (size_t)(r0 + rb + r) * 512 + cg;
        *(float4*)&g_mho[base] = a[r];
        __half2 h01, h23;
        h01.x = __float2half_rn(a[r].x); h01.y = __float2half_rn(a[r].y);
        h23.x = __float2half_rn(a[r].z); h23.y = __float2half_rn(a[r].w);
        *(__half2*)&g_mhoh[base + 0] = h01;
        *(__half2*)&g_mhoh[base + 2] = h23;
    }
}

// ---------------- fused persistent FFN GEMM kernel -------------------------
// Items 0..1023: gemm1 tiles (m=item>>4, n=item&15), gelu epilogue -> g_hh.
// Items 1024..1279: gemm2 tiles (m=idx>>2, n=idx&3), gated on g_cnt[m]==16.
static constexpr int G_STAGE = 20480;   // A(10240)+B(10240)
static constexpr int G_SMEM  = 67584;   // epilogue 128x132 fp32 dominates
static constexpr int N_ITEMS = 1024 + 256;

__device__ __forceinline__ void g3_load(uint32_t stg, int m0, int n0, int k0, int t,
                                        int ldk,
                                        const __half* __restrict__ Ah,
                                        const __half* __restrict__ Bh) {
#pragma unroll
    for (int i = 0; i < 2; i++) {
        int q = t + i * 256;
        int r = q >> 2, gr = q & 3;
        uint32_t off = (uint32_t)r * 80 + gr * 16;
        size_t gidx = (size_t)r * ldk + k0 + gr * 8;
        cp16(stg + off,         Ah + (size_t)m0 * ldk + gidx);
        cp16(stg + 10240 + off, Bh + (size_t)n0 * ldk + gidx);
    }
}

__global__ void __launch_bounds__(256, 2) gemm_fused(
    const float* __restrict__ fc1_b, const float* __restrict__ fc2_b,
    float* __restrict__ outf)
{
    extern __shared__ __align__(128) char sm[];
    __shared__ int sm_item;
    uint32_t sbase = smem_u32(sm);

    int t = threadIdx.x;
    int wid = t >> 5, lane = t & 31;
    int wm = wid & 3, wn = wid >> 2;

    int a_row = lane & 15;
    int a_kg  = lane >> 4;
    int b_row = ((lane >> 4) << 3) + (lane & 7);
    int b_kg  = (lane >> 3) & 1;

    for (;;) {
        __syncthreads();
        if (t == 0) sm_item = atomicAdd(&g_gq, 1);
        __syncthreads();
        int item = sm_item;
        if (item >= N_ITEMS) return;

        const __half* Ap;
        const __half* Bp;
        const float* bias;
        int m0, n0, ldk, NC, N, epi, mblk;
        if (item < 1024) {
            mblk = item >> 4;
            m0 = mblk << 7; n0 = (item & 15) << 7;
            Ap = g_mhoh; Bp = g_w1h; bias = fc1_b;
            ldk = DM; NC = DM / 32; N = DFF; epi = 0;
        } else {
            int idx = item - 1024;
            mblk = idx >> 2;
            m0 = mblk << 7; n0 = (idx & 3) << 7;
            Ap = g_hh; Bp = g_w2h; bias = fc2_b;
            ldk = DFF; NC = DFF / 32; N = DM; epi = 1;
            if (t == 0) {                       // wait for gemm1 rows
                while (atomicAdd(&g_cnt[mblk], 0) < 16) {}
            }
            __syncthreads();
            __threadfence();
        }

        float acc[2][8][4];
#pragma unroll
        for (int i = 0; i < 2; i++)
#pragma unroll
            for (int j = 0; j < 8; j++)
#pragma unroll
                for (int k = 0; k < 4; k++) acc[i][j][k] = 0.f;

        g3_load(sbase, m0, n0, 0, t, ldk, Ap, Bp);
        cp_commit();
        g3_load(sbase + G_STAGE, m0, n0, 32, t, ldk, Ap, Bp);
        cp_commit();

        int sidx = 0;
        for (int c = 0; c < NC; c++) {
            if (c == NC - 1) cp_wait<0>(); else cp_wait<1>();
            __syncthreads();
            if (c + 2 < NC) {
                int pidx = sidx + 2; if (pidx >= 3) pidx -= 3;
                g3_load(sbase + (uint32_t)pidx * G_STAGE, m0, n0, (c + 2) * 32, t, ldk, Ap, Bp);
                cp_commit();
            }
            uint32_t stg = sbase + (uint32_t)sidx * G_STAGE;
            uint32_t sAh = stg, sBh = stg + 10240;

#pragma unroll
            for (int ks = 0; ks < 2; ks++) {
                uint32_t ah[2][4];
#pragma unroll
                for (int mt = 0; mt < 2; mt++) {
                    uint32_t off = (uint32_t)(wm * 32 + mt * 16 + a_row) * 80
                                 + (uint32_t)(ks * 32 + a_kg * 16);
                    ldsm4(sAh + off, ah[mt][0], ah[mt][1], ah[mt][2], ah[mt][3]);
                }
#pragma unroll
                for (int np = 0; np < 4; np++) {
                    uint32_t boff = (uint32_t)(wn * 64 + np * 16 + b_row) * 80
                                  + (uint32_t)(ks * 32 + b_kg * 16);
                    uint32_t bh0, bh1, bh2, bh3;
                    ldsm4(sBh + boff, bh0, bh1, bh2, bh3);
#pragma unroll
                    for (int mt = 0; mt < 2; mt++) {
                        mma16816(acc[mt][np * 2 + 0], ah[mt], bh0, bh1);
                        mma16816(acc[mt][np * 2 + 1], ah[mt], bh2, bh3);
                    }
                }
            }
            if (++sidx == 3) sidx = 0;
        }

        // epilogue: stage accums to smem, coalesced out
        __syncthreads();
        float* eb = (float*)sm;                 // 128 x 132 fp32
#pragma unroll
        for (int mt = 0; mt < 2; mt++) {
#pragma unroll
            for (int nt = 0; nt < 8; nt++) {
                int row = wm * 32 + mt * 16 + (lane >> 2);
                int col = wn * 64 + nt * 8 + (lane & 3) * 2;
                float* p0 = &eb[row * 132 + col];
                p0[0] = acc[mt][nt][0]; p0[1] = acc[mt][nt][1];
                float* p1 = &eb[(row + 8) * 132 + col];
                p1[0] = acc[mt][nt][2]; p1[1] = acc[mt][nt][3];
            }
        }
        __syncthreads();

        int cp2 = (t & 63) * 2;
        float b0 = bias[n0 + cp2], b1 = bias[n0 + cp2 + 1];
#pragma unroll 4
        for (int i = 0; i < 32; i++) {
            int row = (t >> 6) + i * 4;
            float2 v = *(float2*)&eb[row * 132 + cp2];
            float x0 = v.x + b0, x1 = v.y + b1;
            size_t oidx = (size_t)(m0 + row) * N + n0 + cp2;
            if (epi == 0) {
                x0 = 0.5f * x0 * (1.0f + erff(x0 * 0.70710678118654752f));
                x1 = 0.5f * x1 * (1.0f + erff(x1 * 0.70710678118654752f));
                __half2 hp;
                hp.x = __float2half_rn(x0); hp.y = __float2half_rn(x1);
                *(__half2*)&g_hh[oidx] = hp;
            } else {
                float2 rr = *(const float2*)&g_mho[oidx];
                *(float2*)&outf[oidx] = make_float2(x0 + rr.x, x1 + rr.y);
            }
        }

        if (epi == 0) {
            __threadfence();
            __syncthreads();
            if (t == 0) atomicAdd(&g_cnt[mblk], 1);
        }
    }
}

// ---------------- launch ---------------------------------------------------
extern "C" void kernel_launch(void* const* d_in, const int* in_sizes, int n_in,
                              void* d_out, int out_size) {
    const float* frame = (const float*)d_in[0];
    const float* W_q   = (const float*)d_in[1];
    const float* W_k   = (const float*)d_in[2];
    const float* W_v   = (const float*)d_in[3];
    const float* W_o   = (const float*)d_in[4];
    const float* fc1_w = (const float*)d_in[5];
    const float* fc1_b = (const float*)d_in[6];
    const float* fc2_w = (const float*)d_in[7];
    const float* fc2_b = (const float*)d_in[8];
    float* out = (float*)d_out;

    cudaFuncSetAttribute(gemm_fused,
                         cudaFuncAttributeMaxDynamicSharedMemorySize, G_SMEM);
    cudaFuncSetAttribute(attn_tc,
                         cudaFuncAttributeMaxDynamicSharedMemorySize, ATT_SMEM);

    pack_weights<<<96, 256>>>(W_q, W_k, W_v, W_o);
    conv_weights<<<(DFF * DM + 255) / 256, 256>>>(fc1_w, fc2_w);
    qkv_kernel<<<S_LEN / 64, 256>>>(frame);
    attn_tc<<<148 * 3, 128, ATT_SMEM>>>();
    mho_kernel<<<S_LEN / 8, 256>>>();
    gemm_fused<<<148 * 2, 256, G_SMEM>>>(fc1_b, fc2_b, out);
}